// round 1
// baseline (speedup 1.0000x reference)
#include <cuda_runtime.h>
#include <cuda_bf16.h>
#include <math.h>

#define NN      25000
#define NE      100000
#define NEP     125000   // NE + NN self loops
#define NG      512
#define NH      10
#define NF      78
#define HF      780      // NH*NF
#define SEQL    1000
#define EMB     128
#define NFILT   32
#define CONVOUT 121
#define VOCAB   26
#define UCOLS   (VOCAB*8)        // 208
#define USZ     (NFILT*UCOLS)    // 6656

// ---------------- device scratch (static, no allocs) ----------------
__device__ float d_h[NN*HF];
__device__ float d_asrc[NN*NH];
__device__ float d_adst[NN*NH];
__device__ float d_amax[NN*NH];
__device__ float d_denom[NN*NH];
__device__ float d_eexp[(size_t)NEP*NH];
__device__ float d_x1[NN*HF];
__device__ float d_h2[NN*HF];
__device__ float d_x2[NN*HF];
__device__ float d_dinv[NN];
__device__ int   d_start[NG+1];
__device__ float d_pool[NG*2*HF];
__device__ float d_xg1[NG*1024];
__device__ float d_Wt[SEQL*NFILT*8];
__device__ float d_U[(size_t)NG*USZ];
__device__ float d_Mm[UCOLS*CONVOUT];
__device__ float d_conv[(size_t)NG*NFILT*CONVOUT];
__device__ float d_fcxtb2[128];
__device__ float d_xc[NG*256];
__device__ float d_f1[NG*1024];
__device__ float d_f2[NG*512];

// ---------------- helpers ----------------
__device__ __forceinline__ void atomicMaxFloat(float* addr, float v){
    if (v >= 0.f) atomicMax((int*)addr, __float_as_int(v));
    else          atomicMin((unsigned int*)addr, __float_as_uint(v));
}

// ---------------- init ----------------
__global__ void k_init(){
    int i = blockIdx.x*blockDim.x + threadIdx.x;
    if (i < NN*HF){ d_x1[i]=0.f; d_x2[i]=0.f; }
    if (i < NN*NH){ d_denom[i]=0.f; d_amax[i]=__int_as_float(0xFF800000); }
    if (i < NN)   { d_dinv[i]=1.f; }
}

// ---------------- generic tiled GEMM: C = act(A[M,K] @ B[K,N] + bias) ----------------
__global__ void gemm_kernel(const float* __restrict__ A, const float* __restrict__ B,
                            const float* __restrict__ bias, float* __restrict__ C,
                            int M, int N, int K, int ldc, int act)
{
    __shared__ float As[16*64];
    __shared__ float Bs[16*64];
    int tid = threadIdx.x;
    int row0 = blockIdx.y*64, col0 = blockIdx.x*64;
    int tx = tid & 15, ty = tid >> 4;
    float acc[4][4] = {};
    for (int k0 = 0; k0 < K; k0 += 16){
        #pragma unroll
        for (int i=0;i<4;i++){
            int l = tid + i*256;
            int m = l >> 4, kk = l & 15;
            int r = row0 + m, kg = k0 + kk;
            As[kk*64+m] = (r < M && kg < K) ? A[(size_t)r*K + kg] : 0.f;
        }
        #pragma unroll
        for (int i=0;i<4;i++){
            int l = tid + i*256;
            int kk = l >> 6, n = l & 63;
            int kg = k0 + kk, c = col0 + n;
            Bs[kk*64+n] = (kg < K && c < N) ? B[(size_t)kg*N + c] : 0.f;
        }
        __syncthreads();
        #pragma unroll
        for (int kk=0; kk<16; kk++){
            float ra[4], rb[4];
            #pragma unroll
            for (int i=0;i<4;i++) ra[i] = As[kk*64 + ty*4 + i];
            #pragma unroll
            for (int j=0;j<4;j++) rb[j] = Bs[kk*64 + tx*4 + j];
            #pragma unroll
            for (int i=0;i<4;i++)
                #pragma unroll
                for (int j=0;j<4;j++)
                    acc[i][j] += ra[i]*rb[j];
        }
        __syncthreads();
    }
    #pragma unroll
    for (int i=0;i<4;i++){
        int r = row0 + ty*4 + i;
        if (r >= M) continue;
        #pragma unroll
        for (int j=0;j<4;j++){
            int c = col0 + tx*4 + j;
            if (c >= N) continue;
            float v = acc[i][j];
            if (bias) v += bias[c];
            if (act)  v = fmaxf(v, 0.f);
            C[(size_t)r*ldc + c] = v;
        }
    }
}

// ---------------- GAT attention coefficients ----------------
__global__ void k_attn_coef(const float* __restrict__ att_src,
                            const float* __restrict__ att_dst){
    int wid  = (blockIdx.x*blockDim.x + threadIdx.x) >> 5;
    int lane = threadIdx.x & 31;
    if (wid >= NN*NH) return;
    int n = wid / NH, hh = wid % NH;
    const float* hp = d_h + (size_t)n*HF + hh*NF;
    float s1 = 0.f, s2 = 0.f;
    for (int f = lane; f < NF; f += 32){
        float v = hp[f];
        s1 += v * att_src[hh*NF + f];
        s2 += v * att_dst[hh*NF + f];
    }
    #pragma unroll
    for (int o=16;o>0;o>>=1){ s1 += __shfl_down_sync(~0u,s1,o); s2 += __shfl_down_sync(~0u,s2,o); }
    if (!lane){ d_asrc[wid] = s1; d_adst[wid] = s2; }
}

__global__ void k_edge_max(const int* __restrict__ ei){
    int idx = blockIdx.x*blockDim.x + threadIdx.x;
    if (idx >= NEP*NH) return;
    int e = idx / NH, hh = idx % NH;
    int s, d;
    if (e < NE){ s = ei[e]; d = ei[NE+e]; } else { s = d = e - NE; }
    float a = d_asrc[s*NH+hh] + d_adst[d*NH+hh];
    a = a > 0.f ? a : 0.2f*a;
    atomicMaxFloat(&d_amax[d*NH+hh], a);
}

__global__ void k_edge_exp(const int* __restrict__ ei){
    int idx = blockIdx.x*blockDim.x + threadIdx.x;
    if (idx >= NEP*NH) return;
    int e = idx / NH, hh = idx % NH;
    int s, d;
    if (e < NE){ s = ei[e]; d = ei[NE+e]; } else { s = d = e - NE; }
    float a = d_asrc[s*NH+hh] + d_adst[d*NH+hh];
    a = a > 0.f ? a : 0.2f*a;
    float ee = expf(a - d_amax[d*NH+hh]);
    d_eexp[(size_t)e*NH + hh] = ee;
    atomicAdd(&d_denom[d*NH+hh], ee);
}

__global__ void k_gat_scatter(const int* __restrict__ ei){
    int e = blockIdx.x;
    __shared__ float alpha[NH];
    __shared__ int sh_sd[2];
    if (threadIdx.x == 0){
        if (e < NE){ sh_sd[0] = ei[e]; sh_sd[1] = ei[NE+e]; }
        else       { sh_sd[0] = sh_sd[1] = e - NE; }
    }
    __syncthreads();
    int s = sh_sd[0], d = sh_sd[1];
    if (threadIdx.x < NH)
        alpha[threadIdx.x] = d_eexp[(size_t)e*NH + threadIdx.x] /
                             (d_denom[d*NH + threadIdx.x] + 1e-16f);
    __syncthreads();
    for (int c = threadIdx.x; c < HF; c += blockDim.x)
        atomicAdd(&d_x1[(size_t)d*HF + c], d_h[(size_t)s*HF + c] * alpha[c / NF]);
}

__global__ void k_bias_relu(float* __restrict__ buf, const float* __restrict__ bias){
    int i = blockIdx.x*blockDim.x + threadIdx.x;
    if (i >= NN*HF) return;
    buf[i] = fmaxf(buf[i] + bias[i % HF], 0.f);
}

// ---------------- GCN norm + scatter ----------------
__global__ void k_deg(const int* __restrict__ ei){
    int e = blockIdx.x*blockDim.x + threadIdx.x;
    if (e >= NE) return;
    atomicAdd(&d_dinv[ei[NE+e]], 1.f);
}
__global__ void k_dinv(){
    int n = blockIdx.x*blockDim.x + threadIdx.x;
    if (n >= NN) return;
    d_dinv[n] = rsqrtf(d_dinv[n]);
}
__global__ void k_gcn_scatter(const int* __restrict__ ei){
    int e = blockIdx.x;
    int s, d;
    if (e < NE){ s = ei[e]; d = ei[NE+e]; } else { s = d = e - NE; }
    float coef = d_dinv[s] * d_dinv[d];
    for (int c = threadIdx.x; c < HF; c += blockDim.x)
        atomicAdd(&d_x2[(size_t)d*HF + c], d_h2[(size_t)s*HF + c] * coef);
}

// ---------------- pooling ----------------
__global__ void k_start(const int* __restrict__ batch){
    int g = blockIdx.x*blockDim.x + threadIdx.x;
    if (g > NG) return;
    if (g == NG){ d_start[NG] = NN; return; }
    int lo = 0, hi = NN;
    while (lo < hi){ int mid = (lo+hi) >> 1; if (batch[mid] < g) lo = mid+1; else hi = mid; }
    d_start[g] = lo;
}
__global__ void k_pool(){
    int g = blockIdx.x;
    int s = d_start[g], e = d_start[g+1];
    int cnt = e - s;
    for (int c = threadIdx.x; c < HF; c += blockDim.x){
        float mx = -1e30f, sm = 0.f;
        for (int n = s; n < e; n++){
            float v = d_x2[(size_t)n*HF + c];
            mx = fmaxf(mx, v); sm += v;
        }
        d_pool[g*2*HF + c]      = (cnt > 0) ? mx : 0.f;
        d_pool[g*2*HF + HF + c] = sm / fmaxf((float)cnt, 1.f);
    }
}

// ---------------- target branch ----------------
__global__ void k_buildM(const float* __restrict__ emb){
    int i = blockIdx.x*blockDim.x + threadIdx.x;
    if (i >= UCOLS*CONVOUT) return;
    int p = i % CONVOUT, vk = i / CONVOUT;
    int v = vk >> 3, k = vk & 7;
    d_Mm[i] = emb[v*EMB + p + k];
}
__global__ void k_transW(const float* __restrict__ W){
    int i = blockIdx.x*blockDim.x + threadIdx.x;
    if (i >= NFILT*SEQL*8) return;
    int o = i / (SEQL*8), c = (i >> 3) % SEQL, k = i & 7;
    d_Wt[c*(NFILT*8) + o*8 + k] = W[i];
}
__global__ void k_buildU(const int* __restrict__ target){
    __shared__ float sU[USZ];
    __shared__ int   st[SEQL];
    int g = blockIdx.x;
    for (int i = threadIdx.x; i < USZ;  i += blockDim.x) sU[i] = 0.f;
    for (int i = threadIdx.x; i < SEQL; i += blockDim.x) st[i] = target[g*SEQL + i];
    __syncthreads();
    int o = threadIdx.x >> 3, k = threadIdx.x & 7;   // 256 threads = 32 x 8
    for (int c = 0; c < SEQL; c++){
        int v = st[c];
        sU[o*UCOLS + v*8 + k] += d_Wt[c*(NFILT*8) + threadIdx.x];
    }
    __syncthreads();
    for (int i = threadIdx.x; i < USZ; i += blockDim.x)
        d_U[(size_t)g*USZ + i] = sU[i];
}
__global__ void k_fcxtb2(const float* __restrict__ fcxt_W,
                         const float* __restrict__ fcxt_b,
                         const float* __restrict__ conv_b){
    int j = blockIdx.x; // 128 blocks, 128 threads
    __shared__ float red[128];
    float s = 0.f;
    for (int r = threadIdx.x; r < NFILT*CONVOUT; r += blockDim.x)
        s += conv_b[r / CONVOUT] * fcxt_W[(size_t)r*128 + j];
    red[threadIdx.x] = s; __syncthreads();
    for (int o = 64; o > 0; o >>= 1){
        if (threadIdx.x < o) red[threadIdx.x] += red[threadIdx.x + o];
        __syncthreads();
    }
    if (!threadIdx.x) d_fcxtb2[j] = fcxt_b[j] + red[0];
}

// ---------------- final projection ----------------
__global__ void k_out(const float* __restrict__ oW, const float* __restrict__ ob,
                      float* __restrict__ out){
    int g    = (blockIdx.x*blockDim.x + threadIdx.x) >> 5;
    int lane = threadIdx.x & 31;
    if (g >= NG) return;
    float s = 0.f;
    for (int k = lane; k < 512; k += 32) s += d_f2[g*512 + k] * oW[k];
    #pragma unroll
    for (int o = 16; o > 0; o >>= 1) s += __shfl_down_sync(~0u, s, o);
    if (!lane) out[g] = s + ob[0];
}

// ---------------- launch ----------------
static inline void gemm_launch(const float* A, const float* B, const float* bias,
                               float* C, int M, int N, int K, int ldc, int act){
    dim3 grid((N + 63)/64, (M + 63)/64);
    gemm_kernel<<<grid, 256>>>(A, B, bias, C, M, N, K, ldc, act);
}

extern "C" void kernel_launch(void* const* d_in, const int* in_sizes, int n_in,
                              void* d_out, int out_size){
    const float* x        = (const float*)d_in[0];
    const int*   ei       = (const int*)  d_in[1];
    const int*   batch    = (const int*)  d_in[2];
    const int*   target   = (const int*)  d_in[3];
    const float* gat_W    = (const float*)d_in[4];
    const float* gat_asrc = (const float*)d_in[5];
    const float* gat_adst = (const float*)d_in[6];
    const float* gat_b    = (const float*)d_in[7];
    const float* gcn_W    = (const float*)d_in[8];
    const float* gcn_b    = (const float*)d_in[9];
    const float* fcg1_W   = (const float*)d_in[10];
    const float* fcg1_b   = (const float*)d_in[11];
    const float* fcg2_W   = (const float*)d_in[12];
    const float* fcg2_b   = (const float*)d_in[13];
    const float* emb      = (const float*)d_in[14];
    const float* conv_W   = (const float*)d_in[15];
    const float* conv_b   = (const float*)d_in[16];
    const float* fcxt_W   = (const float*)d_in[17];
    const float* fcxt_b   = (const float*)d_in[18];
    const float* fc1_W    = (const float*)d_in[19];
    const float* fc1_b    = (const float*)d_in[20];
    const float* fc2_W    = (const float*)d_in[21];
    const float* fc2_b    = (const float*)d_in[22];
    const float* out_W    = (const float*)d_in[23];
    const float* out_b    = (const float*)d_in[24];

    float *p_h, *p_x1, *p_h2, *p_pool, *p_xg1, *p_xc, *p_U, *p_Mm, *p_conv,
          *p_f1, *p_f2, *p_fcxtb2;
    cudaGetSymbolAddress((void**)&p_h,    d_h);
    cudaGetSymbolAddress((void**)&p_x1,   d_x1);
    cudaGetSymbolAddress((void**)&p_h2,   d_h2);
    cudaGetSymbolAddress((void**)&p_pool, d_pool);
    cudaGetSymbolAddress((void**)&p_xg1,  d_xg1);
    cudaGetSymbolAddress((void**)&p_xc,   d_xc);
    cudaGetSymbolAddress((void**)&p_U,    d_U);
    cudaGetSymbolAddress((void**)&p_Mm,   d_Mm);
    cudaGetSymbolAddress((void**)&p_conv, d_conv);
    cudaGetSymbolAddress((void**)&p_f1,   d_f1);
    cudaGetSymbolAddress((void**)&p_f2,   d_f2);
    cudaGetSymbolAddress((void**)&p_fcxtb2, d_fcxtb2);

    // init scratch
    k_init<<<(NN*HF + 255)/256, 256>>>();

    // GAT: h = x @ gat_W
    gemm_launch(x, gat_W, nullptr, p_h, NN, HF, NF, HF, 0);
    k_attn_coef<<<(NN*NH*32 + 255)/256, 256>>>(gat_asrc, gat_adst);
    k_edge_max<<<(NEP*NH + 255)/256, 256>>>(ei);
    k_edge_exp<<<(NEP*NH + 255)/256, 256>>>(ei);
    k_gat_scatter<<<NEP, 256>>>(ei);
    k_bias_relu<<<(NN*HF + 255)/256, 256>>>(p_x1, gat_b);

    // GCN
    k_deg<<<(NE + 255)/256, 256>>>(ei);
    k_dinv<<<(NN + 255)/256, 256>>>();
    gemm_launch(p_x1, gcn_W, nullptr, p_h2, NN, HF, HF, HF, 0);
    k_gcn_scatter<<<NEP, 256>>>(ei);
    float* p_x2; cudaGetSymbolAddress((void**)&p_x2, d_x2);
    k_bias_relu<<<(NN*HF + 255)/256, 256>>>(p_x2, gcn_b);

    // pooling + graph head
    k_start<<<3, 256>>>(batch);
    k_pool<<<NG, 256>>>();
    gemm_launch(p_pool, fcg1_W, fcg1_b, p_xg1, NG, 1024, 2*HF, 1024, 1);
    gemm_launch(p_xg1, fcg2_W, fcg2_b, p_xc, NG, 128, 1024, 256, 0);

    // target branch (vocab-collapsed conv)
    k_buildM<<<(UCOLS*CONVOUT + 255)/256, 256>>>(emb);
    k_transW<<<(NFILT*SEQL*8 + 255)/256, 256>>>(conv_W);
    k_buildU<<<NG, 256>>>(target);
    gemm_launch(p_U, p_Mm, nullptr, p_conv, NG*NFILT, CONVOUT, UCOLS, CONVOUT, 0);
    k_fcxtb2<<<128, 128>>>(fcxt_W, fcxt_b, conv_b);
    gemm_launch(p_conv, fcxt_W, p_fcxtb2, p_xc + 128, NG, 128, NFILT*CONVOUT, 256, 0);

    // fusion head
    gemm_launch(p_xc, fc1_W, fc1_b, p_f1, NG, 1024, 256, 1024, 1);
    gemm_launch(p_f1, fc2_W, fc2_b, p_f2, NG, 512, 1024, 512, 1);
    k_out<<<(NG*32 + 255)/256, 256>>>(out_W, out_b, (float*)d_out);
}

// round 2
// speedup vs baseline: 1.2881x; 1.2881x over previous
#include <cuda_runtime.h>
#include <cuda_bf16.h>
#include <math.h>

#define NN      25000
#define NE      100000
#define NEP     125000   // NE + NN self loops
#define NG      512
#define NH      10
#define NF      78
#define HF      780      // NH*NF
#define SEQL    1000
#define EMB     128
#define NFILT   32
#define CONVOUT 121
#define VOCAB   26
#define UCOLS   (VOCAB*8)        // 208
#define USZ     (NFILT*UCOLS)    // 6656

// ---------------- device scratch (static, no allocs) ----------------
__device__ float d_h[NN*HF];
__device__ float d_asrc[NN*NH];
__device__ float d_adst[NN*NH];
__device__ float d_invden[NN*NH];
__device__ float d_alpha[(size_t)NEP*NH];
__device__ float d_x1[NN*HF];
__device__ float d_h2[NN*HF];
__device__ float d_x2[NN*HF];
__device__ float d_dinv[NN];
__device__ int   d_deg[NN];
__device__ int   d_roff[NN+1];
__device__ int   d_rpos[NN];
__device__ int   d_csrc[NEP];
__device__ int   d_start[NG+1];
__device__ float d_pool[NG*2*HF];
__device__ float d_xg1[NG*1024];
__device__ float d_Wt[SEQL*NFILT*8];
__device__ float d_U[(size_t)NG*USZ];
__device__ float d_Mm[UCOLS*CONVOUT];
__device__ float d_conv[(size_t)NG*NFILT*CONVOUT];
__device__ float d_fcxtb2[128];
__device__ float d_xc[NG*256];
__device__ float d_f1[NG*1024];
__device__ float d_f2[NG*512];

// ================= CSR build =================
__global__ void k_deg_init(){
    int n = blockIdx.x*blockDim.x + threadIdx.x;
    if (n < NN) d_deg[n] = 1;   // self loop
}
__global__ void k_count(const int* __restrict__ ei){
    int e = blockIdx.x*blockDim.x + threadIdx.x;
    if (e < NE) atomicAdd(&d_deg[ei[NE+e]], 1);
}
__global__ void k_scan(){
    __shared__ int part[1024];
    int t = threadIdx.x;
    const int PER = 25;  // 1024*25 = 25600 >= NN
    int base = t*PER;
    int sum = 0;
    for (int i = 0; i < PER; i++){
        int idx = base + i;
        if (idx < NN) sum += d_deg[idx];
    }
    part[t] = sum;
    __syncthreads();
    for (int off = 1; off < 1024; off <<= 1){
        int v = (t >= off) ? part[t-off] : 0;
        __syncthreads();
        part[t] += v;
        __syncthreads();
    }
    int run = part[t] - sum;  // exclusive prefix
    for (int i = 0; i < PER; i++){
        int idx = base + i;
        if (idx < NN){
            d_roff[idx] = run;
            d_rpos[idx] = run;
            run += d_deg[idx];
        }
    }
    if (t == 1023) d_roff[NN] = NEP;
}
__global__ void k_fill(const int* __restrict__ ei){
    int e = blockIdx.x*blockDim.x + threadIdx.x;
    if (e >= NEP) return;
    int s, d;
    if (e < NE){ s = ei[e]; d = ei[NE+e]; } else { s = d = e - NE; }
    int pos = atomicAdd(&d_rpos[d], 1);
    d_csrc[pos] = s;
}
__global__ void k_dinv(){
    int n = blockIdx.x*blockDim.x + threadIdx.x;
    if (n < NN) d_dinv[n] = rsqrtf((float)d_deg[n]);
}

// ================= big GEMM: 128x128 tile, f32x2 packed FMA =================
template<bool AV, bool BV>
__global__ void gemm128_kernel(const float* __restrict__ A, const float* __restrict__ B,
                               float* __restrict__ C, int M, int N, int K, int ldc)
{
    __shared__ float As[16][128];
    __shared__ float Bs[16][128];
    int tid = threadIdx.x;
    int row0 = blockIdx.y*128, col0 = blockIdx.x*128;
    int tx = tid & 15, ty = tid >> 4;
    unsigned long long acc2[8][4];
    #pragma unroll
    for (int i=0;i<8;i++)
        #pragma unroll
        for (int j=0;j<4;j++) acc2[i][j] = 0ull;

    for (int k0 = 0; k0 < K; k0 += 16){
        // ---- load A tile (transposed into As[k][m]) ----
        if (AV){
            int kq = (tid & 3) * 4, rbase = tid >> 2;
            #pragma unroll
            for (int pass = 0; pass < 2; pass++){
                int m = rbase + pass*64;
                int r = row0 + m, kg = k0 + kq;
                float4 v = make_float4(0.f,0.f,0.f,0.f);
                if (r < M){
                    if (kg + 3 < K) v = *(const float4*)&A[(size_t)r*K + kg];
                    else {
                        float t[4] = {0.f,0.f,0.f,0.f};
                        #pragma unroll
                        for (int q=0;q<4;q++) if (kg+q < K) t[q] = A[(size_t)r*K + kg + q];
                        v = make_float4(t[0],t[1],t[2],t[3]);
                    }
                }
                As[kq+0][m]=v.x; As[kq+1][m]=v.y; As[kq+2][m]=v.z; As[kq+3][m]=v.w;
            }
        } else {
            int m = tid >> 1, kb = (tid & 1) * 8;
            int r = row0 + m;
            #pragma unroll
            for (int i=0;i<8;i++){
                int kg = k0 + kb + i;
                As[kb+i][m] = (r < M && kg < K) ? A[(size_t)r*K + kg] : 0.f;
            }
        }
        // ---- load B tile ----
        if (BV){
            int nq = (tid & 31) * 4, kb = tid >> 5;
            #pragma unroll
            for (int pass = 0; pass < 2; pass++){
                int kk = kb + pass*8;
                int kg = k0 + kk, c = col0 + nq;
                float4 v = make_float4(0.f,0.f,0.f,0.f);
                if (kg < K){
                    if (c + 3 < N) v = *(const float4*)&B[(size_t)kg*N + c];
                    else {
                        float t[4] = {0.f,0.f,0.f,0.f};
                        #pragma unroll
                        for (int q=0;q<4;q++) if (c+q < N) t[q] = B[(size_t)kg*N + c + q];
                        v = make_float4(t[0],t[1],t[2],t[3]);
                    }
                }
                *(float4*)&Bs[kk][nq] = v;
            }
        } else {
            int kk = tid >> 4, nb = (tid & 15) * 8;
            int kg = k0 + kk;
            #pragma unroll
            for (int j=0;j<8;j++){
                int c = col0 + nb + j;
                Bs[kk][nb+j] = (kg < K && c < N) ? B[(size_t)kg*N + c] : 0.f;
            }
        }
        __syncthreads();
        #pragma unroll
        for (int kk = 0; kk < 16; kk++){
            float4 a0 = *(const float4*)&As[kk][ty*8];
            float4 a1 = *(const float4*)&As[kk][ty*8+4];
            unsigned long long rb[4];
            #pragma unroll
            for (int j=0;j<4;j++)
                rb[j] = *(const unsigned long long*)&Bs[kk][tx*8 + 2*j];
            float ra[8] = {a0.x,a0.y,a0.z,a0.w,a1.x,a1.y,a1.z,a1.w};
            #pragma unroll
            for (int i=0;i<8;i++){
                unsigned long long ad;
                asm("mov.b64 %0, {%1, %1};" : "=l"(ad) : "r"(__float_as_uint(ra[i])));
                #pragma unroll
                for (int j=0;j<4;j++)
                    asm("fma.rn.f32x2 %0, %1, %2, %0;" : "+l"(acc2[i][j]) : "l"(ad), "l"(rb[j]));
            }
        }
        __syncthreads();
    }
    #pragma unroll
    for (int i=0;i<8;i++){
        int r = row0 + ty*8 + i;
        if (r >= M) continue;
        #pragma unroll
        for (int j=0;j<4;j++){
            unsigned int lo, hi;
            asm("mov.b64 {%0, %1}, %2;" : "=r"(lo), "=r"(hi) : "l"(acc2[i][j]));
            int c = col0 + tx*8 + 2*j;
            if (c   < N) C[(size_t)r*ldc + c]   = __uint_as_float(lo);
            if (c+1 < N) C[(size_t)r*ldc + c+1] = __uint_as_float(hi);
        }
    }
}

// ================= small GEMM (64x64, with bias/act) =================
__global__ void gemm_kernel(const float* __restrict__ A, const float* __restrict__ B,
                            const float* __restrict__ bias, float* __restrict__ C,
                            int M, int N, int K, int ldc, int act)
{
    __shared__ float As[16*64];
    __shared__ float Bs[16*64];
    int tid = threadIdx.x;
    int row0 = blockIdx.y*64, col0 = blockIdx.x*64;
    int tx = tid & 15, ty = tid >> 4;
    float acc[4][4] = {};
    for (int k0 = 0; k0 < K; k0 += 16){
        #pragma unroll
        for (int i=0;i<4;i++){
            int l = tid + i*256;
            int m = l >> 4, kk = l & 15;
            int r = row0 + m, kg = k0 + kk;
            As[kk*64+m] = (r < M && kg < K) ? A[(size_t)r*K + kg] : 0.f;
        }
        #pragma unroll
        for (int i=0;i<4;i++){
            int l = tid + i*256;
            int kk = l >> 6, n = l & 63;
            int kg = k0 + kk, c = col0 + n;
            Bs[kk*64+n] = (kg < K && c < N) ? B[(size_t)kg*N + c] : 0.f;
        }
        __syncthreads();
        #pragma unroll
        for (int kk=0; kk<16; kk++){
            float ra[4], rb[4];
            #pragma unroll
            for (int i=0;i<4;i++) ra[i] = As[kk*64 + ty*4 + i];
            #pragma unroll
            for (int j=0;j<4;j++) rb[j] = Bs[kk*64 + tx*4 + j];
            #pragma unroll
            for (int i=0;i<4;i++)
                #pragma unroll
                for (int j=0;j<4;j++)
                    acc[i][j] += ra[i]*rb[j];
        }
        __syncthreads();
    }
    #pragma unroll
    for (int i=0;i<4;i++){
        int r = row0 + ty*4 + i;
        if (r >= M) continue;
        #pragma unroll
        for (int j=0;j<4;j++){
            int c = col0 + tx*4 + j;
            if (c >= N) continue;
            float v = acc[i][j];
            if (bias) v += bias[c];
            if (act)  v = fmaxf(v, 0.f);
            C[(size_t)r*ldc + c] = v;
        }
    }
}

// ================= GAT =================
__global__ void k_attn_coef(const float* __restrict__ att_src,
                            const float* __restrict__ att_dst){
    int wid  = (blockIdx.x*blockDim.x + threadIdx.x) >> 5;
    int lane = threadIdx.x & 31;
    if (wid >= NN*NH) return;
    int n = wid / NH, hh = wid % NH;
    const float* hp = d_h + (size_t)n*HF + hh*NF;
    float s1 = 0.f, s2 = 0.f;
    for (int f = lane; f < NF; f += 32){
        float v = hp[f];
        s1 += v * att_src[hh*NF + f];
        s2 += v * att_dst[hh*NF + f];
    }
    #pragma unroll
    for (int o=16;o>0;o>>=1){ s1 += __shfl_down_sync(~0u,s1,o); s2 += __shfl_down_sync(~0u,s2,o); }
    if (!lane){ d_asrc[wid] = s1; d_adst[wid] = s2; }
}

__global__ void k_gat_soft(){
    int w    = (blockIdx.x*blockDim.x + threadIdx.x) >> 5;
    int lane = threadIdx.x & 31;
    if (w >= NN || lane >= NH) return;
    int s0 = d_roff[w], s1 = d_roff[w+1];
    float ad = d_adst[w*NH + lane];
    float mx = -1e30f;
    for (int p = s0; p < s1; p++){
        float a = d_asrc[d_csrc[p]*NH + lane] + ad;
        a = a > 0.f ? a : 0.2f*a;
        mx = fmaxf(mx, a);
    }
    float sum = 0.f;
    for (int p = s0; p < s1; p++){
        float a = d_asrc[d_csrc[p]*NH + lane] + ad;
        a = a > 0.f ? a : 0.2f*a;
        float e = expf(a - mx);
        d_alpha[(size_t)p*NH + lane] = e;
        sum += e;
    }
    d_invden[w*NH + lane] = 1.f / (sum + 1e-16f);
}

__global__ void k_gat_agg(const float* __restrict__ gat_b){
    int n = blockIdx.x;
    int tid = threadIdx.x;
    __shared__ float invd[NH];
    __shared__ float sal[NH];
    __shared__ int   ssrc;
    if (tid < NH) invd[tid] = d_invden[n*NH + tid];
    int s0 = d_roff[n], s1 = d_roff[n+1];
    float acc[4] = {0.f,0.f,0.f,0.f};
    for (int p = s0; p < s1; p++){
        __syncthreads();
        if (tid < NH) sal[tid] = d_alpha[(size_t)p*NH + tid] * invd[tid];
        if (tid == 0) ssrc = d_csrc[p];
        __syncthreads();
        const float* hrow = d_h + (size_t)ssrc*HF;
        #pragma unroll
        for (int q=0;q<4;q++){
            int c = tid + q*256;
            if (c < HF) acc[q] += sal[c/NF] * hrow[c];
        }
    }
    #pragma unroll
    for (int q=0;q<4;q++){
        int c = tid + q*256;
        if (c < HF) d_x1[(size_t)n*HF + c] = fmaxf(acc[q] + gat_b[c], 0.f);
    }
}

// ================= GCN aggregate =================
__global__ void k_gcn_agg(const float* __restrict__ gcn_b){
    int n = blockIdx.x;
    int tid = threadIdx.x;
    int s0 = d_roff[n], s1 = d_roff[n+1];
    float dn = d_dinv[n];
    float acc[4] = {0.f,0.f,0.f,0.f};
    __shared__ int   ssrc;
    __shared__ float scoef;
    for (int p = s0; p < s1; p++){
        __syncthreads();
        if (tid == 0){
            int s = d_csrc[p];
            ssrc = s;
            scoef = dn * d_dinv[s];
        }
        __syncthreads();
        const float* hrow = d_h2 + (size_t)ssrc*HF;
        float coef = scoef;
        #pragma unroll
        for (int q=0;q<4;q++){
            int c = tid + q*256;
            if (c < HF) acc[q] += coef * hrow[c];
        }
    }
    #pragma unroll
    for (int q=0;q<4;q++){
        int c = tid + q*256;
        if (c < HF) d_x2[(size_t)n*HF + c] = fmaxf(acc[q] + gcn_b[c], 0.f);
    }
}

// ================= pooling =================
__global__ void k_start(const int* __restrict__ batch){
    int g = blockIdx.x*blockDim.x + threadIdx.x;
    if (g > NG) return;
    if (g == NG){ d_start[NG] = NN; return; }
    int lo = 0, hi = NN;
    while (lo < hi){ int mid = (lo+hi) >> 1; if (batch[mid] < g) lo = mid+1; else hi = mid; }
    d_start[g] = lo;
}
__global__ void k_pool(){
    int g = blockIdx.x;
    int s = d_start[g], e = d_start[g+1];
    int cnt = e - s;
    for (int c = threadIdx.x; c < HF; c += blockDim.x){
        float mx = -1e30f, sm = 0.f;
        for (int n = s; n < e; n++){
            float v = d_x2[(size_t)n*HF + c];
            mx = fmaxf(mx, v); sm += v;
        }
        d_pool[g*2*HF + c]      = (cnt > 0) ? mx : 0.f;
        d_pool[g*2*HF + HF + c] = sm / fmaxf((float)cnt, 1.f);
    }
}

// ================= target branch =================
__global__ void k_buildM(const float* __restrict__ emb){
    int i = blockIdx.x*blockDim.x + threadIdx.x;
    if (i >= UCOLS*CONVOUT) return;
    int p = i % CONVOUT, vk = i / CONVOUT;
    int v = vk >> 3, k = vk & 7;
    d_Mm[i] = emb[v*EMB + p + k];
}
__global__ void k_transW(const float* __restrict__ W){
    int i = blockIdx.x*blockDim.x + threadIdx.x;
    if (i >= NFILT*SEQL*8) return;
    int o = i / (SEQL*8), c = (i >> 3) % SEQL, k = i & 7;
    d_Wt[c*(NFILT*8) + o*8 + k] = W[i];
}
__global__ void k_buildU(const int* __restrict__ target){
    __shared__ float sU[USZ];
    __shared__ int   st[SEQL];
    int g = blockIdx.x;
    for (int i = threadIdx.x; i < USZ;  i += blockDim.x) sU[i] = 0.f;
    for (int i = threadIdx.x; i < SEQL; i += blockDim.x) st[i] = target[g*SEQL + i];
    __syncthreads();
    int o = threadIdx.x >> 3, k = threadIdx.x & 7;   // 256 threads = 32 x 8
    for (int c = 0; c < SEQL; c++){
        int v = st[c];
        sU[o*UCOLS + v*8 + k] += d_Wt[c*(NFILT*8) + threadIdx.x];
    }
    __syncthreads();
    for (int i = threadIdx.x; i < USZ; i += blockDim.x)
        d_U[(size_t)g*USZ + i] = sU[i];
}
__global__ void k_fcxtb2(const float* __restrict__ fcxt_W,
                         const float* __restrict__ fcxt_b,
                         const float* __restrict__ conv_b){
    int j = blockIdx.x;
    __shared__ float red[128];
    float s = 0.f;
    for (int r = threadIdx.x; r < NFILT*CONVOUT; r += blockDim.x)
        s += conv_b[r / CONVOUT] * fcxt_W[(size_t)r*128 + j];
    red[threadIdx.x] = s; __syncthreads();
    for (int o = 64; o > 0; o >>= 1){
        if (threadIdx.x < o) red[threadIdx.x] += red[threadIdx.x + o];
        __syncthreads();
    }
    if (!threadIdx.x) d_fcxtb2[j] = fcxt_b[j] + red[0];
}

// ================= final projection =================
__global__ void k_out(const float* __restrict__ oW, const float* __restrict__ ob,
                      float* __restrict__ out){
    int g    = (blockIdx.x*blockDim.x + threadIdx.x) >> 5;
    int lane = threadIdx.x & 31;
    if (g >= NG) return;
    float s = 0.f;
    for (int k = lane; k < 512; k += 32) s += d_f2[g*512 + k] * oW[k];
    #pragma unroll
    for (int o = 16; o > 0; o >>= 1) s += __shfl_down_sync(~0u, s, o);
    if (!lane) out[g] = s + ob[0];
}

// ================= launch =================
static inline void gemm_launch(const float* A, const float* B, const float* bias,
                               float* C, int M, int N, int K, int ldc, int act){
    dim3 grid((N + 63)/64, (M + 63)/64);
    gemm_kernel<<<grid, 256>>>(A, B, bias, C, M, N, K, ldc, act);
}
template<bool AV, bool BV>
static inline void gemm128_launch(const float* A, const float* B, float* C,
                                  int M, int N, int K, int ldc){
    dim3 grid((N + 127)/128, (M + 127)/128);
    gemm128_kernel<AV,BV><<<grid, 256>>>(A, B, C, M, N, K, ldc);
}

extern "C" void kernel_launch(void* const* d_in, const int* in_sizes, int n_in,
                              void* d_out, int out_size){
    const float* x        = (const float*)d_in[0];
    const int*   ei       = (const int*)  d_in[1];
    const int*   batch    = (const int*)  d_in[2];
    const int*   target   = (const int*)  d_in[3];
    const float* gat_W    = (const float*)d_in[4];
    const float* gat_asrc = (const float*)d_in[5];
    const float* gat_adst = (const float*)d_in[6];
    const float* gat_b    = (const float*)d_in[7];
    const float* gcn_W    = (const float*)d_in[8];
    const float* gcn_b    = (const float*)d_in[9];
    const float* fcg1_W   = (const float*)d_in[10];
    const float* fcg1_b   = (const float*)d_in[11];
    const float* fcg2_W   = (const float*)d_in[12];
    const float* fcg2_b   = (const float*)d_in[13];
    const float* emb      = (const float*)d_in[14];
    const float* conv_W   = (const float*)d_in[15];
    const float* conv_b   = (const float*)d_in[16];
    const float* fcxt_W   = (const float*)d_in[17];
    const float* fcxt_b   = (const float*)d_in[18];
    const float* fc1_W    = (const float*)d_in[19];
    const float* fc1_b    = (const float*)d_in[20];
    const float* fc2_W    = (const float*)d_in[21];
    const float* fc2_b    = (const float*)d_in[22];
    const float* out_W    = (const float*)d_in[23];
    const float* out_b    = (const float*)d_in[24];

    float *p_h, *p_x1, *p_h2, *p_x2, *p_pool, *p_xg1, *p_xc, *p_U, *p_Mm,
          *p_conv, *p_f1, *p_f2, *p_fcxtb2;
    cudaGetSymbolAddress((void**)&p_h,    d_h);
    cudaGetSymbolAddress((void**)&p_x1,   d_x1);
    cudaGetSymbolAddress((void**)&p_h2,   d_h2);
    cudaGetSymbolAddress((void**)&p_x2,   d_x2);
    cudaGetSymbolAddress((void**)&p_pool, d_pool);
    cudaGetSymbolAddress((void**)&p_xg1,  d_xg1);
    cudaGetSymbolAddress((void**)&p_xc,   d_xc);
    cudaGetSymbolAddress((void**)&p_U,    d_U);
    cudaGetSymbolAddress((void**)&p_Mm,   d_Mm);
    cudaGetSymbolAddress((void**)&p_conv, d_conv);
    cudaGetSymbolAddress((void**)&p_f1,   d_f1);
    cudaGetSymbolAddress((void**)&p_f2,   d_f2);
    cudaGetSymbolAddress((void**)&p_fcxtb2, d_fcxtb2);

    // ---- CSR build ----
    k_deg_init<<<(NN + 255)/256, 256>>>();
    k_count<<<(NE + 255)/256, 256>>>(ei);
    k_scan<<<1, 1024>>>();
    k_fill<<<(NEP + 255)/256, 256>>>(ei);
    k_dinv<<<(NN + 255)/256, 256>>>();

    // ---- GAT ----
    gemm128_launch<false,true>(x, gat_W, p_h, NN, HF, NF, HF);
    k_attn_coef<<<(NN*NH*32 + 255)/256, 256>>>(gat_asrc, gat_adst);
    k_gat_soft<<<(NN*32 + 255)/256, 256>>>();
    k_gat_agg<<<NN, 256>>>(gat_b);

    // ---- GCN ----
    gemm128_launch<true,true>(p_x1, gcn_W, p_h2, NN, HF, HF, HF);
    k_gcn_agg<<<NN, 256>>>(gcn_b);

    // ---- pooling + graph head ----
    k_start<<<3, 256>>>(batch);
    k_pool<<<NG, 256>>>();
    gemm_launch(p_pool, fcg1_W, fcg1_b, p_xg1, NG, 1024, 2*HF, 1024, 1);
    gemm_launch(p_xg1, fcg2_W, fcg2_b, p_xc, NG, 128, 1024, 256, 0);

    // ---- target branch (vocab-collapsed conv) ----
    k_buildM<<<(UCOLS*CONVOUT + 255)/256, 256>>>(emb);
    k_transW<<<(NFILT*SEQL*8 + 255)/256, 256>>>(conv_W);
    k_buildU<<<NG, 256>>>(target);
    gemm128_launch<true,false>(p_U, p_Mm, p_conv, NG*NFILT, CONVOUT, UCOLS, CONVOUT);
    k_fcxtb2<<<128, 128>>>(fcxt_W, fcxt_b, conv_b);
    gemm_launch(p_conv, fcxt_W, p_fcxtb2, p_xc + 128, NG, 128, NFILT*CONVOUT, 256, 0);

    // ---- fusion head ----
    gemm_launch(p_xc, fc1_W, fc1_b, p_f1, NG, 1024, 256, 1024, 1);
    gemm_launch(p_f1, fc2_W, fc2_b, p_f2, NG, 512, 1024, 512, 1);
    k_out<<<(NG*32 + 255)/256, 256>>>(out_W, out_b, (float*)d_out);
}

// round 4
// speedup vs baseline: 1.8234x; 1.4155x over previous
#include <cuda_runtime.h>
#include <cuda_bf16.h>
#include <math.h>
#include <stdint.h>

#define NN      25000
#define NE      100000
#define NEP     125000
#define NG      512
#define NH      10
#define NF      78
#define HF      780
#define SEQL    1000
#define EMB     128
#define NFILT   32
#define CONVOUT 121
#define VOCAB   26
#define UCOLS   (VOCAB*8)
#define USZ     (NFILT*UCOLS)

#define KP_GAT  128                 // padded K for GAT (78 -> 128)
#define KP_GCN  832                 // padded K for GCN (780 -> 832)
#define NPAD    896                 // padded N (7 x 128 tiles)

// ---------------- device scratch ----------------
__device__ float d_h[NN*HF];
__device__ float d_asrc[NN*NH];
__device__ float d_adst[NN*NH];
__device__ float d_invden[NN*NH];
__device__ float d_alpha[(size_t)NEP*NH];
__device__ float d_h2[NN*HF];
__device__ float d_x2[NN*HF];
__device__ float d_dinv[NN];
__device__ int   d_deg[NN];
__device__ int   d_roff[NN+1];
__device__ int   d_rpos[NN];
__device__ int   d_csrc[NEP];
__device__ int   d_start[NG+1];
__device__ float d_pool[NG*2*HF];
__device__ float d_xg1[NG*1024];
__device__ float d_Wt[SEQL*NFILT*8];
__device__ float d_U[(size_t)NG*USZ];
__device__ float d_Mm[UCOLS*CONVOUT];
__device__ float d_conv[(size_t)NG*NFILT*CONVOUT];
__device__ float d_fcxtb2[128];
__device__ float d_xc[NG*256];
__device__ float d_f1[NG*1024];
__device__ float d_f2[NG*512];
// bf16 split buffers (K-major rows, 16B-aligned pitches)
__device__ __nv_bfloat16 d_xh[(size_t)NN*KP_GAT];
__device__ __nv_bfloat16 d_xl[(size_t)NN*KP_GAT];
__device__ __nv_bfloat16 d_x1h[(size_t)NN*KP_GCN];
__device__ __nv_bfloat16 d_x1l[(size_t)NN*KP_GCN];
__device__ __nv_bfloat16 d_gWh[(size_t)NPAD*KP_GAT];
__device__ __nv_bfloat16 d_gWl[(size_t)NPAD*KP_GAT];
__device__ __nv_bfloat16 d_cWh[(size_t)NPAD*KP_GCN];
__device__ __nv_bfloat16 d_cWl[(size_t)NPAD*KP_GCN];

// ================= helpers =================
__device__ __forceinline__ uint32_t smem_u32(const void* p){
    uint32_t a;
    asm("{ .reg .u64 t; cvta.to.shared.u64 t, %1; cvt.u32.u64 %0, t; }" : "=r"(a) : "l"(p));
    return a;
}
#define LDMX4(r, a) \
    asm volatile("ldmatrix.sync.aligned.m8n8.x4.shared.b16 {%0,%1,%2,%3}, [%4];" \
        : "=r"((r)[0]), "=r"((r)[1]), "=r"((r)[2]), "=r"((r)[3]) : "r"(a))
#define MMA16816(d, a, b0, b1) \
    asm volatile("mma.sync.aligned.m16n8k16.row.col.f32.bf16.bf16.f32 " \
        "{%0,%1,%2,%3}, {%4,%5,%6,%7}, {%8,%9}, {%0,%1,%2,%3};" \
        : "+f"((d)[0]), "+f"((d)[1]), "+f"((d)[2]), "+f"((d)[3]) \
        : "r"((a)[0]), "r"((a)[1]), "r"((a)[2]), "r"((a)[3]), "r"(b0), "r"(b1))

// ================= mma.sync split-bf16 GEMM =================
// C[M x Nout] = (Ah+Al)[M x KP] @ (Bh+Bl)^T, B stored [NPAD x KP] K-major.
// Tile 128x128, BK=32; 8 warps, each 32(M) x 64(N).
#define GPITCH 40   // bf16 elems per smem row (32 data + 8 pad)

__global__ void __launch_bounds__(256, 2) gemm_mma(
    const __nv_bfloat16* __restrict__ Ah, const __nv_bfloat16* __restrict__ Al,
    const __nv_bfloat16* __restrict__ Bh, const __nv_bfloat16* __restrict__ Bl,
    float* __restrict__ C, int M, int Nout, int KP, int ldc)
{
    __shared__ __nv_bfloat16 sAh[128*GPITCH], sAl[128*GPITCH];
    __shared__ __nv_bfloat16 sBh[128*GPITCH], sBl[128*GPITCH];
    int tid = threadIdx.x;
    int m0 = blockIdx.y*128, n0 = blockIdx.x*128;
    int w = tid >> 5, lane = tid & 31;
    int wm = (w & 3) * 32;
    int wn = (w >> 2) * 64;

    uint32_t bAh = smem_u32(sAh), bAl = smem_u32(sAl);
    uint32_t bBh = smem_u32(sBh), bBl = smem_u32(sBl);

    float acc[2][8][4];
    #pragma unroll
    for (int i=0;i<2;i++)
        #pragma unroll
        for (int j=0;j<8;j++)
            #pragma unroll
            for (int q=0;q<4;q++) acc[i][j][q] = 0.f;

    // A-frag ldmatrix address offsets (per lane)
    int a_row = (lane & 15);
    int a_kc  = (lane >> 4) * 8;
    // B-frag ldmatrix address offsets (per lane)
    int b_row = ((lane >> 4) * 8) + (lane & 7);
    int b_kc  = ((lane >> 3) & 1) * 8;

    for (int k0 = 0; k0 < KP; k0 += 32){
        if (k0 > 0) __syncthreads();
        // load tiles: 512 vec8 slots each, 2 per thread
        #pragma unroll
        for (int i = 0; i < 2; i++){
            int v = tid + i*256;
            int r = v >> 2, cv = (v & 3) * 8;
            size_t ga = (size_t)(m0 + r)*KP + k0 + cv;
            uint4 vh = make_uint4(0,0,0,0), vl = make_uint4(0,0,0,0);
            if (m0 + r < M){
                vh = *(const uint4*)(Ah + ga);
                vl = *(const uint4*)(Al + ga);
            }
            *(uint4*)&sAh[r*GPITCH + cv] = vh;
            *(uint4*)&sAl[r*GPITCH + cv] = vl;
            size_t gb = (size_t)(n0 + r)*KP + k0 + cv;
            *(uint4*)&sBh[r*GPITCH + cv] = *(const uint4*)(Bh + gb);
            *(uint4*)&sBl[r*GPITCH + cv] = *(const uint4*)(Bl + gb);
        }
        __syncthreads();
        #pragma unroll
        for (int kk = 0; kk < 32; kk += 16){
            uint32_t ah[2][4], al[2][4];
            #pragma unroll
            for (int mt = 0; mt < 2; mt++){
                uint32_t off = (uint32_t)((wm + mt*16 + a_row)*GPITCH + kk + a_kc) * 2;
                LDMX4(ah[mt], bAh + off);
                LDMX4(al[mt], bAl + off);
            }
            #pragma unroll
            for (int nt2 = 0; nt2 < 4; nt2++){
                uint32_t offb = (uint32_t)((wn + nt2*16 + b_row)*GPITCH + kk + b_kc) * 2;
                uint32_t bh[4], bl[4];
                LDMX4(bh, bBh + offb);
                LDMX4(bl, bBl + offb);
                #pragma unroll
                for (int mt = 0; mt < 2; mt++){
                    MMA16816(acc[mt][nt2*2],   ah[mt], bh[0], bh[1]);
                    MMA16816(acc[mt][nt2*2],   ah[mt], bl[0], bl[1]);
                    MMA16816(acc[mt][nt2*2],   al[mt], bh[0], bh[1]);
                    MMA16816(acc[mt][nt2*2+1], ah[mt], bh[2], bh[3]);
                    MMA16816(acc[mt][nt2*2+1], ah[mt], bl[2], bl[3]);
                    MMA16816(acc[mt][nt2*2+1], al[mt], bh[2], bh[3]);
                }
            }
        }
    }
    // epilogue
    #pragma unroll
    for (int mt = 0; mt < 2; mt++){
        int r0 = m0 + wm + mt*16 + (lane >> 2);
        #pragma unroll
        for (int nt = 0; nt < 8; nt++){
            int c = n0 + wn + nt*8 + (lane & 3)*2;
            if (r0 < M){
                if (c   < Nout) C[(size_t)r0*ldc + c]   = acc[mt][nt][0];
                if (c+1 < Nout) C[(size_t)r0*ldc + c+1] = acc[mt][nt][1];
            }
            if (r0 + 8 < M){
                if (c   < Nout) C[(size_t)(r0+8)*ldc + c]   = acc[mt][nt][2];
                if (c+1 < Nout) C[(size_t)(r0+8)*ldc + c+1] = acc[mt][nt][3];
            }
        }
    }
}

// ================= split-prep kernels =================
__device__ __forceinline__ void split_bf16(float v, __nv_bfloat16& h, __nv_bfloat16& l){
    h = __float2bfloat16(v);
    l = __float2bfloat16(v - __bfloat162float(h));
}
__global__ void k_split_x(const float* __restrict__ x){
    int i = blockIdx.x*blockDim.x + threadIdx.x;
    if (i >= NN*KP_GAT) return;
    int r = i >> 7, k = i & (KP_GAT-1);
    float v = (k < NF) ? x[r*NF + k] : 0.f;
    split_bf16(v, d_xh[i], d_xl[i]);
}
__global__ void k_splitB(const float* __restrict__ W, __nv_bfloat16* __restrict__ bh,
                         __nv_bfloat16* __restrict__ bl, int K, int N, int KP){
    int i = blockIdx.x*blockDim.x + threadIdx.x;
    if (i >= NPAD*KP) return;
    int n = i / KP, k = i - n*KP;
    float v = (k < K && n < N) ? W[(size_t)k*N + n] : 0.f;
    __nv_bfloat16 h, l; split_bf16(v, h, l);
    bh[i] = h; bl[i] = l;
}

// ================= CSR build =================
__global__ void k_deg_init(){
    int n = blockIdx.x*blockDim.x + threadIdx.x;
    if (n < NN) d_deg[n] = 1;
}
__global__ void k_count(const int* __restrict__ ei){
    int e = blockIdx.x*blockDim.x + threadIdx.x;
    if (e < NE) atomicAdd(&d_deg[ei[NE+e]], 1);
}
__global__ void k_scan(){
    __shared__ int part[1024];
    int t = threadIdx.x;
    const int PER = 25;
    int base = t*PER, sum = 0;
    for (int i = 0; i < PER; i++){ int idx = base+i; if (idx < NN) sum += d_deg[idx]; }
    part[t] = sum; __syncthreads();
    for (int off = 1; off < 1024; off <<= 1){
        int v = (t >= off) ? part[t-off] : 0; __syncthreads();
        part[t] += v; __syncthreads();
    }
    int run = part[t] - sum;
    for (int i = 0; i < PER; i++){
        int idx = base+i;
        if (idx < NN){ d_roff[idx] = run; d_rpos[idx] = run; run += d_deg[idx]; }
    }
    if (t == 1023) d_roff[NN] = NEP;
}
__global__ void k_fill(const int* __restrict__ ei){
    int e = blockIdx.x*blockDim.x + threadIdx.x;
    if (e >= NEP) return;
    int s, d;
    if (e < NE){ s = ei[e]; d = ei[NE+e]; } else { s = d = e - NE; }
    int pos = atomicAdd(&d_rpos[d], 1);
    d_csrc[pos] = s;
}
__global__ void k_dinv(){
    int n = blockIdx.x*blockDim.x + threadIdx.x;
    if (n < NN) d_dinv[n] = rsqrtf((float)d_deg[n]);
}

// ================= GAT =================
__global__ void k_attn_coef(const float* __restrict__ att_src,
                            const float* __restrict__ att_dst){
    int wid  = (blockIdx.x*blockDim.x + threadIdx.x) >> 5;
    int lane = threadIdx.x & 31;
    if (wid >= NN*NH) return;
    int n = wid / NH, hh = wid % NH;
    const float* hp = d_h + (size_t)n*HF + hh*NF;
    float s1 = 0.f, s2 = 0.f;
    for (int f = lane; f < NF; f += 32){
        float v = hp[f];
        s1 += v * att_src[hh*NF + f];
        s2 += v * att_dst[hh*NF + f];
    }
    #pragma unroll
    for (int o=16;o>0;o>>=1){ s1 += __shfl_down_sync(~0u,s1,o); s2 += __shfl_down_sync(~0u,s2,o); }
    if (!lane){ d_asrc[wid] = s1; d_adst[wid] = s2; }
}
__global__ void k_gat_soft(){
    int w    = (blockIdx.x*blockDim.x + threadIdx.x) >> 5;
    int lane = threadIdx.x & 31;
    if (w >= NN || lane >= NH) return;
    int s0 = d_roff[w], s1 = d_roff[w+1];
    float ad = d_adst[w*NH + lane];
    float mx = -1e30f;
    for (int p = s0; p < s1; p++){
        float a = d_asrc[d_csrc[p]*NH + lane] + ad;
        a = a > 0.f ? a : 0.2f*a;
        mx = fmaxf(mx, a);
    }
    float sum = 0.f;
    for (int p = s0; p < s1; p++){
        float a = d_asrc[d_csrc[p]*NH + lane] + ad;
        a = a > 0.f ? a : 0.2f*a;
        float e = expf(a - mx);
        d_alpha[(size_t)p*NH + lane] = e;
        sum += e;
    }
    d_invden[w*NH + lane] = 1.f / (sum + 1e-16f);
}
__global__ void k_gat_agg(const float* __restrict__ gat_b){
    int n = blockIdx.x;
    int tid = threadIdx.x;
    __shared__ float invd[NH];
    __shared__ float sal[NH];
    __shared__ int   ssrc;
    if (tid < NH) invd[tid] = d_invden[n*NH + tid];
    int s0 = d_roff[n], s1 = d_roff[n+1];
    float acc[4] = {0.f,0.f,0.f,0.f};
    for (int p = s0; p < s1; p++){
        __syncthreads();
        if (tid < NH) sal[tid] = d_alpha[(size_t)p*NH + tid] * invd[tid];
        if (tid == 0) ssrc = d_csrc[p];
        __syncthreads();
        const float* hrow = d_h + (size_t)ssrc*HF;
        #pragma unroll
        for (int q=0;q<4;q++){
            int c = tid + q*256;
            if (c < HF) acc[q] += sal[c/NF] * hrow[c];
        }
    }
    #pragma unroll
    for (int q=0;q<4;q++){
        int c = tid + q*256;
        if (c < KP_GCN){
            float v = (c < HF) ? fmaxf(acc[q] + gat_b[c], 0.f) : 0.f;
            __nv_bfloat16 h, l; split_bf16(v, h, l);
            d_x1h[(size_t)n*KP_GCN + c] = h;
            d_x1l[(size_t)n*KP_GCN + c] = l;
        }
    }
}

// ================= GCN aggregate =================
__global__ void k_gcn_agg(const float* __restrict__ gcn_b){
    int n = blockIdx.x;
    int tid = threadIdx.x;
    int s0 = d_roff[n], s1 = d_roff[n+1];
    float dn = d_dinv[n];
    float acc[4] = {0.f,0.f,0.f,0.f};
    __shared__ int   ssrc;
    __shared__ float scoef;
    for (int p = s0; p < s1; p++){
        __syncthreads();
        if (tid == 0){
            int s = d_csrc[p];
            ssrc = s;
            scoef = dn * d_dinv[s];
        }
        __syncthreads();
        const float* hrow = d_h2 + (size_t)ssrc*HF;
        float coef = scoef;
        #pragma unroll
        for (int q=0;q<4;q++){
            int c = tid + q*256;
            if (c < HF) acc[q] += coef * hrow[c];
        }
    }
    #pragma unroll
    for (int q=0;q<4;q++){
        int c = tid + q*256;
        if (c < HF) d_x2[(size_t)n*HF + c] = fmaxf(acc[q] + gcn_b[c], 0.f);
    }
}

// ================= pooling =================
__global__ void k_start(const int* __restrict__ batch){
    int g = blockIdx.x*blockDim.x + threadIdx.x;
    if (g > NG) return;
    if (g == NG){ d_start[NG] = NN; return; }
    int lo = 0, hi = NN;
    while (lo < hi){ int mid = (lo+hi) >> 1; if (batch[mid] < g) lo = mid+1; else hi = mid; }
    d_start[g] = lo;
}
__global__ void k_pool(){
    int g = blockIdx.x;
    int s = d_start[g], e = d_start[g+1];
    int cnt = e - s;
    for (int c = threadIdx.x; c < HF; c += blockDim.x){
        float mx = -1e30f, sm = 0.f;
        for (int n = s; n < e; n++){
            float v = d_x2[(size_t)n*HF + c];
            mx = fmaxf(mx, v); sm += v;
        }
        d_pool[g*2*HF + c]      = (cnt > 0) ? mx : 0.f;
        d_pool[g*2*HF + HF + c] = sm / fmaxf((float)cnt, 1.f);
    }
}

// ================= small GEMM (fp32, bias/act) =================
__global__ void gemm_kernel(const float* __restrict__ A, const float* __restrict__ B,
                            const float* __restrict__ bias, float* __restrict__ C,
                            int M, int N, int K, int ldc, int act)
{
    __shared__ float As[16*64];
    __shared__ float Bs[16*64];
    int tid = threadIdx.x;
    int row0 = blockIdx.y*64, col0 = blockIdx.x*64;
    int tx = tid & 15, ty = tid >> 4;
    float acc[4][4] = {};
    for (int k0 = 0; k0 < K; k0 += 16){
        #pragma unroll
        for (int i=0;i<4;i++){
            int l = tid + i*256;
            int m = l >> 4, kk = l & 15;
            int r = row0 + m, kg = k0 + kk;
            As[kk*64+m] = (r < M && kg < K) ? A[(size_t)r*K + kg] : 0.f;
        }
        #pragma unroll
        for (int i=0;i<4;i++){
            int l = tid + i*256;
            int kk = l >> 6, n = l & 63;
            int kg = k0 + kk, c = col0 + n;
            Bs[kk*64+n] = (kg < K && c < N) ? B[(size_t)kg*N + c] : 0.f;
        }
        __syncthreads();
        #pragma unroll
        for (int kk=0; kk<16; kk++){
            float ra[4], rb[4];
            #pragma unroll
            for (int i=0;i<4;i++) ra[i] = As[kk*64 + ty*4 + i];
            #pragma unroll
            for (int j=0;j<4;j++) rb[j] = Bs[kk*64 + tx*4 + j];
            #pragma unroll
            for (int i=0;i<4;i++)
                #pragma unroll
                for (int j=0;j<4;j++)
                    acc[i][j] += ra[i]*rb[j];
        }
        __syncthreads();
    }
    #pragma unroll
    for (int i=0;i<4;i++){
        int r = row0 + ty*4 + i;
        if (r >= M) continue;
        #pragma unroll
        for (int j=0;j<4;j++){
            int c = col0 + tx*4 + j;
            if (c >= N) continue;
            float v = acc[i][j];
            if (bias) v += bias[c];
            if (act)  v = fmaxf(v, 0.f);
            C[(size_t)r*ldc + c] = v;
        }
    }
}

// ================= target branch =================
__global__ void k_buildM(const float* __restrict__ emb){
    int i = blockIdx.x*blockDim.x + threadIdx.x;
    if (i >= UCOLS*CONVOUT) return;
    int p = i % CONVOUT, vk = i / CONVOUT;
    int v = vk >> 3, k = vk & 7;
    d_Mm[i] = emb[v*EMB + p + k];
}
__global__ void k_transW(const float* __restrict__ W){
    int i = blockIdx.x*blockDim.x + threadIdx.x;
    if (i >= NFILT*SEQL*8) return;
    int o = i / (SEQL*8), c = (i >> 3) % SEQL, k = i & 7;
    d_Wt[c*(NFILT*8) + o*8 + k] = W[i];
}
__global__ void k_buildU(const int* __restrict__ target){
    __shared__ float sU[USZ];
    __shared__ int   st[SEQL];
    int g = blockIdx.x;
    for (int i = threadIdx.x; i < USZ;  i += blockDim.x) sU[i] = 0.f;
    for (int i = threadIdx.x; i < SEQL; i += blockDim.x) st[i] = target[g*SEQL + i];
    __syncthreads();
    int o = threadIdx.x >> 3, k = threadIdx.x & 7;
    for (int c = 0; c < SEQL; c++){
        int v = st[c];
        sU[o*UCOLS + v*8 + k] += d_Wt[c*(NFILT*8) + threadIdx.x];
    }
    __syncthreads();
    for (int i = threadIdx.x; i < USZ; i += blockDim.x)
        d_U[(size_t)g*USZ + i] = sU[i];
}
__global__ void k_fcxtb2(const float* __restrict__ fcxt_W,
                         const float* __restrict__ fcxt_b,
                         const float* __restrict__ conv_b){
    int j = blockIdx.x;
    __shared__ float red[128];
    float s = 0.f;
    for (int r = threadIdx.x; r < NFILT*CONVOUT; r += blockDim.x)
        s += conv_b[r / CONVOUT] * fcxt_W[(size_t)r*128 + j];
    red[threadIdx.x] = s; __syncthreads();
    for (int o = 64; o > 0; o >>= 1){
        if (threadIdx.x < o) red[threadIdx.x] += red[threadIdx.x + o];
        __syncthreads();
    }
    if (!threadIdx.x) d_fcxtb2[j] = fcxt_b[j] + red[0];
}

// ================= final projection =================
__global__ void k_out(const float* __restrict__ oW, const float* __restrict__ ob,
                      float* __restrict__ out){
    int g    = (blockIdx.x*blockDim.x + threadIdx.x) >> 5;
    int lane = threadIdx.x & 31;
    if (g >= NG) return;
    float s = 0.f;
    for (int k = lane; k < 512; k += 32) s += d_f2[g*512 + k] * oW[k];
    #pragma unroll
    for (int o = 16; o > 0; o >>= 1) s += __shfl_down_sync(~0u, s, o);
    if (!lane) out[g] = s + ob[0];
}

// ================= launch =================
static inline void gemm_launch(const float* A, const float* B, const float* bias,
                               float* C, int M, int N, int K, int ldc, int act){
    dim3 grid((N + 63)/64, (M + 63)/64);
    gemm_kernel<<<grid, 256>>>(A, B, bias, C, M, N, K, ldc, act);
}

extern "C" void kernel_launch(void* const* d_in, const int* in_sizes, int n_in,
                              void* d_out, int out_size){
    const float* x        = (const float*)d_in[0];
    const int*   ei       = (const int*)  d_in[1];
    const int*   batch    = (const int*)  d_in[2];
    const int*   target   = (const int*)  d_in[3];
    const float* gat_W    = (const float*)d_in[4];
    const float* gat_asrc = (const float*)d_in[5];
    const float* gat_adst = (const float*)d_in[6];
    const float* gat_b    = (const float*)d_in[7];
    const float* gcn_W    = (const float*)d_in[8];
    const float* gcn_b    = (const float*)d_in[9];
    const float* fcg1_W   = (const float*)d_in[10];
    const float* fcg1_b   = (const float*)d_in[11];
    const float* fcg2_W   = (const float*)d_in[12];
    const float* fcg2_b   = (const float*)d_in[13];
    const float* emb      = (const float*)d_in[14];
    const float* conv_W   = (const float*)d_in[15];
    const float* conv_b   = (const float*)d_in[16];
    const float* fcxt_W   = (const float*)d_in[17];
    const float* fcxt_b   = (const float*)d_in[18];
    const float* fc1_W    = (const float*)d_in[19];
    const float* fc1_b    = (const float*)d_in[20];
    const float* fc2_W    = (const float*)d_in[21];
    const float* fc2_b    = (const float*)d_in[22];
    const float* out_W    = (const float*)d_in[23];
    const float* out_b    = (const float*)d_in[24];

    float *p_h, *p_h2, *p_x2, *p_pool, *p_xg1, *p_xc, *p_U, *p_Mm, *p_conv,
          *p_f1, *p_f2, *p_fcxtb2;
    __nv_bfloat16 *p_xh, *p_xl, *p_x1h, *p_x1l, *p_gWh, *p_gWl, *p_cWh, *p_cWl;
    cudaGetSymbolAddress((void**)&p_h,    d_h);
    cudaGetSymbolAddress((void**)&p_h2,   d_h2);
    cudaGetSymbolAddress((void**)&p_x2,   d_x2);
    cudaGetSymbolAddress((void**)&p_pool, d_pool);
    cudaGetSymbolAddress((void**)&p_xg1,  d_xg1);
    cudaGetSymbolAddress((void**)&p_xc,   d_xc);
    cudaGetSymbolAddress((void**)&p_U,    d_U);
    cudaGetSymbolAddress((void**)&p_Mm,   d_Mm);
    cudaGetSymbolAddress((void**)&p_conv, d_conv);
    cudaGetSymbolAddress((void**)&p_f1,   d_f1);
    cudaGetSymbolAddress((void**)&p_f2,   d_f2);
    cudaGetSymbolAddress((void**)&p_fcxtb2, d_fcxtb2);
    cudaGetSymbolAddress((void**)&p_xh,  d_xh);
    cudaGetSymbolAddress((void**)&p_xl,  d_xl);
    cudaGetSymbolAddress((void**)&p_x1h, d_x1h);
    cudaGetSymbolAddress((void**)&p_x1l, d_x1l);
    cudaGetSymbolAddress((void**)&p_gWh, d_gWh);
    cudaGetSymbolAddress((void**)&p_gWl, d_gWl);
    cudaGetSymbolAddress((void**)&p_cWh, d_cWh);
    cudaGetSymbolAddress((void**)&p_cWl, d_cWl);

    // ---- CSR build ----
    k_deg_init<<<(NN + 255)/256, 256>>>();
    k_count<<<(NE + 255)/256, 256>>>(ei);
    k_scan<<<1, 1024>>>();
    k_fill<<<(NEP + 255)/256, 256>>>(ei);
    k_dinv<<<(NN + 255)/256, 256>>>();

    // ---- split-bf16 prep ----
    k_split_x<<<(NN*KP_GAT + 255)/256, 256>>>(x);
    k_splitB<<<(NPAD*KP_GAT + 255)/256, 256>>>(gat_W, p_gWh, p_gWl, NF, HF, KP_GAT);
    k_splitB<<<(NPAD*KP_GCN + 255)/256, 256>>>(gcn_W, p_cWh, p_cWl, HF, HF, KP_GCN);

    // ---- GAT: h = x @ gat_W (tensor cores via mma.sync) ----
    {
        dim3 grid(NPAD/128, (NN + 127)/128);
        gemm_mma<<<grid, 256>>>(p_xh, p_xl, p_gWh, p_gWl, p_h, NN, HF, KP_GAT, HF);
    }
    k_attn_coef<<<(NN*NH*32 + 255)/256, 256>>>(gat_asrc, gat_adst);
    k_gat_soft<<<(NN*32 + 255)/256, 256>>>();
    k_gat_agg<<<NN, 256>>>(gat_b);

    // ---- GCN: h2 = x1 @ gcn_W (tensor cores via mma.sync) ----
    {
        dim3 grid(NPAD/128, (NN + 127)/128);
        gemm_mma<<<grid, 256>>>(p_x1h, p_x1l, p_cWh, p_cWl, p_h2, NN, HF, KP_GCN, HF);
    }
    k_gcn_agg<<<NN, 256>>>(gcn_b);

    // ---- pooling + graph head ----
    k_start<<<3, 256>>>(batch);
    k_pool<<<NG, 256>>>();
    gemm_launch(p_pool, fcg1_W, fcg1_b, p_xg1, NG, 1024, 2*HF, 1024, 1);
    gemm_launch(p_xg1, fcg2_W, fcg2_b, p_xc, NG, 128, 1024, 256, 0);

    // ---- target branch ----
    k_buildM<<<(UCOLS*CONVOUT + 255)/256, 256>>>(emb);
    k_transW<<<(NFILT*SEQL*8 + 255)/256, 256>>>(conv_W);
    k_buildU<<<NG, 256>>>(target);
    gemm_launch(p_U, p_Mm, nullptr, p_conv, NG*NFILT, CONVOUT, UCOLS, CONVOUT, 0);
    k_fcxtb2<<<128, 128>>>(fcxt_W, fcxt_b, conv_b);
    gemm_launch(p_conv, fcxt_W, p_fcxtb2, p_xc + 128, NG, 128, NFILT*CONVOUT, 256, 0);

    // ---- fusion head ----
    gemm_launch(p_xc, fc1_W, fc1_b, p_f1, NG, 1024, 256, 1024, 1);
    gemm_launch(p_f1, fc2_W, fc2_b, p_f2, NG, 512, 1024, 512, 1);
    k_out<<<(NG*32 + 255)/256, 256>>>(out_W, out_b, (float*)d_out);
}

// round 5
// speedup vs baseline: 2.2845x; 1.2529x over previous
#include <cuda_runtime.h>
#include <cuda_bf16.h>
#include <math.h>
#include <stdint.h>

#define NN      25000
#define NE      100000
#define NEP     125000
#define NG      512
#define NH      10
#define NF      78
#define HF      780
#define SEQL    1000
#define EMB     128
#define NFILT   32
#define CONVOUT 121
#define VOCAB   26
#define UCOLS   (VOCAB*8)
#define USZ     (NFILT*UCOLS)

#define KP_GAT  128
#define KP_GCN  832
#define NPAD    896

// ---------------- device scratch ----------------
__device__ float d_h[NN*HF];
__device__ float d_asrc[NN*NH];
__device__ float d_adst[NN*NH];
__device__ float d_invden[NN*NH];
__device__ float d_alpha[(size_t)NEP*NH];
__device__ float d_h2[NN*HF];
__device__ float d_x2[NN*HF];
__device__ float d_dinv[NN];
__device__ int   d_deg[NN];
__device__ int   d_roff[NN+1];
__device__ int   d_rpos[NN];
__device__ int   d_csrc[NEP];
__device__ int   d_start[NG+1];
__device__ float d_pool[NG*2*HF];
__device__ float d_xg1[NG*1024];
__device__ float d_Wt[SEQL*NFILT*8];
__device__ float d_U[(size_t)NG*USZ];
__device__ float d_Mm[UCOLS*CONVOUT];
__device__ float d_conv[(size_t)NG*NFILT*CONVOUT];
__device__ float d_fcxtb2[128];
__device__ float d_xc[NG*256];
__device__ float d_f1[NG*1024];
__device__ float d_f2[NG*512];
__device__ __nv_bfloat16 d_xh[(size_t)NN*KP_GAT];
__device__ __nv_bfloat16 d_xl[(size_t)NN*KP_GAT];
__device__ __nv_bfloat16 d_x1h[(size_t)NN*KP_GCN];
__device__ __nv_bfloat16 d_x1l[(size_t)NN*KP_GCN];
__device__ __nv_bfloat16 d_gWh[(size_t)NPAD*KP_GAT];
__device__ __nv_bfloat16 d_gWl[(size_t)NPAD*KP_GAT];
__device__ __nv_bfloat16 d_cWh[(size_t)NPAD*KP_GCN];
__device__ __nv_bfloat16 d_cWl[(size_t)NPAD*KP_GCN];

// ================= helpers =================
__device__ __forceinline__ uint32_t smem_u32(const void* p){
    uint32_t a;
    asm("{ .reg .u64 t; cvta.to.shared.u64 t, %1; cvt.u32.u64 %0, t; }" : "=r"(a) : "l"(p));
    return a;
}
#define LDMX4(r, a) \
    asm volatile("ldmatrix.sync.aligned.m8n8.x4.shared.b16 {%0,%1,%2,%3}, [%4];" \
        : "=r"((r)[0]), "=r"((r)[1]), "=r"((r)[2]), "=r"((r)[3]) : "r"(a))
#define MMA16816(d, a, b0, b1) \
    asm volatile("mma.sync.aligned.m16n8k16.row.col.f32.bf16.bf16.f32 " \
        "{%0,%1,%2,%3}, {%4,%5,%6,%7}, {%8,%9}, {%0,%1,%2,%3};" \
        : "+f"((d)[0]), "+f"((d)[1]), "+f"((d)[2]), "+f"((d)[3]) \
        : "r"((a)[0]), "r"((a)[1]), "r"((a)[2]), "r"((a)[3]), "r"(b0), "r"(b1))
#define CPA_COMMIT() asm volatile("cp.async.commit_group;" ::: "memory")
#define CPA_WAIT0()  asm volatile("cp.async.wait_group 0;" ::: "memory")

__device__ __forceinline__ void cpa16(uint32_t dst, const void* src, int sz){
    size_t g;
    asm("cvta.to.global.u64 %0, %1;" : "=l"(g) : "l"(src));
    asm volatile("cp.async.cg.shared.global [%0], [%1], 16, %2;" :: "r"(dst), "l"(g), "r"(sz) : "memory");
}

// ================= mma.sync split-bf16 GEMM, cp.async double-buffered =================
#define GPITCH 40
#define TILEB  10240          // 128 * GPITCH * 2 bytes
#define STG    40960          // 4 arrays per stage

__device__ __forceinline__ void ld_tile(uint32_t sdst, const __nv_bfloat16* G,
                                        int row0, int k0, int KP, int rlim, int tid){
    #pragma unroll
    for (int i = 0; i < 2; i++){
        int v = tid + i*256;
        int r = v >> 2, cq = v & 3;
        int row = row0 + r;
        int sz = (row < rlim) ? 16 : 0;
        const void* src = G + (size_t)(sz ? row : row0)*KP + k0 + cq*8;
        cpa16(sdst + r*80 + cq*16, src, sz);
    }
}

__global__ void __launch_bounds__(256, 2) gemm_mma(
    const __nv_bfloat16* __restrict__ Ah, const __nv_bfloat16* __restrict__ Al,
    const __nv_bfloat16* __restrict__ Bh, const __nv_bfloat16* __restrict__ Bl,
    float* __restrict__ C, int M, int Nout, int KP, int ldc)
{
    extern __shared__ char sm[];
    uint32_t sb = smem_u32(sm);
    int tid = threadIdx.x;
    int m0 = blockIdx.y*128, n0 = blockIdx.x*128;
    int w = tid >> 5, lane = tid & 31;
    int wm = (w & 3) * 32;
    int wn = (w >> 2) * 64;
    int NC = KP / 32;

    float acc[2][8][4];
    #pragma unroll
    for (int i=0;i<2;i++)
        #pragma unroll
        for (int j=0;j<8;j++)
            #pragma unroll
            for (int q=0;q<4;q++) acc[i][j][q] = 0.f;

    int a_row = (lane & 15);
    int a_kc  = (lane >> 4) * 8;
    int b_row = ((lane >> 4) * 8) + (lane & 7);
    int b_kc  = ((lane >> 3) & 1) * 8;

    // prologue: stage 0 <- chunk 0
    ld_tile(sb + 0*TILEB, Ah, m0, 0, KP, M, tid);
    ld_tile(sb + 1*TILEB, Al, m0, 0, KP, M, tid);
    ld_tile(sb + 2*TILEB, Bh, n0, 0, KP, 1<<30, tid);
    ld_tile(sb + 3*TILEB, Bl, n0, 0, KP, 1<<30, tid);
    CPA_COMMIT();

    for (int ci = 0; ci < NC; ci++){
        int b = ci & 1;
        uint32_t st = sb + b*STG;
        CPA_WAIT0();
        __syncthreads();
        if (ci + 1 < NC){
            uint32_t s2 = sb + (1-b)*STG;
            int k0n = (ci+1)*32;
            ld_tile(s2 + 0*TILEB, Ah, m0, k0n, KP, M, tid);
            ld_tile(s2 + 1*TILEB, Al, m0, k0n, KP, M, tid);
            ld_tile(s2 + 2*TILEB, Bh, n0, k0n, KP, 1<<30, tid);
            ld_tile(s2 + 3*TILEB, Bl, n0, k0n, KP, 1<<30, tid);
            CPA_COMMIT();
        }
        uint32_t bAh = st, bAl = st + TILEB, bBh = st + 2*TILEB, bBl = st + 3*TILEB;
        #pragma unroll
        for (int kk = 0; kk < 32; kk += 16){
            uint32_t ah[2][4], al[2][4];
            #pragma unroll
            for (int mt = 0; mt < 2; mt++){
                uint32_t off = (uint32_t)((wm + mt*16 + a_row)*GPITCH + kk + a_kc) * 2;
                LDMX4(ah[mt], bAh + off);
                LDMX4(al[mt], bAl + off);
            }
            #pragma unroll
            for (int nt2 = 0; nt2 < 4; nt2++){
                uint32_t offb = (uint32_t)((wn + nt2*16 + b_row)*GPITCH + kk + b_kc) * 2;
                uint32_t bh[4], bl[4];
                LDMX4(bh, bBh + offb);
                LDMX4(bl, bBl + offb);
                #pragma unroll
                for (int mt = 0; mt < 2; mt++){
                    MMA16816(acc[mt][nt2*2],   ah[mt], bh[0], bh[1]);
                    MMA16816(acc[mt][nt2*2],   ah[mt], bl[0], bl[1]);
                    MMA16816(acc[mt][nt2*2],   al[mt], bh[0], bh[1]);
                    MMA16816(acc[mt][nt2*2+1], ah[mt], bh[2], bh[3]);
                    MMA16816(acc[mt][nt2*2+1], ah[mt], bl[2], bl[3]);
                    MMA16816(acc[mt][nt2*2+1], al[mt], bh[2], bh[3]);
                }
            }
        }
    }
    #pragma unroll
    for (int mt = 0; mt < 2; mt++){
        int r0 = m0 + wm + mt*16 + (lane >> 2);
        #pragma unroll
        for (int nt = 0; nt < 8; nt++){
            int c = n0 + wn + nt*8 + (lane & 3)*2;
            if (r0 < M){
                if (c   < Nout) C[(size_t)r0*ldc + c]   = acc[mt][nt][0];
                if (c+1 < Nout) C[(size_t)r0*ldc + c+1] = acc[mt][nt][1];
            }
            if (r0 + 8 < M){
                if (c   < Nout) C[(size_t)(r0+8)*ldc + c]   = acc[mt][nt][2];
                if (c+1 < Nout) C[(size_t)(r0+8)*ldc + c+1] = acc[mt][nt][3];
            }
        }
    }
}

// ================= split-prep =================
__device__ __forceinline__ void split_bf16(float v, __nv_bfloat16& h, __nv_bfloat16& l){
    h = __float2bfloat16(v);
    l = __float2bfloat16(v - __bfloat162float(h));
}
__global__ void k_split_x(const float* __restrict__ x){
    int i = blockIdx.x*blockDim.x + threadIdx.x;
    if (i >= NN*KP_GAT) return;
    int r = i >> 7, k = i & (KP_GAT-1);
    float v = (k < NF) ? x[r*NF + k] : 0.f;
    split_bf16(v, d_xh[i], d_xl[i]);
}
__global__ void k_splitB(const float* __restrict__ W, __nv_bfloat16* __restrict__ bh,
                         __nv_bfloat16* __restrict__ bl, int K, int N, int KP){
    int i = blockIdx.x*blockDim.x + threadIdx.x;
    if (i >= NPAD*KP) return;
    int n = i / KP, k = i - n*KP;
    float v = (k < K && n < N) ? W[(size_t)k*N + n] : 0.f;
    __nv_bfloat16 h, l; split_bf16(v, h, l);
    bh[i] = h; bl[i] = l;
}

// ================= CSR build =================
__global__ void k_deg_init(){
    int n = blockIdx.x*blockDim.x + threadIdx.x;
    if (n < NN) d_deg[n] = 1;
}
__global__ void k_count(const int* __restrict__ ei){
    int e = blockIdx.x*blockDim.x + threadIdx.x;
    if (e < NE) atomicAdd(&d_deg[ei[NE+e]], 1);
}
__global__ void k_scan(){
    __shared__ int part[1024];
    int t = threadIdx.x;
    const int PER = 25;
    int base = t*PER, sum = 0;
    for (int i = 0; i < PER; i++){ int idx = base+i; if (idx < NN) sum += d_deg[idx]; }
    part[t] = sum; __syncthreads();
    for (int off = 1; off < 1024; off <<= 1){
        int v = (t >= off) ? part[t-off] : 0; __syncthreads();
        part[t] += v; __syncthreads();
    }
    int run = part[t] - sum;
    for (int i = 0; i < PER; i++){
        int idx = base+i;
        if (idx < NN){ d_roff[idx] = run; d_rpos[idx] = run; run += d_deg[idx]; }
    }
    if (t == 1023) d_roff[NN] = NEP;
}
__global__ void k_fill(const int* __restrict__ ei){
    int e = blockIdx.x*blockDim.x + threadIdx.x;
    if (e >= NEP) return;
    int s, d;
    if (e < NE){ s = ei[e]; d = ei[NE+e]; } else { s = d = e - NE; }
    int pos = atomicAdd(&d_rpos[d], 1);
    d_csrc[pos] = s;
}
__global__ void k_dinv(){
    int n = blockIdx.x*blockDim.x + threadIdx.x;
    if (n < NN) d_dinv[n] = rsqrtf((float)d_deg[n]);
}

// ================= GAT =================
__global__ void k_attn_coef(const float* __restrict__ att_src,
                            const float* __restrict__ att_dst){
    int wid  = (blockIdx.x*blockDim.x + threadIdx.x) >> 5;
    int lane = threadIdx.x & 31;
    if (wid >= NN*NH) return;
    int n = wid / NH, hh = wid % NH;
    const float* hp = d_h + (size_t)n*HF + hh*NF;
    float s1 = 0.f, s2 = 0.f;
    for (int f = lane; f < NF; f += 32){
        float v = hp[f];
        s1 += v * att_src[hh*NF + f];
        s2 += v * att_dst[hh*NF + f];
    }
    #pragma unroll
    for (int o=16;o>0;o>>=1){ s1 += __shfl_down_sync(~0u,s1,o); s2 += __shfl_down_sync(~0u,s2,o); }
    if (!lane){ d_asrc[wid] = s1; d_adst[wid] = s2; }
}
__global__ void k_gat_soft(){
    int w    = (blockIdx.x*blockDim.x + threadIdx.x) >> 5;
    int lane = threadIdx.x & 31;
    if (w >= NN || lane >= NH) return;
    int s0 = d_roff[w], s1 = d_roff[w+1];
    float ad = d_adst[w*NH + lane];
    float mx = -1e30f;
    for (int p = s0; p < s1; p++){
        float a = d_asrc[d_csrc[p]*NH + lane] + ad;
        a = a > 0.f ? a : 0.2f*a;
        mx = fmaxf(mx, a);
    }
    float sum = 0.f;
    for (int p = s0; p < s1; p++){
        float a = d_asrc[d_csrc[p]*NH + lane] + ad;
        a = a > 0.f ? a : 0.2f*a;
        float e = expf(a - mx);
        d_alpha[(size_t)p*NH + lane] = e;
        sum += e;
    }
    d_invden[w*NH + lane] = 1.f / (sum + 1e-16f);
}

// chunked GAT aggregation: 25 edges staged per round
__global__ void k_gat_agg(const float* __restrict__ gat_b){
    int n = blockIdx.x;
    int tid = threadIdx.x;
    __shared__ float invd[NH];
    __shared__ int   csrc_c[25];
    __shared__ float coef_c[25][NH];
    if (tid < NH) invd[tid] = d_invden[n*NH + tid];
    __syncthreads();
    int s0 = d_roff[n], s1 = d_roff[n+1];
    float4 acc = make_float4(0.f,0.f,0.f,0.f);
    int c0 = tid*4;
    int h0 = c0/NF, h1 = (c0+1)/NF, h2 = (c0+2)/NF, h3 = (c0+3)/NF;
    for (int base = s0; base < s1; base += 25){
        int cnt = s1 - base; if (cnt > 25) cnt = 25;
        if (tid < cnt) csrc_c[tid] = d_csrc[base + tid];
        if (tid < cnt*NH){
            int p = tid / NH, hh = tid - p*NH;
            coef_c[p][hh] = d_alpha[(size_t)(base+p)*NH + hh] * invd[hh];
        }
        __syncthreads();
        if (tid < 195){
            #pragma unroll 2
            for (int j = 0; j < cnt; j++){
                float4 v = *(const float4*)(d_h + (size_t)csrc_c[j]*HF + c0);
                acc.x += coef_c[j][h0]*v.x;
                acc.y += coef_c[j][h1]*v.y;
                acc.z += coef_c[j][h2]*v.z;
                acc.w += coef_c[j][h3]*v.w;
            }
        }
        __syncthreads();
    }
    if (tid < 195){
        float4 bb = *(const float4*)(gat_b + c0);
        float r[4] = { fmaxf(acc.x + bb.x, 0.f), fmaxf(acc.y + bb.y, 0.f),
                       fmaxf(acc.z + bb.z, 0.f), fmaxf(acc.w + bb.w, 0.f) };
        #pragma unroll
        for (int q = 0; q < 4; q++){
            __nv_bfloat16 h, l; split_bf16(r[q], h, l);
            d_x1h[(size_t)n*KP_GCN + c0 + q] = h;
            d_x1l[(size_t)n*KP_GCN + c0 + q] = l;
        }
    } else if (tid < 208){
        #pragma unroll
        for (int q = 0; q < 4; q++){
            d_x1h[(size_t)n*KP_GCN + c0 + q] = __float2bfloat16(0.f);
            d_x1l[(size_t)n*KP_GCN + c0 + q] = __float2bfloat16(0.f);
        }
    }
}

// chunked GCN aggregation: 64 edges staged per round
__global__ void k_gcn_agg(const float* __restrict__ gcn_b){
    int n = blockIdx.x;
    int tid = threadIdx.x;
    __shared__ int   csrc_c[64];
    __shared__ float coef_c[64];
    int s0 = d_roff[n], s1 = d_roff[n+1];
    float dn = d_dinv[n];
    float4 acc = make_float4(0.f,0.f,0.f,0.f);
    int c0 = tid*4;
    for (int base = s0; base < s1; base += 64){
        int cnt = s1 - base; if (cnt > 64) cnt = 64;
        if (tid < cnt){
            int s = d_csrc[base + tid];
            csrc_c[tid] = s;
            coef_c[tid] = dn * d_dinv[s];
        }
        __syncthreads();
        if (tid < 195){
            #pragma unroll 2
            for (int j = 0; j < cnt; j++){
                float4 v = *(const float4*)(d_h2 + (size_t)csrc_c[j]*HF + c0);
                float cf = coef_c[j];
                acc.x += cf*v.x; acc.y += cf*v.y; acc.z += cf*v.z; acc.w += cf*v.w;
            }
        }
        __syncthreads();
    }
    if (tid < 195){
        float4 bb = *(const float4*)(gcn_b + c0);
        float4 r = make_float4(fmaxf(acc.x + bb.x, 0.f), fmaxf(acc.y + bb.y, 0.f),
                               fmaxf(acc.z + bb.z, 0.f), fmaxf(acc.w + bb.w, 0.f));
        *(float4*)(d_x2 + (size_t)n*HF + c0) = r;
    }
}

// ================= pooling =================
__global__ void k_start(const int* __restrict__ batch){
    int g = blockIdx.x*blockDim.x + threadIdx.x;
    if (g > NG) return;
    if (g == NG){ d_start[NG] = NN; return; }
    int lo = 0, hi = NN;
    while (lo < hi){ int mid = (lo+hi) >> 1; if (batch[mid] < g) lo = mid+1; else hi = mid; }
    d_start[g] = lo;
}
__global__ void k_pool(){
    int g = blockIdx.x;
    int s = d_start[g], e = d_start[g+1];
    int cnt = e - s;
    for (int c = threadIdx.x; c < HF; c += blockDim.x){
        float mx = -1e30f, sm = 0.f;
        #pragma unroll 4
        for (int n = s; n < e; n++){
            float v = d_x2[(size_t)n*HF + c];
            mx = fmaxf(mx, v); sm += v;
        }
        d_pool[g*2*HF + c]      = (cnt > 0) ? mx : 0.f;
        d_pool[g*2*HF + HF + c] = sm / fmaxf((float)cnt, 1.f);
    }
}

// ================= small GEMM (f32x2 packed, bias/act) =================
__global__ void gemm2_kernel(const float* __restrict__ A, const float* __restrict__ B,
                             const float* __restrict__ bias, float* __restrict__ C,
                             int M, int N, int K, int ldc, int act)
{
    __shared__ float As[16*64];
    __shared__ float Bs[16*64];
    int tid = threadIdx.x;
    int row0 = blockIdx.y*64, col0 = blockIdx.x*64;
    int tx = tid & 15, ty = tid >> 4;
    unsigned long long acc2[4][2];
    #pragma unroll
    for (int i=0;i<4;i++){ acc2[i][0] = 0ull; acc2[i][1] = 0ull; }
    for (int k0 = 0; k0 < K; k0 += 16){
        #pragma unroll
        for (int i=0;i<4;i++){
            int l = tid + i*256;
            int m = l >> 4, kk = l & 15;
            int r = row0 + m, kg = k0 + kk;
            As[kk*64+m] = (r < M && kg < K) ? A[(size_t)r*K + kg] : 0.f;
        }
        #pragma unroll
        for (int i=0;i<4;i++){
            int l = tid + i*256;
            int kk = l >> 6, n = l & 63;
            int kg = k0 + kk, c = col0 + n;
            Bs[kk*64+n] = (kg < K && c < N) ? B[(size_t)kg*N + c] : 0.f;
        }
        __syncthreads();
        #pragma unroll
        for (int kk=0; kk<16; kk++){
            float ra[4];
            #pragma unroll
            for (int i=0;i<4;i++) ra[i] = As[kk*64 + ty*4 + i];
            unsigned long long rb0 = *(const unsigned long long*)&Bs[kk*64 + tx*4];
            unsigned long long rb1 = *(const unsigned long long*)&Bs[kk*64 + tx*4 + 2];
            #pragma unroll
            for (int i=0;i<4;i++){
                unsigned long long ad;
                asm("mov.b64 %0, {%1, %1};" : "=l"(ad) : "r"(__float_as_uint(ra[i])));
                asm("fma.rn.f32x2 %0, %1, %2, %0;" : "+l"(acc2[i][0]) : "l"(ad), "l"(rb0));
                asm("fma.rn.f32x2 %0, %1, %2, %0;" : "+l"(acc2[i][1]) : "l"(ad), "l"(rb1));
            }
        }
        __syncthreads();
    }
    #pragma unroll
    for (int i=0;i<4;i++){
        int r = row0 + ty*4 + i;
        if (r >= M) continue;
        #pragma unroll
        for (int jp=0;jp<2;jp++){
            unsigned int lo, hi;
            asm("mov.b64 {%0, %1}, %2;" : "=r"(lo), "=r"(hi) : "l"(acc2[i][jp]));
            float v0 = __uint_as_float(lo), v1 = __uint_as_float(hi);
            int c = col0 + tx*4 + jp*2;
            if (c < N){
                float v = v0;
                if (bias) v += bias[c];
                if (act)  v = fmaxf(v, 0.f);
                C[(size_t)r*ldc + c] = v;
            }
            if (c+1 < N){
                float v = v1;
                if (bias) v += bias[c+1];
                if (act)  v = fmaxf(v, 0.f);
                C[(size_t)r*ldc + c+1] = v;
            }
        }
    }
}

// ================= target branch =================
__global__ void k_buildM(const float* __restrict__ emb){
    int i = blockIdx.x*blockDim.x + threadIdx.x;
    if (i >= UCOLS*CONVOUT) return;
    int p = i % CONVOUT, vk = i / CONVOUT;
    int v = vk >> 3, k = vk & 7;
    d_Mm[i] = emb[v*EMB + p + k];
}
__global__ void k_transW(const float* __restrict__ W){
    int i = blockIdx.x*blockDim.x + threadIdx.x;
    if (i >= NFILT*SEQL*8) return;
    int o = i / (SEQL*8), c = (i >> 3) % SEQL, k = i & 7;
    d_Wt[c*(NFILT*8) + o*8 + k] = W[i];
}
__global__ void k_buildU(const int* __restrict__ target){
    __shared__ float sU[USZ];
    __shared__ int   st[SEQL];
    int g = blockIdx.x;
    for (int i = threadIdx.x; i < USZ;  i += blockDim.x) sU[i] = 0.f;
    for (int i = threadIdx.x; i < SEQL; i += blockDim.x) st[i] = target[g*SEQL + i];
    __syncthreads();
    int o = threadIdx.x >> 3, k = threadIdx.x & 7;
    for (int c = 0; c < SEQL; c++){
        int v = st[c];
        sU[o*UCOLS + v*8 + k] += d_Wt[c*(NFILT*8) + threadIdx.x];
    }
    __syncthreads();
    for (int i = threadIdx.x; i < USZ; i += blockDim.x)
        d_U[(size_t)g*USZ + i] = sU[i];
}
__global__ void k_fcxtb2(const float* __restrict__ fcxt_W,
                         const float* __restrict__ fcxt_b,
                         const float* __restrict__ conv_b){
    int j = blockIdx.x;
    __shared__ float red[128];
    float s = 0.f;
    for (int r = threadIdx.x; r < NFILT*CONVOUT; r += blockDim.x)
        s += conv_b[r / CONVOUT] * fcxt_W[(size_t)r*128 + j];
    red[threadIdx.x] = s; __syncthreads();
    for (int o = 64; o > 0; o >>= 1){
        if (threadIdx.x < o) red[threadIdx.x] += red[threadIdx.x + o];
        __syncthreads();
    }
    if (!threadIdx.x) d_fcxtb2[j] = fcxt_b[j] + red[0];
}

// ================= final projection =================
__global__ void k_out(const float* __restrict__ oW, const float* __restrict__ ob,
                      float* __restrict__ out){
    int g    = (blockIdx.x*blockDim.x + threadIdx.x) >> 5;
    int lane = threadIdx.x & 31;
    if (g >= NG) return;
    float s = 0.f;
    for (int k = lane; k < 512; k += 32) s += d_f2[g*512 + k] * oW[k];
    #pragma unroll
    for (int o = 16; o > 0; o >>= 1) s += __shfl_down_sync(~0u, s, o);
    if (!lane) out[g] = s + ob[0];
}

// ================= launch =================
static inline void gemm_launch(const float* A, const float* B, const float* bias,
                               float* C, int M, int N, int K, int ldc, int act){
    dim3 grid((N + 63)/64, (M + 63)/64);
    gemm2_kernel<<<grid, 256>>>(A, B, bias, C, M, N, K, ldc, act);
}

extern "C" void kernel_launch(void* const* d_in, const int* in_sizes, int n_in,
                              void* d_out, int out_size){
    const float* x        = (const float*)d_in[0];
    const int*   ei       = (const int*)  d_in[1];
    const int*   batch    = (const int*)  d_in[2];
    const int*   target   = (const int*)  d_in[3];
    const float* gat_W    = (const float*)d_in[4];
    const float* gat_asrc = (const float*)d_in[5];
    const float* gat_adst = (const float*)d_in[6];
    const float* gat_b    = (const float*)d_in[7];
    const float* gcn_W    = (const float*)d_in[8];
    const float* gcn_b    = (const float*)d_in[9];
    const float* fcg1_W   = (const float*)d_in[10];
    const float* fcg1_b   = (const float*)d_in[11];
    const float* fcg2_W   = (const float*)d_in[12];
    const float* fcg2_b   = (const float*)d_in[13];
    const float* emb      = (const float*)d_in[14];
    const float* conv_W   = (const float*)d_in[15];
    const float* conv_b   = (const float*)d_in[16];
    const float* fcxt_W   = (const float*)d_in[17];
    const float* fcxt_b   = (const float*)d_in[18];
    const float* fc1_W    = (const float*)d_in[19];
    const float* fc1_b    = (const float*)d_in[20];
    const float* fc2_W    = (const float*)d_in[21];
    const float* fc2_b    = (const float*)d_in[22];
    const float* out_W    = (const float*)d_in[23];
    const float* out_b    = (const float*)d_in[24];

    float *p_h, *p_h2, *p_x2, *p_pool, *p_xg1, *p_xc, *p_U, *p_Mm, *p_conv,
          *p_f1, *p_f2, *p_fcxtb2;
    __nv_bfloat16 *p_xh, *p_xl, *p_x1h, *p_x1l, *p_gWh, *p_gWl, *p_cWh, *p_cWl;
    cudaGetSymbolAddress((void**)&p_h,    d_h);
    cudaGetSymbolAddress((void**)&p_h2,   d_h2);
    cudaGetSymbolAddress((void**)&p_x2,   d_x2);
    cudaGetSymbolAddress((void**)&p_pool, d_pool);
    cudaGetSymbolAddress((void**)&p_xg1,  d_xg1);
    cudaGetSymbolAddress((void**)&p_xc,   d_xc);
    cudaGetSymbolAddress((void**)&p_U,    d_U);
    cudaGetSymbolAddress((void**)&p_Mm,   d_Mm);
    cudaGetSymbolAddress((void**)&p_conv, d_conv);
    cudaGetSymbolAddress((void**)&p_f1,   d_f1);
    cudaGetSymbolAddress((void**)&p_f2,   d_f2);
    cudaGetSymbolAddress((void**)&p_fcxtb2, d_fcxtb2);
    cudaGetSymbolAddress((void**)&p_xh,  d_xh);
    cudaGetSymbolAddress((void**)&p_xl,  d_xl);
    cudaGetSymbolAddress((void**)&p_x1h, d_x1h);
    cudaGetSymbolAddress((void**)&p_x1l, d_x1l);
    cudaGetSymbolAddress((void**)&p_gWh, d_gWh);
    cudaGetSymbolAddress((void**)&p_gWl, d_gWl);
    cudaGetSymbolAddress((void**)&p_cWh, d_cWh);
    cudaGetSymbolAddress((void**)&p_cWl, d_cWl);

    cudaFuncSetAttribute(gemm_mma, cudaFuncAttributeMaxDynamicSharedMemorySize, 2*STG);

    // ---- CSR build ----
    k_deg_init<<<(NN + 255)/256, 256>>>();
    k_count<<<(NE + 255)/256, 256>>>(ei);
    k_scan<<<1, 1024>>>();
    k_fill<<<(NEP + 255)/256, 256>>>(ei);
    k_dinv<<<(NN + 255)/256, 256>>>();

    // ---- split-bf16 prep ----
    k_split_x<<<(NN*KP_GAT + 255)/256, 256>>>(x);
    k_splitB<<<(NPAD*KP_GAT + 255)/256, 256>>>(gat_W, p_gWh, p_gWl, NF, HF, KP_GAT);
    k_splitB<<<(NPAD*KP_GCN + 255)/256, 256>>>(gcn_W, p_cWh, p_cWl, HF, HF, KP_GCN);

    // ---- GAT ----
    {
        dim3 grid(NPAD/128, (NN + 127)/128);
        gemm_mma<<<grid, 256, 2*STG>>>(p_xh, p_xl, p_gWh, p_gWl, p_h, NN, HF, KP_GAT, HF);
    }
    k_attn_coef<<<(NN*NH*32 + 255)/256, 256>>>(gat_asrc, gat_adst);
    k_gat_soft<<<(NN*32 + 255)/256, 256>>>();
    k_gat_agg<<<NN, 256>>>(gat_b);

    // ---- GCN ----
    {
        dim3 grid(NPAD/128, (NN + 127)/128);
        gemm_mma<<<grid, 256, 2*STG>>>(p_x1h, p_x1l, p_cWh, p_cWl, p_h2, NN, HF, KP_GCN, HF);
    }
    k_gcn_agg<<<NN, 256>>>(gcn_b);

    // ---- pooling + graph head ----
    k_start<<<3, 256>>>(batch);
    k_pool<<<NG, 256>>>();
    gemm_launch(p_pool, fcg1_W, fcg1_b, p_xg1, NG, 1024, 2*HF, 1024, 1);
    gemm_launch(p_xg1, fcg2_W, fcg2_b, p_xc, NG, 128, 1024, 256, 0);

    // ---- target branch ----
    k_buildM<<<(UCOLS*CONVOUT + 255)/256, 256>>>(emb);
    k_transW<<<(NFILT*SEQL*8 + 255)/256, 256>>>(conv_W);
    k_buildU<<<NG, 256>>>(target);
    gemm_launch(p_U, p_Mm, nullptr, p_conv, NG*NFILT, CONVOUT, UCOLS, CONVOUT, 0);
    k_fcxtb2<<<128, 128>>>(fcxt_W, fcxt_b, conv_b);
    gemm_launch(p_conv, fcxt_W, p_fcxtb2, p_xc + 128, NG, 128, NFILT*CONVOUT, 256, 0);

    // ---- fusion head ----
    gemm_launch(p_xc, fc1_W, fc1_b, p_f1, NG, 1024, 256, 1024, 1);
    gemm_launch(p_f1, fc2_W, fc2_b, p_f2, NG, 512, 1024, 512, 1);
    k_out<<<(NG*32 + 255)/256, 256>>>(out_W, out_b, (float*)d_out);
}

// round 6
// speedup vs baseline: 2.8490x; 1.2471x over previous
#include <cuda_runtime.h>
#include <cuda_bf16.h>
#include <math.h>
#include <stdint.h>

#define NN      25000
#define NE      100000
#define NEP     125000
#define NG      512
#define NH      10
#define NF      78
#define HF      780
#define SEQL    1000
#define EMB     128
#define NFILT   32
#define CONVOUT 121
#define VOCAB   26
#define UCOLS   (VOCAB*8)        // 208
#define USZ     (NFILT*UCOLS)

#define KP_GAT  128
#define KP_GCN  832
#define NPADG   896              // padded N for gat/gcn weights
#define KP_POOL 1568             // padded K for fcg1 (2*780 -> 1568)
#define NP_FCG1 1024
#define KP_U    224              // padded K for conv gemm (208 -> 224)

// ---------------- device scratch ----------------
__device__ float d_h[NN*HF];
__device__ float d_asrc[NN*NH];
__device__ float d_adst[NN*NH];
__device__ float d_invden[NN*NH];
__device__ float d_alpha[(size_t)NEP*NH];
__device__ float d_h2[NN*HF];
__device__ float d_x2[NN*HF];
__device__ float d_dinv[NN];
__device__ int   d_deg[NN];
__device__ int   d_roff[NN+1];
__device__ int   d_rpos[NN];
__device__ int   d_csrc[NEP];
__device__ int   d_start[NG+1];
__device__ float d_xg1[NG*1024];
__device__ float d_Wt[SEQL*NFILT*8];
__device__ float d_conv[(size_t)NG*NFILT*CONVOUT];
__device__ float d_fcxtb2[128];
__device__ float d_xc[NG*256];
__device__ float d_f1[NG*1024];
__device__ float d_f2[NG*512];
__device__ __nv_bfloat16 d_xh[(size_t)NN*KP_GAT];
__device__ __nv_bfloat16 d_xl[(size_t)NN*KP_GAT];
__device__ __nv_bfloat16 d_x1h[(size_t)NN*KP_GCN];
__device__ __nv_bfloat16 d_x1l[(size_t)NN*KP_GCN];
__device__ __nv_bfloat16 d_gWh[(size_t)NPADG*KP_GAT];
__device__ __nv_bfloat16 d_gWl[(size_t)NPADG*KP_GAT];
__device__ __nv_bfloat16 d_cWh[(size_t)NPADG*KP_GCN];
__device__ __nv_bfloat16 d_cWl[(size_t)NPADG*KP_GCN];
__device__ __nv_bfloat16 d_poolh[(size_t)NG*KP_POOL];
__device__ __nv_bfloat16 d_pooll[(size_t)NG*KP_POOL];
__device__ __nv_bfloat16 d_fWh[(size_t)NP_FCG1*KP_POOL];
__device__ __nv_bfloat16 d_fWl[(size_t)NP_FCG1*KP_POOL];
__device__ __nv_bfloat16 d_Uh[(size_t)NG*NFILT*KP_U];
__device__ __nv_bfloat16 d_Ul[(size_t)NG*NFILT*KP_U];
__device__ __nv_bfloat16 d_Mmh[128*KP_U];
__device__ __nv_bfloat16 d_Mml[128*KP_U];

// ================= helpers =================
__device__ __forceinline__ uint32_t smem_u32(const void* p){
    uint32_t a;
    asm("{ .reg .u64 t; cvta.to.shared.u64 t, %1; cvt.u32.u64 %0, t; }" : "=r"(a) : "l"(p));
    return a;
}
#define LDMX4(r, a) \
    asm volatile("ldmatrix.sync.aligned.m8n8.x4.shared.b16 {%0,%1,%2,%3}, [%4];" \
        : "=r"((r)[0]), "=r"((r)[1]), "=r"((r)[2]), "=r"((r)[3]) : "r"(a))
#define MMA16816(d, a, b0, b1) \
    asm volatile("mma.sync.aligned.m16n8k16.row.col.f32.bf16.bf16.f32 " \
        "{%0,%1,%2,%3}, {%4,%5,%6,%7}, {%8,%9}, {%0,%1,%2,%3};" \
        : "+f"((d)[0]), "+f"((d)[1]), "+f"((d)[2]), "+f"((d)[3]) \
        : "r"((a)[0]), "r"((a)[1]), "r"((a)[2]), "r"((a)[3]), "r"(b0), "r"(b1))
#define CPA_COMMIT() asm volatile("cp.async.commit_group;" ::: "memory")
#define CPA_WAIT0()  asm volatile("cp.async.wait_group 0;" ::: "memory")

__device__ __forceinline__ void cpa16(uint32_t dst, const void* src, int sz){
    size_t g;
    asm("cvta.to.global.u64 %0, %1;" : "=l"(g) : "l"(src));
    asm volatile("cp.async.cg.shared.global [%0], [%1], 16, %2;" :: "r"(dst), "l"(g), "r"(sz) : "memory");
}
__device__ __forceinline__ void split_bf16(float v, __nv_bfloat16& h, __nv_bfloat16& l){
    h = __float2bfloat16(v);
    l = __float2bfloat16(v - __bfloat162float(h));
}

// ================= mma.sync split-bf16 GEMM, cp.async double-buffered =================
#define GPITCH 40
#define TILEB  10240
#define STG    40960

__device__ __forceinline__ void ld_tile(uint32_t sdst, const __nv_bfloat16* G,
                                        int row0, int k0, int KP, int rlim, int tid){
    #pragma unroll
    for (int i = 0; i < 2; i++){
        int v = tid + i*256;
        int r = v >> 2, cq = v & 3;
        int row = row0 + r;
        int sz = (row < rlim) ? 16 : 0;
        const void* src = G + (size_t)(sz ? row : row0)*KP + k0 + cq*8;
        cpa16(sdst + r*80 + cq*16, src, sz);
    }
}

__global__ void __launch_bounds__(256, 2) gemm_mma(
    const __nv_bfloat16* __restrict__ Ah, const __nv_bfloat16* __restrict__ Al,
    const __nv_bfloat16* __restrict__ Bh, const __nv_bfloat16* __restrict__ Bl,
    float* __restrict__ C, int M, int Nout, int KP, int ldc,
    const float* __restrict__ bias, int act)
{
    extern __shared__ char sm[];
    uint32_t sb = smem_u32(sm);
    int tid = threadIdx.x;
    int m0 = blockIdx.y*128, n0 = blockIdx.x*128;
    int w = tid >> 5, lane = tid & 31;
    int wm = (w & 3) * 32;
    int wn = (w >> 2) * 64;
    int NC = KP / 32;

    float acc[2][8][4];
    #pragma unroll
    for (int i=0;i<2;i++)
        #pragma unroll
        for (int j=0;j<8;j++)
            #pragma unroll
            for (int q=0;q<4;q++) acc[i][j][q] = 0.f;

    int a_row = (lane & 15);
    int a_kc  = (lane >> 4) * 8;
    int b_row = ((lane >> 4) * 8) + (lane & 7);
    int b_kc  = ((lane >> 3) & 1) * 8;

    ld_tile(sb + 0*TILEB, Ah, m0, 0, KP, M, tid);
    ld_tile(sb + 1*TILEB, Al, m0, 0, KP, M, tid);
    ld_tile(sb + 2*TILEB, Bh, n0, 0, KP, 1<<30, tid);
    ld_tile(sb + 3*TILEB, Bl, n0, 0, KP, 1<<30, tid);
    CPA_COMMIT();

    for (int ci = 0; ci < NC; ci++){
        int b = ci & 1;
        uint32_t st = sb + b*STG;
        CPA_WAIT0();
        __syncthreads();
        if (ci + 1 < NC){
            uint32_t s2 = sb + (1-b)*STG;
            int k0n = (ci+1)*32;
            ld_tile(s2 + 0*TILEB, Ah, m0, k0n, KP, M, tid);
            ld_tile(s2 + 1*TILEB, Al, m0, k0n, KP, M, tid);
            ld_tile(s2 + 2*TILEB, Bh, n0, k0n, KP, 1<<30, tid);
            ld_tile(s2 + 3*TILEB, Bl, n0, k0n, KP, 1<<30, tid);
            CPA_COMMIT();
        }
        uint32_t bAh = st, bAl = st + TILEB, bBh = st + 2*TILEB, bBl = st + 3*TILEB;
        #pragma unroll
        for (int kk = 0; kk < 32; kk += 16){
            uint32_t ah[2][4], al[2][4];
            #pragma unroll
            for (int mt = 0; mt < 2; mt++){
                uint32_t off = (uint32_t)((wm + mt*16 + a_row)*GPITCH + kk + a_kc) * 2;
                LDMX4(ah[mt], bAh + off);
                LDMX4(al[mt], bAl + off);
            }
            #pragma unroll
            for (int nt2 = 0; nt2 < 4; nt2++){
                uint32_t offb = (uint32_t)((wn + nt2*16 + b_row)*GPITCH + kk + b_kc) * 2;
                uint32_t bh[4], bl[4];
                LDMX4(bh, bBh + offb);
                LDMX4(bl, bBl + offb);
                #pragma unroll
                for (int mt = 0; mt < 2; mt++){
                    MMA16816(acc[mt][nt2*2],   ah[mt], bh[0], bh[1]);
                    MMA16816(acc[mt][nt2*2],   ah[mt], bl[0], bl[1]);
                    MMA16816(acc[mt][nt2*2],   al[mt], bh[0], bh[1]);
                    MMA16816(acc[mt][nt2*2+1], ah[mt], bh[2], bh[3]);
                    MMA16816(acc[mt][nt2*2+1], ah[mt], bl[2], bl[3]);
                    MMA16816(acc[mt][nt2*2+1], al[mt], bh[2], bh[3]);
                }
            }
        }
    }
    #pragma unroll
    for (int mt = 0; mt < 2; mt++){
        int r0 = m0 + wm + mt*16 + (lane >> 2);
        #pragma unroll
        for (int nt = 0; nt < 8; nt++){
            int c = n0 + wn + nt*8 + (lane & 3)*2;
            #pragma unroll
            for (int half = 0; half < 2; half++){
                int rr = r0 + half*8;
                if (rr >= M) continue;
                #pragma unroll
                for (int q = 0; q < 2; q++){
                    int cc = c + q;
                    if (cc >= Nout) continue;
                    float v = acc[mt][nt][half*2 + q];
                    if (bias) v += bias[cc];
                    if (act)  v = fmaxf(v, 0.f);
                    C[(size_t)rr*ldc + cc] = v;
                }
            }
        }
    }
}

// ================= split-prep =================
__global__ void k_split_x(const float* __restrict__ x){
    int i = blockIdx.x*blockDim.x + threadIdx.x;
    if (i >= NN*KP_GAT) return;
    int r = i >> 7, k = i & (KP_GAT-1);
    float v = (k < NF) ? x[r*NF + k] : 0.f;
    split_bf16(v, d_xh[i], d_xl[i]);
}
// W[K x N] -> [NR rows x KP] K-major split
__global__ void k_splitB(const float* __restrict__ W, __nv_bfloat16* __restrict__ bh,
                         __nv_bfloat16* __restrict__ bl, int K, int N, int KP, int NR){
    int i = blockIdx.x*blockDim.x + threadIdx.x;
    if (i >= NR*KP) return;
    int n = i / KP, k = i - n*KP;
    float v = (k < K && n < N) ? W[(size_t)k*N + n] : 0.f;
    __nv_bfloat16 h, l; split_bf16(v, h, l);
    bh[i] = h; bl[i] = l;
}

// ================= CSR build =================
__global__ void k_deg_init(){
    int n = blockIdx.x*blockDim.x + threadIdx.x;
    if (n < NN) d_deg[n] = 1;
}
__global__ void k_count(const int* __restrict__ ei){
    int e = blockIdx.x*blockDim.x + threadIdx.x;
    if (e < NE) atomicAdd(&d_deg[ei[NE+e]], 1);
}
__global__ void k_scan(){
    __shared__ int part[1024];
    int t = threadIdx.x;
    const int PER = 25;
    int base = t*PER, sum = 0;
    for (int i = 0; i < PER; i++){ int idx = base+i; if (idx < NN) sum += d_deg[idx]; }
    part[t] = sum; __syncthreads();
    for (int off = 1; off < 1024; off <<= 1){
        int v = (t >= off) ? part[t-off] : 0; __syncthreads();
        part[t] += v; __syncthreads();
    }
    int run = part[t] - sum;
    for (int i = 0; i < PER; i++){
        int idx = base+i;
        if (idx < NN){ d_roff[idx] = run; d_rpos[idx] = run; run += d_deg[idx]; }
    }
    if (t == 1023) d_roff[NN] = NEP;
}
__global__ void k_fill(const int* __restrict__ ei){
    int e = blockIdx.x*blockDim.x + threadIdx.x;
    if (e >= NEP) return;
    int s, d;
    if (e < NE){ s = ei[e]; d = ei[NE+e]; } else { s = d = e - NE; }
    int pos = atomicAdd(&d_rpos[d], 1);
    d_csrc[pos] = s;
}
__global__ void k_dinv(){
    int n = blockIdx.x*blockDim.x + threadIdx.x;
    if (n < NN) d_dinv[n] = rsqrtf((float)d_deg[n]);
}

// ================= GAT =================
__global__ void k_attn_coef(const float* __restrict__ att_src,
                            const float* __restrict__ att_dst){
    int wid  = (blockIdx.x*blockDim.x + threadIdx.x) >> 5;
    int lane = threadIdx.x & 31;
    if (wid >= NN*NH) return;
    int n = wid / NH, hh = wid % NH;
    const float* hp = d_h + (size_t)n*HF + hh*NF;
    float s1 = 0.f, s2 = 0.f;
    for (int f = lane; f < NF; f += 32){
        float v = hp[f];
        s1 += v * att_src[hh*NF + f];
        s2 += v * att_dst[hh*NF + f];
    }
    #pragma unroll
    for (int o=16;o>0;o>>=1){ s1 += __shfl_down_sync(~0u,s1,o); s2 += __shfl_down_sync(~0u,s2,o); }
    if (!lane){ d_asrc[wid] = s1; d_adst[wid] = s2; }
}
__global__ void k_gat_soft(){
    int w    = (blockIdx.x*blockDim.x + threadIdx.x) >> 5;
    int lane = threadIdx.x & 31;
    if (w >= NN || lane >= NH) return;
    int s0 = d_roff[w], s1 = d_roff[w+1];
    float ad = d_adst[w*NH + lane];
    float mx = -1e30f;
    for (int p = s0; p < s1; p++){
        float a = d_asrc[d_csrc[p]*NH + lane] + ad;
        a = a > 0.f ? a : 0.2f*a;
        mx = fmaxf(mx, a);
    }
    float sum = 0.f;
    for (int p = s0; p < s1; p++){
        float a = d_asrc[d_csrc[p]*NH + lane] + ad;
        a = a > 0.f ? a : 0.2f*a;
        float e = expf(a - mx);
        d_alpha[(size_t)p*NH + lane] = e;
        sum += e;
    }
    d_invden[w*NH + lane] = 1.f / (sum + 1e-16f);
}
__global__ void k_gat_agg(const float* __restrict__ gat_b){
    int n = blockIdx.x;
    int tid = threadIdx.x;
    __shared__ float invd[NH];
    __shared__ int   csrc_c[25];
    __shared__ float coef_c[25][NH];
    if (tid < NH) invd[tid] = d_invden[n*NH + tid];
    __syncthreads();
    int s0 = d_roff[n], s1 = d_roff[n+1];
    float4 acc = make_float4(0.f,0.f,0.f,0.f);
    int c0 = tid*4;
    int h0 = c0/NF, h1 = (c0+1)/NF, h2 = (c0+2)/NF, h3 = (c0+3)/NF;
    for (int base = s0; base < s1; base += 25){
        int cnt = s1 - base; if (cnt > 25) cnt = 25;
        if (tid < cnt) csrc_c[tid] = d_csrc[base + tid];
        if (tid < cnt*NH){
            int p = tid / NH, hh = tid - p*NH;
            coef_c[p][hh] = d_alpha[(size_t)(base+p)*NH + hh] * invd[hh];
        }
        __syncthreads();
        if (tid < 195){
            #pragma unroll 2
            for (int j = 0; j < cnt; j++){
                float4 v = *(const float4*)(d_h + (size_t)csrc_c[j]*HF + c0);
                acc.x += coef_c[j][h0]*v.x;
                acc.y += coef_c[j][h1]*v.y;
                acc.z += coef_c[j][h2]*v.z;
                acc.w += coef_c[j][h3]*v.w;
            }
        }
        __syncthreads();
    }
    if (tid < 195){
        float4 bb = *(const float4*)(gat_b + c0);
        float r[4] = { fmaxf(acc.x + bb.x, 0.f), fmaxf(acc.y + bb.y, 0.f),
                       fmaxf(acc.z + bb.z, 0.f), fmaxf(acc.w + bb.w, 0.f) };
        #pragma unroll
        for (int q = 0; q < 4; q++){
            __nv_bfloat16 h, l; split_bf16(r[q], h, l);
            d_x1h[(size_t)n*KP_GCN + c0 + q] = h;
            d_x1l[(size_t)n*KP_GCN + c0 + q] = l;
        }
    } else if (tid < 208){
        #pragma unroll
        for (int q = 0; q < 4; q++){
            d_x1h[(size_t)n*KP_GCN + c0 + q] = __float2bfloat16(0.f);
            d_x1l[(size_t)n*KP_GCN + c0 + q] = __float2bfloat16(0.f);
        }
    }
}

// ================= GCN aggregate =================
__global__ void k_gcn_agg(const float* __restrict__ gcn_b){
    int n = blockIdx.x;
    int tid = threadIdx.x;
    __shared__ int   csrc_c[64];
    __shared__ float coef_c[64];
    int s0 = d_roff[n], s1 = d_roff[n+1];
    float dn = d_dinv[n];
    float4 acc = make_float4(0.f,0.f,0.f,0.f);
    int c0 = tid*4;
    for (int base = s0; base < s1; base += 64){
        int cnt = s1 - base; if (cnt > 64) cnt = 64;
        if (tid < cnt){
            int s = d_csrc[base + tid];
            csrc_c[tid] = s;
            coef_c[tid] = dn * d_dinv[s];
        }
        __syncthreads();
        if (tid < 195){
            #pragma unroll 2
            for (int j = 0; j < cnt; j++){
                float4 v = *(const float4*)(d_h2 + (size_t)csrc_c[j]*HF + c0);
                float cf = coef_c[j];
                acc.x += cf*v.x; acc.y += cf*v.y; acc.z += cf*v.z; acc.w += cf*v.w;
            }
        }
        __syncthreads();
    }
    if (tid < 195){
        float4 bb = *(const float4*)(gcn_b + c0);
        float4 r = make_float4(fmaxf(acc.x + bb.x, 0.f), fmaxf(acc.y + bb.y, 0.f),
                               fmaxf(acc.z + bb.z, 0.f), fmaxf(acc.w + bb.w, 0.f));
        *(float4*)(d_x2 + (size_t)n*HF + c0) = r;
    }
}

// ================= pooling (emits split-bf16 for fcg1) =================
__global__ void k_start(const int* __restrict__ batch){
    int g = blockIdx.x*blockDim.x + threadIdx.x;
    if (g > NG) return;
    if (g == NG){ d_start[NG] = NN; return; }
    int lo = 0, hi = NN;
    while (lo < hi){ int mid = (lo+hi) >> 1; if (batch[mid] < g) lo = mid+1; else hi = mid; }
    d_start[g] = lo;
}
__global__ void k_pool(){
    int g = blockIdx.x;
    int s = d_start[g], e = d_start[g+1];
    int cnt = e - s;
    size_t rb = (size_t)g*KP_POOL;
    for (int c = threadIdx.x; c < HF; c += blockDim.x){
        float mx = -1e30f, sm = 0.f;
        #pragma unroll 4
        for (int n = s; n < e; n++){
            float v = d_x2[(size_t)n*HF + c];
            mx = fmaxf(mx, v); sm += v;
        }
        float vmax = (cnt > 0) ? mx : 0.f;
        float vmean = sm / fmaxf((float)cnt, 1.f);
        __nv_bfloat16 h, l;
        split_bf16(vmax, h, l);  d_poolh[rb + c] = h;      d_pooll[rb + c] = l;
        split_bf16(vmean, h, l); d_poolh[rb + HF + c] = h; d_pooll[rb + HF + c] = l;
    }
    if (threadIdx.x < 8){
        d_poolh[rb + 2*HF + threadIdx.x] = __float2bfloat16(0.f);
        d_pooll[rb + 2*HF + threadIdx.x] = __float2bfloat16(0.f);
    }
}

// ================= small GEMM (f32x2, split-K capable) =================
__global__ void gemm2_kernel(const float* __restrict__ A, const float* __restrict__ B,
                             const float* __restrict__ bias, float* __restrict__ C,
                             int M, int N, int K, int ldc, int act)
{
    __shared__ float As[16*64];
    __shared__ float Bs[16*64];
    int tid = threadIdx.x;
    int row0 = blockIdx.y*64, col0 = blockIdx.x*64;
    int tx = tid & 15, ty = tid >> 4;
    int Z = gridDim.z, z = blockIdx.z;
    int T = (K + 15) / 16;
    int kc0 = (int)((long long)T * z / Z), kc1 = (int)((long long)T * (z+1) / Z);
    unsigned long long acc2[4][2];
    #pragma unroll
    for (int i=0;i<4;i++){ acc2[i][0] = 0ull; acc2[i][1] = 0ull; }
    for (int kc = kc0; kc < kc1; kc++){
        int k0 = kc*16;
        #pragma unroll
        for (int i=0;i<4;i++){
            int l = tid + i*256;
            int m = l >> 4, kk = l & 15;
            int r = row0 + m, kg = k0 + kk;
            As[kk*64+m] = (r < M && kg < K) ? A[(size_t)r*K + kg] : 0.f;
        }
        #pragma unroll
        for (int i=0;i<4;i++){
            int l = tid + i*256;
            int kk = l >> 6, n = l & 63;
            int kg = k0 + kk, c = col0 + n;
            Bs[kk*64+n] = (kg < K && c < N) ? B[(size_t)kg*N + c] : 0.f;
        }
        __syncthreads();
        #pragma unroll
        for (int kk=0; kk<16; kk++){
            float ra[4];
            #pragma unroll
            for (int i=0;i<4;i++) ra[i] = As[kk*64 + ty*4 + i];
            unsigned long long rb0 = *(const unsigned long long*)&Bs[kk*64 + tx*4];
            unsigned long long rb1 = *(const unsigned long long*)&Bs[kk*64 + tx*4 + 2];
            #pragma unroll
            for (int i=0;i<4;i++){
                unsigned long long ad;
                asm("mov.b64 %0, {%1, %1};" : "=l"(ad) : "r"(__float_as_uint(ra[i])));
                asm("fma.rn.f32x2 %0, %1, %2, %0;" : "+l"(acc2[i][0]) : "l"(ad), "l"(rb0));
                asm("fma.rn.f32x2 %0, %1, %2, %0;" : "+l"(acc2[i][1]) : "l"(ad), "l"(rb1));
            }
        }
        __syncthreads();
    }
    #pragma unroll
    for (int i=0;i<4;i++){
        int r = row0 + ty*4 + i;
        if (r >= M) continue;
        #pragma unroll
        for (int jp=0;jp<2;jp++){
            unsigned int lo, hi;
            asm("mov.b64 {%0, %1}, %2;" : "=r"(lo), "=r"(hi) : "l"(acc2[i][jp]));
            float vv[2] = { __uint_as_float(lo), __uint_as_float(hi) };
            int c = col0 + tx*4 + jp*2;
            #pragma unroll
            for (int q=0;q<2;q++){
                int cc = c + q;
                if (cc >= N) continue;
                if (Z == 1){
                    float v = vv[q];
                    if (bias) v += bias[cc];
                    if (act)  v = fmaxf(v, 0.f);
                    C[(size_t)r*ldc + cc] = v;
                } else {
                    atomicAdd(&C[(size_t)r*ldc + cc], vv[q]);
                }
            }
        }
    }
}

__global__ void k_binit(float* __restrict__ C, const float* __restrict__ bias,
                        int M, int N, int ldc){
    int i = blockIdx.x*blockDim.x + threadIdx.x;
    if (i >= M*N) return;
    int r = i / N, c = i - r*N;
    C[(size_t)r*ldc + c] = bias[c];
}
__global__ void k_relu(float* __restrict__ C, int total){
    int i = blockIdx.x*blockDim.x + threadIdx.x;
    if (i < total) C[i] = fmaxf(C[i], 0.f);
}

// ================= target branch =================
__global__ void k_buildM(const float* __restrict__ emb){
    int i = blockIdx.x*blockDim.x + threadIdx.x;
    if (i >= 128*KP_U) return;
    int p = i / KP_U, kidx = i - p*KP_U;
    float val = 0.f;
    if (p < CONVOUT && kidx < UCOLS){
        int v = kidx >> 3, kk = kidx & 7;
        val = emb[v*EMB + p + kk];
    }
    __nv_bfloat16 h, l; split_bf16(val, h, l);
    d_Mmh[i] = h; d_Mml[i] = l;
}
__global__ void k_transW(const float* __restrict__ W){
    int i = blockIdx.x*blockDim.x + threadIdx.x;
    if (i >= NFILT*SEQL*8) return;
    int o = i / (SEQL*8), c = (i >> 3) % SEQL, k = i & 7;
    d_Wt[c*(NFILT*8) + o*8 + k] = W[i];
}
__global__ void k_buildU(const int* __restrict__ target){
    __shared__ float sU[USZ];
    __shared__ int   st[SEQL];
    int g = blockIdx.x;
    for (int i = threadIdx.x; i < USZ;  i += blockDim.x) sU[i] = 0.f;
    for (int i = threadIdx.x; i < SEQL; i += blockDim.x) st[i] = target[g*SEQL + i];
    __syncthreads();
    int o = threadIdx.x >> 3, k = threadIdx.x & 7;
    for (int c = 0; c < SEQL; c++){
        int v = st[c];
        sU[o*UCOLS + v*8 + k] += d_Wt[c*(NFILT*8) + threadIdx.x];
    }
    __syncthreads();
    for (int i = threadIdx.x; i < NFILT*KP_U; i += blockDim.x){
        int oo = i / KP_U, col = i - oo*KP_U;
        float v = (col < UCOLS) ? sU[oo*UCOLS + col] : 0.f;
        __nv_bfloat16 h, l; split_bf16(v, h, l);
        size_t idx = ((size_t)g*NFILT + oo)*KP_U + col;
        d_Uh[idx] = h; d_Ul[idx] = l;
    }
}
__global__ void k_fcxtb2(const float* __restrict__ fcxt_W,
                         const float* __restrict__ fcxt_b,
                         const float* __restrict__ conv_b){
    int j = blockIdx.x;
    __shared__ float red[128];
    float s = 0.f;
    for (int r = threadIdx.x; r < NFILT*CONVOUT; r += blockDim.x)
        s += conv_b[r / CONVOUT] * fcxt_W[(size_t)r*128 + j];
    red[threadIdx.x] = s; __syncthreads();
    for (int o = 64; o > 0; o >>= 1){
        if (threadIdx.x < o) red[threadIdx.x] += red[threadIdx.x + o];
        __syncthreads();
    }
    if (!threadIdx.x) d_fcxtb2[j] = fcxt_b[j] + red[0];
}

// ================= final projection =================
__global__ void k_out(const float* __restrict__ oW, const float* __restrict__ ob,
                      float* __restrict__ out){
    int g    = (blockIdx.x*blockDim.x + threadIdx.x) >> 5;
    int lane = threadIdx.x & 31;
    if (g >= NG) return;
    float s = 0.f;
    for (int k = lane; k < 512; k += 32) s += d_f2[g*512 + k] * oW[k];
    #pragma unroll
    for (int o = 16; o > 0; o >>= 1) s += __shfl_down_sync(~0u, s, o);
    if (!lane) out[g] = s + ob[0];
}

extern "C" void kernel_launch(void* const* d_in, const int* in_sizes, int n_in,
                              void* d_out, int out_size){
    const float* x        = (const float*)d_in[0];
    const int*   ei       = (const int*)  d_in[1];
    const int*   batch    = (const int*)  d_in[2];
    const int*   target   = (const int*)  d_in[3];
    const float* gat_W    = (const float*)d_in[4];
    const float* gat_asrc = (const float*)d_in[5];
    const float* gat_adst = (const float*)d_in[6];
    const float* gat_b    = (const float*)d_in[7];
    const float* gcn_W    = (const float*)d_in[8];
    const float* gcn_b    = (const float*)d_in[9];
    const float* fcg1_W   = (const float*)d_in[10];
    const float* fcg1_b   = (const float*)d_in[11];
    const float* fcg2_W   = (const float*)d_in[12];
    const float* fcg2_b   = (const float*)d_in[13];
    const float* emb      = (const float*)d_in[14];
    const float* conv_W   = (const float*)d_in[15];
    const float* conv_b   = (const float*)d_in[16];
    const float* fcxt_W   = (const float*)d_in[17];
    const float* fcxt_b   = (const float*)d_in[18];
    const float* fc1_W    = (const float*)d_in[19];
    const float* fc1_b    = (const float*)d_in[20];
    const float* fc2_W    = (const float*)d_in[21];
    const float* fc2_b    = (const float*)d_in[22];
    const float* out_W    = (const float*)d_in[23];
    const float* out_b    = (const float*)d_in[24];

    float *p_h, *p_h2, *p_xg1, *p_xc, *p_conv, *p_f1, *p_f2, *p_fcxtb2;
    __nv_bfloat16 *p_xh, *p_xl, *p_x1h, *p_x1l, *p_gWh, *p_gWl, *p_cWh, *p_cWl;
    __nv_bfloat16 *p_poolh, *p_pooll, *p_fWh, *p_fWl, *p_Uh, *p_Ul, *p_Mmh, *p_Mml;
    cudaGetSymbolAddress((void**)&p_h,    d_h);
    cudaGetSymbolAddress((void**)&p_h2,   d_h2);
    cudaGetSymbolAddress((void**)&p_xg1,  d_xg1);
    cudaGetSymbolAddress((void**)&p_xc,   d_xc);
    cudaGetSymbolAddress((void**)&p_conv, d_conv);
    cudaGetSymbolAddress((void**)&p_f1,   d_f1);
    cudaGetSymbolAddress((void**)&p_f2,   d_f2);
    cudaGetSymbolAddress((void**)&p_fcxtb2, d_fcxtb2);
    cudaGetSymbolAddress((void**)&p_xh,  d_xh);
    cudaGetSymbolAddress((void**)&p_xl,  d_xl);
    cudaGetSymbolAddress((void**)&p_x1h, d_x1h);
    cudaGetSymbolAddress((void**)&p_x1l, d_x1l);
    cudaGetSymbolAddress((void**)&p_gWh, d_gWh);
    cudaGetSymbolAddress((void**)&p_gWl, d_gWl);
    cudaGetSymbolAddress((void**)&p_cWh, d_cWh);
    cudaGetSymbolAddress((void**)&p_cWl, d_cWl);
    cudaGetSymbolAddress((void**)&p_poolh, d_poolh);
    cudaGetSymbolAddress((void**)&p_pooll, d_pooll);
    cudaGetSymbolAddress((void**)&p_fWh, d_fWh);
    cudaGetSymbolAddress((void**)&p_fWl, d_fWl);
    cudaGetSymbolAddress((void**)&p_Uh, d_Uh);
    cudaGetSymbolAddress((void**)&p_Ul, d_Ul);
    cudaGetSymbolAddress((void**)&p_Mmh, d_Mmh);
    cudaGetSymbolAddress((void**)&p_Mml, d_Mml);

    cudaFuncSetAttribute(gemm_mma, cudaFuncAttributeMaxDynamicSharedMemorySize, 2*STG);

    // launches 0..2: splits (so launch 3 = gemm_mma GAT lands under ncu -s 5)
    k_split_x<<<(NN*KP_GAT + 255)/256, 256>>>(x);
    k_splitB<<<(NPADG*KP_GAT + 255)/256, 256>>>(gat_W, p_gWh, p_gWl, NF, HF, KP_GAT, NPADG);
    k_splitB<<<(NPADG*KP_GCN + 255)/256, 256>>>(gcn_W, p_cWh, p_cWl, HF, HF, KP_GCN, NPADG);

    // launch 3: GAT transform (profiled)
    {
        dim3 grid(NPADG/128, (NN + 127)/128);
        gemm_mma<<<grid, 256, 2*STG>>>(p_xh, p_xl, p_gWh, p_gWl, p_h, NN, HF, KP_GAT, HF, nullptr, 0);
    }

    // CSR build
    k_deg_init<<<(NN + 255)/256, 256>>>();
    k_count<<<(NE + 255)/256, 256>>>(ei);
    k_scan<<<1, 1024>>>();
    k_fill<<<(NEP + 255)/256, 256>>>(ei);
    k_dinv<<<(NN + 255)/256, 256>>>();

    // remaining prep
    k_splitB<<<(NP_FCG1*KP_POOL + 255)/256, 256>>>(fcg1_W, p_fWh, p_fWl, 2*HF, 1024, KP_POOL, NP_FCG1);
    k_buildM<<<(128*KP_U + 255)/256, 256>>>(emb);
    k_transW<<<(NFILT*SEQL*8 + 255)/256, 256>>>(conv_W);

    // GAT attention + aggregation
    k_attn_coef<<<(NN*NH*32 + 255)/256, 256>>>(gat_asrc, gat_adst);
    k_gat_soft<<<(NN*32 + 255)/256, 256>>>();
    k_gat_agg<<<NN, 256>>>(gat_b);

    // GCN
    {
        dim3 grid(NPADG/128, (NN + 127)/128);
        gemm_mma<<<grid, 256, 2*STG>>>(p_x1h, p_x1l, p_cWh, p_cWl, p_h2, NN, HF, KP_GCN, HF, nullptr, 0);
    }
    k_gcn_agg<<<NN, 256>>>(gcn_b);

    // pooling + graph head
    k_start<<<3, 256>>>(batch);
    k_pool<<<NG, 256>>>();
    {   // fcg1 on tensor cores, fused bias+relu
        dim3 grid(1024/128, NG/128);
        gemm_mma<<<grid, 256, 2*STG>>>(p_poolh, p_pooll, p_fWh, p_fWl, p_xg1, NG, 1024, KP_POOL, 1024, fcg1_b, 1);
    }
    {   // fcg2 split-K
        k_binit<<<(NG*128 + 255)/256, 256>>>(p_xc, fcg2_b, NG, 128, 256);
        dim3 grid(2, 8, 4);
        gemm2_kernel<<<grid, 256>>>(p_xg1, fcg2_W, nullptr, p_xc, NG, 128, 1024, 256, 0);
    }

    // target branch
    k_buildU<<<NG, 256>>>(target);
    {   // conv GEMM on tensor cores
        dim3 grid(1, (NG*NFILT)/128);
        gemm_mma<<<grid, 256, 2*STG>>>(p_Uh, p_Ul, p_Mmh, p_Mml, p_conv, NG*NFILT, CONVOUT, KP_U, CONVOUT, nullptr, 0);
    }
    k_fcxtb2<<<128, 128>>>(fcxt_W, fcxt_b, conv_b);
    {   // fcxt split-K
        k_binit<<<(NG*128 + 255)/256, 256>>>(p_xc + 128, p_fcxtb2, NG, 128, 256);
        dim3 grid(2, 8, 4);
        gemm2_kernel<<<grid, 256>>>(p_conv, fcxt_W, nullptr, p_xc + 128, NG, 128, NFILT*CONVOUT, 256, 0);
    }

    // fusion head
    {
        dim3 grid(16, 8, 1);
        gemm2_kernel<<<grid, 256>>>(p_xc, fc1_W, fc1_b, p_f1, NG, 1024, 256, 1024, 1);
    }
    {
        k_binit<<<(NG*512 + 255)/256, 256>>>(p_f2, fc2_b, NG, 512, 512);
        dim3 grid(8, 8, 2);
        gemm2_kernel<<<grid, 256>>>(p_f1, fc2_W, nullptr, p_f2, NG, 512, 1024, 512, 0);
        k_relu<<<(NG*512 + 255)/256, 256>>>(p_f2, NG*512);
    }
    k_out<<<(NG*32 + 255)/256, 256>>>(out_W, out_b, (float*)d_out);
}

// round 7
// speedup vs baseline: 2.9173x; 1.0240x over previous
#include <cuda_runtime.h>
#include <cuda_bf16.h>
#include <math.h>
#include <stdint.h>

#define NN      25000
#define NE      100000
#define NEP     125000
#define NG      512
#define NH      10
#define NF      78
#define HF      780
#define SEQL    1000
#define EMB     128
#define NFILT   32
#define CONVOUT 121
#define VOCAB   26
#define UCOLS   (VOCAB*8)        // 208
#define USZ     (NFILT*UCOLS)

#define KP_GAT  128
#define KP_GCN  832
#define NPADG   832              // padded N for gat/gcn weights (13 x 64)
#define KP_POOL 1568
#define NP_FCG1 1024
#define KP_U    224

// ---------------- device scratch ----------------
__device__ float d_h[NN*HF];
__device__ float d_asrc[NN*NH];
__device__ float d_adst[NN*NH];
__device__ float d_invden[NN*NH];
__device__ float d_alpha[(size_t)NEP*NH];
__device__ float d_h2[NN*HF];
__device__ float d_x2[NN*HF];
__device__ float d_dinv[NN];
__device__ int   d_deg[NN];
__device__ int   d_roff[NN+1];
__device__ int   d_rpos[NN];
__device__ int   d_csrc[NEP];
__device__ int   d_start[NG+1];
__device__ float d_xg1[NG*1024];
__device__ float d_Wt[SEQL*NFILT*8];
__device__ float d_conv[(size_t)NG*NFILT*CONVOUT];
__device__ float d_fcxtb2[128];
__device__ float d_xc[NG*256];
__device__ float d_f1[NG*1024];
__device__ float d_f2[NG*512];
__device__ __nv_bfloat16 d_xh[(size_t)NN*KP_GAT];
__device__ __nv_bfloat16 d_xl[(size_t)NN*KP_GAT];
__device__ __nv_bfloat16 d_x1h[(size_t)NN*KP_GCN];
__device__ __nv_bfloat16 d_x1l[(size_t)NN*KP_GCN];
__device__ __nv_bfloat16 d_gWh[(size_t)NPADG*KP_GAT];
__device__ __nv_bfloat16 d_gWl[(size_t)NPADG*KP_GAT];
__device__ __nv_bfloat16 d_cWh[(size_t)NPADG*KP_GCN];
__device__ __nv_bfloat16 d_cWl[(size_t)NPADG*KP_GCN];
__device__ __nv_bfloat16 d_poolh[(size_t)NG*KP_POOL];
__device__ __nv_bfloat16 d_pooll[(size_t)NG*KP_POOL];
__device__ __nv_bfloat16 d_fWh[(size_t)NP_FCG1*KP_POOL];
__device__ __nv_bfloat16 d_fWl[(size_t)NP_FCG1*KP_POOL];
__device__ __nv_bfloat16 d_Uh[(size_t)NG*NFILT*KP_U];
__device__ __nv_bfloat16 d_Ul[(size_t)NG*NFILT*KP_U];
__device__ __nv_bfloat16 d_Mmh[128*KP_U];
__device__ __nv_bfloat16 d_Mml[128*KP_U];

// ================= helpers =================
__device__ __forceinline__ uint32_t smem_u32(const void* p){
    uint32_t a;
    asm("{ .reg .u64 t; cvta.to.shared.u64 t, %1; cvt.u32.u64 %0, t; }" : "=r"(a) : "l"(p));
    return a;
}
#define LDMX4(r, a) \
    asm volatile("ldmatrix.sync.aligned.m8n8.x4.shared.b16 {%0,%1,%2,%3}, [%4];" \
        : "=r"((r)[0]), "=r"((r)[1]), "=r"((r)[2]), "=r"((r)[3]) : "r"(a))
#define MMA16816(d, a, b0, b1) \
    asm volatile("mma.sync.aligned.m16n8k16.row.col.f32.bf16.bf16.f32 " \
        "{%0,%1,%2,%3}, {%4,%5,%6,%7}, {%8,%9}, {%0,%1,%2,%3};" \
        : "+f"((d)[0]), "+f"((d)[1]), "+f"((d)[2]), "+f"((d)[3]) \
        : "r"((a)[0]), "r"((a)[1]), "r"((a)[2]), "r"((a)[3]), "r"(b0), "r"(b1))
#define CPA_COMMIT() asm volatile("cp.async.commit_group;" ::: "memory")
#define CPA_WAIT0()  asm volatile("cp.async.wait_group 0;" ::: "memory")

__device__ __forceinline__ void cpa16(uint32_t dst, const void* src, int sz){
    size_t g;
    asm("cvta.to.global.u64 %0, %1;" : "=l"(g) : "l"(src));
    asm volatile("cp.async.cg.shared.global [%0], [%1], 16, %2;" :: "r"(dst), "l"(g), "r"(sz) : "memory");
}
__device__ __forceinline__ void split_bf16(float v, __nv_bfloat16& h, __nv_bfloat16& l){
    h = __float2bfloat16(v);
    l = __float2bfloat16(v - __bfloat162float(h));
}

// ================= mma.sync split-bf16 GEMM =================
// CTA tile 128(M) x 64(N), K chunk 32, 8 warps of 32x32, 2-stage cp.async.
#define GPITCH 40
#define ATILEB 10240     // 128 * 40 * 2
#define BTILEB 5120      // 64 * 40 * 2
#define STG    30720     // AH + AL + BH + BL

__device__ __forceinline__ void ld_tileA(uint32_t sdst, const __nv_bfloat16* G,
                                         int row0, int k0, int KP, int rlim, int tid){
    #pragma unroll
    for (int i = 0; i < 2; i++){
        int v = tid + i*256;
        int r = v >> 2, cq = v & 3;
        int row = row0 + r;
        int sz = (row < rlim) ? 16 : 0;
        cpa16(sdst + r*80 + cq*16, G + (size_t)(sz ? row : row0)*KP + k0 + cq*8, sz);
    }
}
__device__ __forceinline__ void ld_tileB(uint32_t sdst, const __nv_bfloat16* G,
                                         int row0, int k0, int KP, int rlim, int tid){
    if (tid < 256){
        int r = tid >> 2, cq = tid & 3;
        int row = row0 + r;
        int sz = (row < rlim) ? 16 : 0;
        cpa16(sdst + r*80 + cq*16, G + (size_t)(sz ? row : row0)*KP + k0 + cq*8, sz);
    }
}

__global__ void __launch_bounds__(256, 3) gemm_mma(
    const __nv_bfloat16* __restrict__ Ah, const __nv_bfloat16* __restrict__ Al,
    const __nv_bfloat16* __restrict__ Bh, const __nv_bfloat16* __restrict__ Bl,
    float* __restrict__ C, int M, int Nout, int KP, int ldc,
    const float* __restrict__ bias, int act, int Brows)
{
    extern __shared__ char sm[];
    uint32_t sb = smem_u32(sm);
    int tid = threadIdx.x;
    int m0 = blockIdx.y*128, n0 = blockIdx.x*64;
    int w = tid >> 5, lane = tid & 31;
    int wm = (w >> 1) * 32;
    int wn = (w & 1) * 32;
    int NC = KP / 32;

    float acc[2][4][4];
    #pragma unroll
    for (int i=0;i<2;i++)
        #pragma unroll
        for (int j=0;j<4;j++)
            #pragma unroll
            for (int q=0;q<4;q++) acc[i][j][q] = 0.f;

    int a_row = (lane & 15);
    int a_kc  = (lane >> 4) * 8;
    int b_row = ((lane >> 4) * 8) + (lane & 7);
    int b_kc  = ((lane >> 3) & 1) * 8;

    ld_tileA(sb + 0,            Ah, m0, 0, KP, M, tid);
    ld_tileA(sb + ATILEB,       Al, m0, 0, KP, M, tid);
    ld_tileB(sb + 2*ATILEB,          Bh, n0, 0, KP, Brows, tid);
    ld_tileB(sb + 2*ATILEB + BTILEB, Bl, n0, 0, KP, Brows, tid);
    CPA_COMMIT();

    for (int ci = 0; ci < NC; ci++){
        int b = ci & 1;
        uint32_t st = sb + b*STG;
        CPA_WAIT0();
        __syncthreads();
        if (ci + 1 < NC){
            uint32_t s2 = sb + (1-b)*STG;
            int k0n = (ci+1)*32;
            ld_tileA(s2 + 0,            Ah, m0, k0n, KP, M, tid);
            ld_tileA(s2 + ATILEB,       Al, m0, k0n, KP, M, tid);
            ld_tileB(s2 + 2*ATILEB,          Bh, n0, k0n, KP, Brows, tid);
            ld_tileB(s2 + 2*ATILEB + BTILEB, Bl, n0, k0n, KP, Brows, tid);
            CPA_COMMIT();
        }
        uint32_t bAh = st, bAl = st + ATILEB, bBh = st + 2*ATILEB, bBl = st + 2*ATILEB + BTILEB;
        #pragma unroll
        for (int kk = 0; kk < 32; kk += 16){
            uint32_t ah[2][4], al[2][4];
            #pragma unroll
            for (int mt = 0; mt < 2; mt++){
                uint32_t off = (uint32_t)((wm + mt*16 + a_row)*GPITCH + kk + a_kc) * 2;
                LDMX4(ah[mt], bAh + off);
                LDMX4(al[mt], bAl + off);
            }
            #pragma unroll
            for (int nt2 = 0; nt2 < 2; nt2++){
                uint32_t offb = (uint32_t)((wn + nt2*16 + b_row)*GPITCH + kk + b_kc) * 2;
                uint32_t bh[4], bl[4];
                LDMX4(bh, bBh + offb);
                LDMX4(bl, bBl + offb);
                #pragma unroll
                for (int mt = 0; mt < 2; mt++){
                    MMA16816(acc[mt][nt2*2],   ah[mt], bh[0], bh[1]);
                    MMA16816(acc[mt][nt2*2],   ah[mt], bl[0], bl[1]);
                    MMA16816(acc[mt][nt2*2],   al[mt], bh[0], bh[1]);
                    MMA16816(acc[mt][nt2*2+1], ah[mt], bh[2], bh[3]);
                    MMA16816(acc[mt][nt2*2+1], ah[mt], bl[2], bl[3]);
                    MMA16816(acc[mt][nt2*2+1], al[mt], bh[2], bh[3]);
                }
            }
        }
    }
    #pragma unroll
    for (int mt = 0; mt < 2; mt++){
        int r0 = m0 + wm + mt*16 + (lane >> 2);
        #pragma unroll
        for (int nt = 0; nt < 4; nt++){
            int c = n0 + wn + nt*8 + (lane & 3)*2;
            #pragma unroll
            for (int half = 0; half < 2; half++){
                int rr = r0 + half*8;
                if (rr >= M) continue;
                #pragma unroll
                for (int q = 0; q < 2; q++){
                    int cc = c + q;
                    if (cc >= Nout) continue;
                    float v = acc[mt][nt][half*2 + q];
                    if (bias) v += bias[cc];
                    if (act)  v = fmaxf(v, 0.f);
                    C[(size_t)rr*ldc + cc] = v;
                }
            }
        }
    }
}

// ================= split-prep =================
__global__ void k_split_x(const float* __restrict__ x){
    int i = blockIdx.x*blockDim.x + threadIdx.x;
    if (i >= NN*KP_GAT) return;
    int r = i >> 7, k = i & (KP_GAT-1);
    float v = (k < NF) ? x[r*NF + k] : 0.f;
    split_bf16(v, d_xh[i], d_xl[i]);
}
__global__ void k_splitB(const float* __restrict__ W, __nv_bfloat16* __restrict__ bh,
                         __nv_bfloat16* __restrict__ bl, int K, int N, int KP, int NR){
    int i = blockIdx.x*blockDim.x + threadIdx.x;
    if (i >= NR*KP) return;
    int n = i / KP, k = i - n*KP;
    float v = (k < K && n < N) ? W[(size_t)k*N + n] : 0.f;
    __nv_bfloat16 h, l; split_bf16(v, h, l);
    bh[i] = h; bl[i] = l;
}

// ================= CSR build =================
__global__ void k_deg_init(){
    int n = blockIdx.x*blockDim.x + threadIdx.x;
    if (n < NN) d_deg[n] = 1;
}
__global__ void k_count(const int* __restrict__ ei){
    int e = blockIdx.x*blockDim.x + threadIdx.x;
    if (e < NE) atomicAdd(&d_deg[ei[NE+e]], 1);
}
__global__ void k_scan(){
    __shared__ int part[1024];
    int t = threadIdx.x;
    const int PER = 25;
    int base = t*PER, sum = 0;
    for (int i = 0; i < PER; i++){ int idx = base+i; if (idx < NN) sum += d_deg[idx]; }
    part[t] = sum; __syncthreads();
    for (int off = 1; off < 1024; off <<= 1){
        int v = (t >= off) ? part[t-off] : 0; __syncthreads();
        part[t] += v; __syncthreads();
    }
    int run = part[t] - sum;
    for (int i = 0; i < PER; i++){
        int idx = base+i;
        if (idx < NN){ d_roff[idx] = run; d_rpos[idx] = run; run += d_deg[idx]; }
    }
    if (t == 1023) d_roff[NN] = NEP;
}
__global__ void k_fill(const int* __restrict__ ei){
    int e = blockIdx.x*blockDim.x + threadIdx.x;
    if (e >= NEP) return;
    int s, d;
    if (e < NE){ s = ei[e]; d = ei[NE+e]; } else { s = d = e - NE; }
    int pos = atomicAdd(&d_rpos[d], 1);
    d_csrc[pos] = s;
}
__global__ void k_dinv(){
    int n = blockIdx.x*blockDim.x + threadIdx.x;
    if (n < NN) d_dinv[n] = rsqrtf((float)d_deg[n]);
}

// ================= GAT =================
__global__ void k_attn_coef(const float* __restrict__ att_src,
                            const float* __restrict__ att_dst){
    int wid  = (blockIdx.x*blockDim.x + threadIdx.x) >> 5;
    int lane = threadIdx.x & 31;
    if (wid >= NN*NH) return;
    int n = wid / NH, hh = wid % NH;
    const float* hp = d_h + (size_t)n*HF + hh*NF;
    float s1 = 0.f, s2 = 0.f;
    for (int f = lane; f < NF; f += 32){
        float v = hp[f];
        s1 += v * att_src[hh*NF + f];
        s2 += v * att_dst[hh*NF + f];
    }
    #pragma unroll
    for (int o=16;o>0;o>>=1){ s1 += __shfl_down_sync(~0u,s1,o); s2 += __shfl_down_sync(~0u,s2,o); }
    if (!lane){ d_asrc[wid] = s1; d_adst[wid] = s2; }
}
__global__ void k_gat_soft(){
    int w    = (blockIdx.x*blockDim.x + threadIdx.x) >> 5;
    int lane = threadIdx.x & 31;
    if (w >= NN || lane >= NH) return;
    int s0 = d_roff[w], s1 = d_roff[w+1];
    float ad = d_adst[w*NH + lane];
    float mx = -1e30f;
    for (int p = s0; p < s1; p++){
        float a = d_asrc[d_csrc[p]*NH + lane] + ad;
        a = a > 0.f ? a : 0.2f*a;
        mx = fmaxf(mx, a);
    }
    float sum = 0.f;
    for (int p = s0; p < s1; p++){
        float a = d_asrc[d_csrc[p]*NH + lane] + ad;
        a = a > 0.f ? a : 0.2f*a;
        float e = expf(a - mx);
        d_alpha[(size_t)p*NH + lane] = e;
        sum += e;
    }
    d_invden[w*NH + lane] = 1.f / (sum + 1e-16f);
}
__global__ void k_gat_agg(const float* __restrict__ gat_b){
    int n = blockIdx.x;
    int tid = threadIdx.x;
    __shared__ float invd[NH];
    __shared__ int   csrc_c[25];
    __shared__ float coef_c[25][NH];
    if (tid < NH) invd[tid] = d_invden[n*NH + tid];
    __syncthreads();
    int s0 = d_roff[n], s1 = d_roff[n+1];
    float4 acc = make_float4(0.f,0.f,0.f,0.f);
    int c0 = tid*4;
    int h0 = c0/NF, h1 = (c0+1)/NF, h2 = (c0+2)/NF, h3 = (c0+3)/NF;
    for (int base = s0; base < s1; base += 25){
        int cnt = s1 - base; if (cnt > 25) cnt = 25;
        if (tid < cnt) csrc_c[tid] = d_csrc[base + tid];
        if (tid < cnt*NH){
            int p = tid / NH, hh = tid - p*NH;
            coef_c[p][hh] = d_alpha[(size_t)(base+p)*NH + hh] * invd[hh];
        }
        __syncthreads();
        if (tid < 195){
            #pragma unroll 2
            for (int j = 0; j < cnt; j++){
                float4 v = *(const float4*)(d_h + (size_t)csrc_c[j]*HF + c0);
                acc.x += coef_c[j][h0]*v.x;
                acc.y += coef_c[j][h1]*v.y;
                acc.z += coef_c[j][h2]*v.z;
                acc.w += coef_c[j][h3]*v.w;
            }
        }
        __syncthreads();
    }
    if (tid < 195){
        float4 bb = *(const float4*)(gat_b + c0);
        float r[4] = { fmaxf(acc.x + bb.x, 0.f), fmaxf(acc.y + bb.y, 0.f),
                       fmaxf(acc.z + bb.z, 0.f), fmaxf(acc.w + bb.w, 0.f) };
        #pragma unroll
        for (int q = 0; q < 4; q++){
            __nv_bfloat16 h, l; split_bf16(r[q], h, l);
            d_x1h[(size_t)n*KP_GCN + c0 + q] = h;
            d_x1l[(size_t)n*KP_GCN + c0 + q] = l;
        }
    } else if (tid < 208){
        #pragma unroll
        for (int q = 0; q < 4; q++){
            d_x1h[(size_t)n*KP_GCN + c0 + q] = __float2bfloat16(0.f);
            d_x1l[(size_t)n*KP_GCN + c0 + q] = __float2bfloat16(0.f);
        }
    }
}

// ================= GCN aggregate =================
__global__ void k_gcn_agg(const float* __restrict__ gcn_b){
    int n = blockIdx.x;
    int tid = threadIdx.x;
    __shared__ int   csrc_c[64];
    __shared__ float coef_c[64];
    int s0 = d_roff[n], s1 = d_roff[n+1];
    float dn = d_dinv[n];
    float4 acc = make_float4(0.f,0.f,0.f,0.f);
    int c0 = tid*4;
    for (int base = s0; base < s1; base += 64){
        int cnt = s1 - base; if (cnt > 64) cnt = 64;
        if (tid < cnt){
            int s = d_csrc[base + tid];
            csrc_c[tid] = s;
            coef_c[tid] = dn * d_dinv[s];
        }
        __syncthreads();
        if (tid < 195){
            #pragma unroll 2
            for (int j = 0; j < cnt; j++){
                float4 v = *(const float4*)(d_h2 + (size_t)csrc_c[j]*HF + c0);
                float cf = coef_c[j];
                acc.x += cf*v.x; acc.y += cf*v.y; acc.z += cf*v.z; acc.w += cf*v.w;
            }
        }
        __syncthreads();
    }
    if (tid < 195){
        float4 bb = *(const float4*)(gcn_b + c0);
        float4 r = make_float4(fmaxf(acc.x + bb.x, 0.f), fmaxf(acc.y + bb.y, 0.f),
                               fmaxf(acc.z + bb.z, 0.f), fmaxf(acc.w + bb.w, 0.f));
        *(float4*)(d_x2 + (size_t)n*HF + c0) = r;
    }
}

// ================= pooling =================
__global__ void k_start(const int* __restrict__ batch){
    int g = blockIdx.x*blockDim.x + threadIdx.x;
    if (g > NG) return;
    if (g == NG){ d_start[NG] = NN; return; }
    int lo = 0, hi = NN;
    while (lo < hi){ int mid = (lo+hi) >> 1; if (batch[mid] < g) lo = mid+1; else hi = mid; }
    d_start[g] = lo;
}
__global__ void k_pool(){
    int g = blockIdx.x;
    int s = d_start[g], e = d_start[g+1];
    int cnt = e - s;
    size_t rb = (size_t)g*KP_POOL;
    for (int c = threadIdx.x; c < HF; c += blockDim.x){
        float mx = -1e30f, sm = 0.f;
        #pragma unroll 4
        for (int n = s; n < e; n++){
            float v = d_x2[(size_t)n*HF + c];
            mx = fmaxf(mx, v); sm += v;
        }
        float vmax = (cnt > 0) ? mx : 0.f;
        float vmean = sm / fmaxf((float)cnt, 1.f);
        __nv_bfloat16 h, l;
        split_bf16(vmax, h, l);  d_poolh[rb + c] = h;      d_pooll[rb + c] = l;
        split_bf16(vmean, h, l); d_poolh[rb + HF + c] = h; d_pooll[rb + HF + c] = l;
    }
    if (threadIdx.x < 8){
        d_poolh[rb + 2*HF + threadIdx.x] = __float2bfloat16(0.f);
        d_pooll[rb + 2*HF + threadIdx.x] = __float2bfloat16(0.f);
    }
}

// ================= small GEMM (f32x2, split-K capable) =================
__global__ void gemm2_kernel(const float* __restrict__ A, const float* __restrict__ B,
                             const float* __restrict__ bias, float* __restrict__ C,
                             int M, int N, int K, int ldc, int act)
{
    __shared__ float As[16*64];
    __shared__ float Bs[16*64];
    int tid = threadIdx.x;
    int row0 = blockIdx.y*64, col0 = blockIdx.x*64;
    int tx = tid & 15, ty = tid >> 4;
    int Z = gridDim.z, z = blockIdx.z;
    int T = (K + 15) / 16;
    int kc0 = (int)((long long)T * z / Z), kc1 = (int)((long long)T * (z+1) / Z);
    unsigned long long acc2[4][2];
    #pragma unroll
    for (int i=0;i<4;i++){ acc2[i][0] = 0ull; acc2[i][1] = 0ull; }
    for (int kc = kc0; kc < kc1; kc++){
        int k0 = kc*16;
        #pragma unroll
        for (int i=0;i<4;i++){
            int l = tid + i*256;
            int m = l >> 4, kk = l & 15;
            int r = row0 + m, kg = k0 + kk;
            As[kk*64+m] = (r < M && kg < K) ? A[(size_t)r*K + kg] : 0.f;
        }
        #pragma unroll
        for (int i=0;i<4;i++){
            int l = tid + i*256;
            int kk = l >> 6, n = l & 63;
            int kg = k0 + kk, c = col0 + n;
            Bs[kk*64+n] = (kg < K && c < N) ? B[(size_t)kg*N + c] : 0.f;
        }
        __syncthreads();
        #pragma unroll
        for (int kk=0; kk<16; kk++){
            float ra[4];
            #pragma unroll
            for (int i=0;i<4;i++) ra[i] = As[kk*64 + ty*4 + i];
            unsigned long long rb0 = *(const unsigned long long*)&Bs[kk*64 + tx*4];
            unsigned long long rb1 = *(const unsigned long long*)&Bs[kk*64 + tx*4 + 2];
            #pragma unroll
            for (int i=0;i<4;i++){
                unsigned long long ad;
                asm("mov.b64 %0, {%1, %1};" : "=l"(ad) : "r"(__float_as_uint(ra[i])));
                asm("fma.rn.f32x2 %0, %1, %2, %0;" : "+l"(acc2[i][0]) : "l"(ad), "l"(rb0));
                asm("fma.rn.f32x2 %0, %1, %2, %0;" : "+l"(acc2[i][1]) : "l"(ad), "l"(rb1));
            }
        }
        __syncthreads();
    }
    #pragma unroll
    for (int i=0;i<4;i++){
        int r = row0 + ty*4 + i;
        if (r >= M) continue;
        #pragma unroll
        for (int jp=0;jp<2;jp++){
            unsigned int lo, hi;
            asm("mov.b64 {%0, %1}, %2;" : "=r"(lo), "=r"(hi) : "l"(acc2[i][jp]));
            float vv[2] = { __uint_as_float(lo), __uint_as_float(hi) };
            int c = col0 + tx*4 + jp*2;
            #pragma unroll
            for (int q=0;q<2;q++){
                int cc = c + q;
                if (cc >= N) continue;
                if (Z == 1){
                    float v = vv[q];
                    if (bias) v += bias[cc];
                    if (act)  v = fmaxf(v, 0.f);
                    C[(size_t)r*ldc + cc] = v;
                } else {
                    atomicAdd(&C[(size_t)r*ldc + cc], vv[q]);
                }
            }
        }
    }
}

__global__ void k_binit(float* __restrict__ C, const float* __restrict__ bias,
                        int M, int N, int ldc){
    int i = blockIdx.x*blockDim.x + threadIdx.x;
    if (i >= M*N) return;
    int r = i / N, c = i - r*N;
    C[(size_t)r*ldc + c] = bias[c];
}
__global__ void k_relu(float* __restrict__ C, int total){
    int i = blockIdx.x*blockDim.x + threadIdx.x;
    if (i < total) C[i] = fmaxf(C[i], 0.f);
}

// ================= target branch =================
__global__ void k_buildM(const float* __restrict__ emb){
    int i = blockIdx.x*blockDim.x + threadIdx.x;
    if (i >= 128*KP_U) return;
    int p = i / KP_U, kidx = i - p*KP_U;
    float val = 0.f;
    if (p < CONVOUT && kidx < UCOLS){
        int v = kidx >> 3, kk = kidx & 7;
        val = emb[v*EMB + p + kk];
    }
    __nv_bfloat16 h, l; split_bf16(val, h, l);
    d_Mmh[i] = h; d_Mml[i] = l;
}
__global__ void k_transW(const float* __restrict__ W){
    int i = blockIdx.x*blockDim.x + threadIdx.x;
    if (i >= NFILT*SEQL*8) return;
    int o = i / (SEQL*8), c = (i >> 3) % SEQL, k = i & 7;
    d_Wt[c*(NFILT*8) + o*8 + k] = W[i];
}
__global__ void k_buildU(const int* __restrict__ target){
    __shared__ float sU[USZ];
    __shared__ int   st[SEQL];
    int g = blockIdx.x;
    for (int i = threadIdx.x; i < USZ;  i += blockDim.x) sU[i] = 0.f;
    for (int i = threadIdx.x; i < SEQL; i += blockDim.x) st[i] = target[g*SEQL + i];
    __syncthreads();
    int o = threadIdx.x >> 3, k = threadIdx.x & 7;
    for (int c = 0; c < SEQL; c++){
        int v = st[c];
        sU[o*UCOLS + v*8 + k] += d_Wt[c*(NFILT*8) + threadIdx.x];
    }
    __syncthreads();
    for (int i = threadIdx.x; i < NFILT*KP_U; i += blockDim.x){
        int oo = i / KP_U, col = i - oo*KP_U;
        float v = (col < UCOLS) ? sU[oo*UCOLS + col] : 0.f;
        __nv_bfloat16 h, l; split_bf16(v, h, l);
        size_t idx = ((size_t)g*NFILT + oo)*KP_U + col;
        d_Uh[idx] = h; d_Ul[idx] = l;
    }
}
__global__ void k_fcxtb2(const float* __restrict__ fcxt_W,
                         const float* __restrict__ fcxt_b,
                         const float* __restrict__ conv_b){
    int j = blockIdx.x;
    __shared__ float red[128];
    float s = 0.f;
    for (int r = threadIdx.x; r < NFILT*CONVOUT; r += blockDim.x)
        s += conv_b[r / CONVOUT] * fcxt_W[(size_t)r*128 + j];
    red[threadIdx.x] = s; __syncthreads();
    for (int o = 64; o > 0; o >>= 1){
        if (threadIdx.x < o) red[threadIdx.x] += red[threadIdx.x + o];
        __syncthreads();
    }
    if (!threadIdx.x) d_fcxtb2[j] = fcxt_b[j] + red[0];
}

// ================= final projection =================
__global__ void k_out(const float* __restrict__ oW, const float* __restrict__ ob,
                      float* __restrict__ out){
    int g    = (blockIdx.x*blockDim.x + threadIdx.x) >> 5;
    int lane = threadIdx.x & 31;
    if (g >= NG) return;
    float s = 0.f;
    for (int k = lane; k < 512; k += 32) s += d_f2[g*512 + k] * oW[k];
    #pragma unroll
    for (int o = 16; o > 0; o >>= 1) s += __shfl_down_sync(~0u, s, o);
    if (!lane) out[g] = s + ob[0];
}

extern "C" void kernel_launch(void* const* d_in, const int* in_sizes, int n_in,
                              void* d_out, int out_size){
    const float* x        = (const float*)d_in[0];
    const int*   ei       = (const int*)  d_in[1];
    const int*   batch    = (const int*)  d_in[2];
    const int*   target   = (const int*)  d_in[3];
    const float* gat_W    = (const float*)d_in[4];
    const float* gat_asrc = (const float*)d_in[5];
    const float* gat_adst = (const float*)d_in[6];
    const float* gat_b    = (const float*)d_in[7];
    const float* gcn_W    = (const float*)d_in[8];
    const float* gcn_b    = (const float*)d_in[9];
    const float* fcg1_W   = (const float*)d_in[10];
    const float* fcg1_b   = (const float*)d_in[11];
    const float* fcg2_W   = (const float*)d_in[12];
    const float* fcg2_b   = (const float*)d_in[13];
    const float* emb      = (const float*)d_in[14];
    const float* conv_W   = (const float*)d_in[15];
    const float* conv_b   = (const float*)d_in[16];
    const float* fcxt_W   = (const float*)d_in[17];
    const float* fcxt_b   = (const float*)d_in[18];
    const float* fc1_W    = (const float*)d_in[19];
    const float* fc1_b    = (const float*)d_in[20];
    const float* fc2_W    = (const float*)d_in[21];
    const float* fc2_b    = (const float*)d_in[22];
    const float* out_W    = (const float*)d_in[23];
    const float* out_b    = (const float*)d_in[24];

    float *p_h, *p_h2, *p_xg1, *p_xc, *p_conv, *p_f1, *p_f2, *p_fcxtb2;
    __nv_bfloat16 *p_xh, *p_xl, *p_x1h, *p_x1l, *p_gWh, *p_gWl, *p_cWh, *p_cWl;
    __nv_bfloat16 *p_poolh, *p_pooll, *p_fWh, *p_fWl, *p_Uh, *p_Ul, *p_Mmh, *p_Mml;
    cudaGetSymbolAddress((void**)&p_h,    d_h);
    cudaGetSymbolAddress((void**)&p_h2,   d_h2);
    cudaGetSymbolAddress((void**)&p_xg1,  d_xg1);
    cudaGetSymbolAddress((void**)&p_xc,   d_xc);
    cudaGetSymbolAddress((void**)&p_conv, d_conv);
    cudaGetSymbolAddress((void**)&p_f1,   d_f1);
    cudaGetSymbolAddress((void**)&p_f2,   d_f2);
    cudaGetSymbolAddress((void**)&p_fcxtb2, d_fcxtb2);
    cudaGetSymbolAddress((void**)&p_xh,  d_xh);
    cudaGetSymbolAddress((void**)&p_xl,  d_xl);
    cudaGetSymbolAddress((void**)&p_x1h, d_x1h);
    cudaGetSymbolAddress((void**)&p_x1l, d_x1l);
    cudaGetSymbolAddress((void**)&p_gWh, d_gWh);
    cudaGetSymbolAddress((void**)&p_gWl, d_gWl);
    cudaGetSymbolAddress((void**)&p_cWh, d_cWh);
    cudaGetSymbolAddress((void**)&p_cWl, d_cWl);
    cudaGetSymbolAddress((void**)&p_poolh, d_poolh);
    cudaGetSymbolAddress((void**)&p_pooll, d_pooll);
    cudaGetSymbolAddress((void**)&p_fWh, d_fWh);
    cudaGetSymbolAddress((void**)&p_fWl, d_fWl);
    cudaGetSymbolAddress((void**)&p_Uh, d_Uh);
    cudaGetSymbolAddress((void**)&p_Ul, d_Ul);
    cudaGetSymbolAddress((void**)&p_Mmh, d_Mmh);
    cudaGetSymbolAddress((void**)&p_Mml, d_Mml);

    cudaFuncSetAttribute(gemm_mma, cudaFuncAttributeMaxDynamicSharedMemorySize, 2*STG);

    // launches 0..2: splits (so launch 3 = gemm_mma GAT lands under ncu -s 5)
    k_split_x<<<(NN*KP_GAT + 255)/256, 256>>>(x);
    k_splitB<<<(NPADG*KP_GAT + 255)/256, 256>>>(gat_W, p_gWh, p_gWl, NF, HF, KP_GAT, NPADG);
    k_splitB<<<(NPADG*KP_GCN + 255)/256, 256>>>(gcn_W, p_cWh, p_cWl, HF, HF, KP_GCN, NPADG);

    // launch 3: GAT transform (profiled)
    {
        dim3 grid(NPADG/64, (NN + 127)/128);
        gemm_mma<<<grid, 256, 2*STG>>>(p_xh, p_xl, p_gWh, p_gWl, p_h, NN, HF, KP_GAT, HF, nullptr, 0, NPADG);
    }

    // CSR build
    k_deg_init<<<(NN + 255)/256, 256>>>();
    k_count<<<(NE + 255)/256, 256>>>(ei);
    k_scan<<<1, 1024>>>();
    k_fill<<<(NEP + 255)/256, 256>>>(ei);
    k_dinv<<<(NN + 255)/256, 256>>>();

    // remaining prep
    k_splitB<<<(NP_FCG1*KP_POOL + 255)/256, 256>>>(fcg1_W, p_fWh, p_fWl, 2*HF, 1024, KP_POOL, NP_FCG1);
    k_buildM<<<(128*KP_U + 255)/256, 256>>>(emb);
    k_transW<<<(NFILT*SEQL*8 + 255)/256, 256>>>(conv_W);

    // GAT attention + aggregation
    k_attn_coef<<<(NN*NH*32 + 255)/256, 256>>>(gat_asrc, gat_adst);
    k_gat_soft<<<(NN*32 + 255)/256, 256>>>();
    k_gat_agg<<<NN, 256>>>(gat_b);

    // GCN
    {
        dim3 grid(NPADG/64, (NN + 127)/128);
        gemm_mma<<<grid, 256, 2*STG>>>(p_x1h, p_x1l, p_cWh, p_cWl, p_h2, NN, HF, KP_GCN, HF, nullptr, 0, NPADG);
    }
    k_gcn_agg<<<NN, 256>>>(gcn_b);

    // pooling + graph head
    k_start<<<3, 256>>>(batch);
    k_pool<<<NG, 256>>>();
    {   // fcg1 on tensor cores, fused bias+relu
        dim3 grid(1024/64, NG/128);
        gemm_mma<<<grid, 256, 2*STG>>>(p_poolh, p_pooll, p_fWh, p_fWl, p_xg1, NG, 1024, KP_POOL, 1024, fcg1_b, 1, NP_FCG1);
    }
    {   // fcg2 split-K
        k_binit<<<(NG*128 + 255)/256, 256>>>(p_xc, fcg2_b, NG, 128, 256);
        dim3 grid(2, 8, 4);
        gemm2_kernel<<<grid, 256>>>(p_xg1, fcg2_W, nullptr, p_xc, NG, 128, 1024, 256, 0);
    }

    // target branch
    k_buildU<<<NG, 256>>>(target);
    {   // conv GEMM on tensor cores
        dim3 grid(2, (NG*NFILT)/128);
        gemm_mma<<<grid, 256, 2*STG>>>(p_Uh, p_Ul, p_Mmh, p_Mml, p_conv, NG*NFILT, CONVOUT, KP_U, CONVOUT, nullptr, 0, 128);
    }
    k_fcxtb2<<<128, 128>>>(fcxt_W, fcxt_b, conv_b);
    {   // fcxt split-K
        k_binit<<<(NG*128 + 255)/256, 256>>>(p_xc + 128, p_fcxtb2, NG, 128, 256);
        dim3 grid(2, 8, 4);
        gemm2_kernel<<<grid, 256>>>(p_conv, fcxt_W, nullptr, p_xc + 128, NG, 128, NFILT*CONVOUT, 256, 0);
    }

    // fusion head
    {
        dim3 grid(16, 8, 1);
        gemm2_kernel<<<grid, 256>>>(p_xc, fc1_W, fc1_b, p_f1, NG, 1024, 256, 1024, 1);
    }
    {
        k_binit<<<(NG*512 + 255)/256, 256>>>(p_f2, fc2_b, NG, 512, 512);
        dim3 grid(8, 8, 2);
        gemm2_kernel<<<grid, 256>>>(p_f1, fc2_W, nullptr, p_f2, NG, 512, 1024, 512, 0);
        k_relu<<<(NG*512 + 255)/256, 256>>>(p_f2, NG*512);
    }
    k_out<<<(NG*32 + 255)/256, 256>>>(out_W, out_b, (float*)d_out);
}

// round 8
// speedup vs baseline: 3.0435x; 1.0433x over previous
#include <cuda_runtime.h>
#include <cuda_bf16.h>
#include <math.h>
#include <stdint.h>

#define NN      25000
#define NE      100000
#define NEP     125000
#define NG      512
#define NH      10
#define NF      78
#define HF      780
#define SEQL    1000
#define EMB     128
#define NFILT   32
#define CONVOUT 121
#define VOCAB   26
#define UCOLS   (VOCAB*8)        // 208
#define USZ     (NFILT*UCOLS)

#define KP_GAT  128
#define KP_GCN  832
#define NPADG   832
#define KP_POOL 1600             // 2*780 -> 1600 (64-divisible)
#define NP_FCG1 1024
#define KP_U    256              // 208 -> 256 (64-divisible)

// ---------------- device scratch ----------------
__device__ float d_h[NN*HF];
__device__ float d_asrc[NN*NH];
__device__ float d_adst[NN*NH];
__device__ float d_invden[NN*NH];
__device__ float d_alpha[(size_t)NEP*NH];
__device__ float d_h2[NN*HF];
__device__ float d_x2[NN*HF];
__device__ float d_dinv[NN];
__device__ int   d_deg[NN];
__device__ int   d_roff[NN+1];
__device__ int   d_rpos[NN];
__device__ int   d_csrc[NEP];
__device__ int   d_start[NG+1];
__device__ float d_xg1[NG*1024];
__device__ float d_Wt[SEQL*NFILT*8];
__device__ float d_conv[(size_t)NG*NFILT*CONVOUT];
__device__ float d_fcxtb2[128];
__device__ float d_xc[NG*256];
__device__ float d_f1[NG*1024];
__device__ float d_f2[NG*512];
__device__ __nv_bfloat16 d_xh[(size_t)NN*KP_GAT];
__device__ __nv_bfloat16 d_xl[(size_t)NN*KP_GAT];
__device__ __nv_bfloat16 d_x1h[(size_t)NN*KP_GCN];
__device__ __nv_bfloat16 d_x1l[(size_t)NN*KP_GCN];
__device__ __nv_bfloat16 d_gWh[(size_t)NPADG*KP_GAT];
__device__ __nv_bfloat16 d_gWl[(size_t)NPADG*KP_GAT];
__device__ __nv_bfloat16 d_cWh[(size_t)NPADG*KP_GCN];
__device__ __nv_bfloat16 d_cWl[(size_t)NPADG*KP_GCN];
__device__ __nv_bfloat16 d_poolh[(size_t)NG*KP_POOL];
__device__ __nv_bfloat16 d_pooll[(size_t)NG*KP_POOL];
__device__ __nv_bfloat16 d_fWh[(size_t)NP_FCG1*KP_POOL];
__device__ __nv_bfloat16 d_fWl[(size_t)NP_FCG1*KP_POOL];
__device__ __nv_bfloat16 d_Uh[(size_t)NG*NFILT*KP_U];
__device__ __nv_bfloat16 d_Ul[(size_t)NG*NFILT*KP_U];
__device__ __nv_bfloat16 d_Mmh[128*KP_U];
__device__ __nv_bfloat16 d_Mml[128*KP_U];

// ================= helpers =================
__device__ __forceinline__ uint32_t smem_u32(const void* p){
    uint32_t a;
    asm("{ .reg .u64 t; cvta.to.shared.u64 t, %1; cvt.u32.u64 %0, t; }" : "=r"(a) : "l"(p));
    return a;
}
#define LDMX4(r, a) \
    asm volatile("ldmatrix.sync.aligned.m8n8.x4.shared.b16 {%0,%1,%2,%3}, [%4];" \
        : "=r"((r)[0]), "=r"((r)[1]), "=r"((r)[2]), "=r"((r)[3]) : "r"(a))
#define MMA16816(d, a, b0, b1) \
    asm volatile("mma.sync.aligned.m16n8k16.row.col.f32.bf16.bf16.f32 " \
        "{%0,%1,%2,%3}, {%4,%5,%6,%7}, {%8,%9}, {%0,%1,%2,%3};" \
        : "+f"((d)[0]), "+f"((d)[1]), "+f"((d)[2]), "+f"((d)[3]) \
        : "r"((a)[0]), "r"((a)[1]), "r"((a)[2]), "r"((a)[3]), "r"(b0), "r"(b1))
#define CPA_COMMIT() asm volatile("cp.async.commit_group;" ::: "memory")
#define CPA_WAIT0()  asm volatile("cp.async.wait_group 0;" ::: "memory")

__device__ __forceinline__ void cpa16(uint32_t dst, const void* src, int sz){
    size_t g;
    asm("cvta.to.global.u64 %0, %1;" : "=l"(g) : "l"(src));
    asm volatile("cp.async.cg.shared.global [%0], [%1], 16, %2;" :: "r"(dst), "l"(g), "r"(sz) : "memory");
}
__device__ __forceinline__ void split_bf16(float v, __nv_bfloat16& h, __nv_bfloat16& l){
    h = __float2bfloat16(v);
    l = __float2bfloat16(v - __bfloat162float(h));
}

// ================= mma.sync split-bf16 GEMM =================
// CTA tile 128(M) x 64(N), K chunk 64, 8 warps of 32x32, 2-stage cp.async,
// register double-buffered fragments for LDSM/MMA overlap.
#define GPITCH 72        // 64 + 8 pad bf16 per row (144B pitch, odd*16B -> conflict-free)
#define ATILEB 18432     // 128 * 144
#define BTILEB 9216      // 64 * 144
#define STG    55296     // AH + AL + BH + BL

__device__ __forceinline__ void ld_tileA(uint32_t sdst, const __nv_bfloat16* G,
                                         int row0, int k0, int KP, int rlim, int tid){
    #pragma unroll
    for (int i = 0; i < 4; i++){
        int v = tid + i*256;          // 0..1023
        int r = v >> 3, cq = v & 7;
        int row = row0 + r;
        int sz = (row < rlim) ? 16 : 0;
        cpa16(sdst + r*144 + cq*16, G + (size_t)(sz ? row : row0)*KP + k0 + cq*8, sz);
    }
}
__device__ __forceinline__ void ld_tileB(uint32_t sdst, const __nv_bfloat16* G,
                                         int row0, int k0, int KP, int rlim, int tid){
    #pragma unroll
    for (int i = 0; i < 2; i++){
        int v = tid + i*256;          // 0..511
        int r = v >> 3, cq = v & 7;
        int row = row0 + r;
        int sz = (row < rlim) ? 16 : 0;
        cpa16(sdst + r*144 + cq*16, G + (size_t)(sz ? row : row0)*KP + k0 + cq*8, sz);
    }
}

__global__ void __launch_bounds__(256, 2) gemm_mma(
    const __nv_bfloat16* __restrict__ Ah, const __nv_bfloat16* __restrict__ Al,
    const __nv_bfloat16* __restrict__ Bh, const __nv_bfloat16* __restrict__ Bl,
    float* __restrict__ C, int M, int Nout, int KP, int ldc,
    const float* __restrict__ bias, int act, int Brows)
{
    extern __shared__ char sm[];
    uint32_t sb = smem_u32(sm);
    int tid = threadIdx.x;
    int m0 = blockIdx.y*128, n0 = blockIdx.x*64;
    int w = tid >> 5, lane = tid & 31;
    int wm = (w >> 1) * 32;
    int wn = (w & 1) * 32;
    int NC = KP / 64;

    float acc[2][4][4];
    #pragma unroll
    for (int i=0;i<2;i++)
        #pragma unroll
        for (int j=0;j<4;j++)
            #pragma unroll
            for (int q=0;q<4;q++) acc[i][j][q] = 0.f;

    int a_row = (lane & 15);
    int a_kc  = (lane >> 4) * 8;
    int b_row = ((lane >> 4) * 8) + (lane & 7);
    int b_kc  = ((lane >> 3) & 1) * 8;

    ld_tileA(sb + 0,                 Ah, m0, 0, KP, M, tid);
    ld_tileA(sb + ATILEB,            Al, m0, 0, KP, M, tid);
    ld_tileB(sb + 2*ATILEB,          Bh, n0, 0, KP, Brows, tid);
    ld_tileB(sb + 2*ATILEB + BTILEB, Bl, n0, 0, KP, Brows, tid);
    CPA_COMMIT();

    uint32_t ah[2][2][4], al[2][2][4], bh[2][2][4], bl[2][2][4];

    for (int ci = 0; ci < NC; ci++){
        int b = ci & 1;
        uint32_t st = sb + b*STG;
        CPA_WAIT0();
        __syncthreads();
        if (ci + 1 < NC){
            uint32_t s2 = sb + (1-b)*STG;
            int k0n = (ci+1)*64;
            ld_tileA(s2 + 0,                 Ah, m0, k0n, KP, M, tid);
            ld_tileA(s2 + ATILEB,            Al, m0, k0n, KP, M, tid);
            ld_tileB(s2 + 2*ATILEB,          Bh, n0, k0n, KP, Brows, tid);
            ld_tileB(s2 + 2*ATILEB + BTILEB, Bl, n0, k0n, KP, Brows, tid);
            CPA_COMMIT();
        }
        uint32_t bAh = st, bAl = st + ATILEB, bBh = st + 2*ATILEB, bBl = st + 2*ATILEB + BTILEB;

        #define LOADF(buf, kk) do{ \
            _Pragma("unroll") \
            for (int mt = 0; mt < 2; mt++){ \
                uint32_t off = (uint32_t)((wm + mt*16 + a_row)*GPITCH + (kk) + a_kc) * 2; \
                LDMX4(ah[buf][mt], bAh + off); \
                LDMX4(al[buf][mt], bAl + off); \
            } \
            _Pragma("unroll") \
            for (int nt = 0; nt < 2; nt++){ \
                uint32_t offb = (uint32_t)((wn + nt*16 + b_row)*GPITCH + (kk) + b_kc) * 2; \
                LDMX4(bh[buf][nt], bBh + offb); \
                LDMX4(bl[buf][nt], bBl + offb); \
            } \
        }while(0)

        LOADF(0, 0);
        #pragma unroll
        for (int kks = 0; kks < 4; kks++){
            int cur = kks & 1;
            if (kks < 3){
                int nxt = 1 - cur;
                LOADF(nxt, (kks+1)*16);
            }
            #pragma unroll
            for (int nt2 = 0; nt2 < 2; nt2++){
                #pragma unroll
                for (int mt = 0; mt < 2; mt++){
                    MMA16816(acc[mt][nt2*2],   ah[cur][mt], bh[cur][nt2][0], bh[cur][nt2][1]);
                    MMA16816(acc[mt][nt2*2],   ah[cur][mt], bl[cur][nt2][0], bl[cur][nt2][1]);
                    MMA16816(acc[mt][nt2*2],   al[cur][mt], bh[cur][nt2][0], bh[cur][nt2][1]);
                    MMA16816(acc[mt][nt2*2+1], ah[cur][mt], bh[cur][nt2][2], bh[cur][nt2][3]);
                    MMA16816(acc[mt][nt2*2+1], ah[cur][mt], bl[cur][nt2][2], bl[cur][nt2][3]);
                    MMA16816(acc[mt][nt2*2+1], al[cur][mt], bh[cur][nt2][2], bh[cur][nt2][3]);
                }
            }
        }
        #undef LOADF
    }
    #pragma unroll
    for (int mt = 0; mt < 2; mt++){
        int r0 = m0 + wm + mt*16 + (lane >> 2);
        #pragma unroll
        for (int nt = 0; nt < 4; nt++){
            int c = n0 + wn + nt*8 + (lane & 3)*2;
            #pragma unroll
            for (int half = 0; half < 2; half++){
                int rr = r0 + half*8;
                if (rr >= M) continue;
                #pragma unroll
                for (int q = 0; q < 2; q++){
                    int cc = c + q;
                    if (cc >= Nout) continue;
                    float v = acc[mt][nt][half*2 + q];
                    if (bias) v += bias[cc];
                    if (act)  v = fmaxf(v, 0.f);
                    C[(size_t)rr*ldc + cc] = v;
                }
            }
        }
    }
}

// ================= split-prep =================
__global__ void k_split_x(const float* __restrict__ x){
    int i = blockIdx.x*blockDim.x + threadIdx.x;
    if (i >= NN*KP_GAT) return;
    int r = i >> 7, k = i & (KP_GAT-1);
    float v = (k < NF) ? x[r*NF + k] : 0.f;
    split_bf16(v, d_xh[i], d_xl[i]);
}
__global__ void k_splitB(const float* __restrict__ W, __nv_bfloat16* __restrict__ bh,
                         __nv_bfloat16* __restrict__ bl, int K, int N, int KP, int NR){
    int i = blockIdx.x*blockDim.x + threadIdx.x;
    if (i >= NR*KP) return;
    int n = i / KP, k = i - n*KP;
    float v = (k < K && n < N) ? W[(size_t)k*N + n] : 0.f;
    __nv_bfloat16 h, l; split_bf16(v, h, l);
    bh[i] = h; bl[i] = l;
}

// ================= CSR build =================
__global__ void k_deg_init(){
    int n = blockIdx.x*blockDim.x + threadIdx.x;
    if (n < NN) d_deg[n] = 1;
}
__global__ void k_count(const int* __restrict__ ei){
    int e = blockIdx.x*blockDim.x + threadIdx.x;
    if (e < NE) atomicAdd(&d_deg[ei[NE+e]], 1);
}
__global__ void k_scan(){
    __shared__ int part[1024];
    int t = threadIdx.x;
    const int PER = 25;
    int base = t*PER, sum = 0;
    for (int i = 0; i < PER; i++){ int idx = base+i; if (idx < NN) sum += d_deg[idx]; }
    part[t] = sum; __syncthreads();
    for (int off = 1; off < 1024; off <<= 1){
        int v = (t >= off) ? part[t-off] : 0; __syncthreads();
        part[t] += v; __syncthreads();
    }
    int run = part[t] - sum;
    for (int i = 0; i < PER; i++){
        int idx = base+i;
        if (idx < NN){ d_roff[idx] = run; d_rpos[idx] = run; run += d_deg[idx]; }
    }
    if (t == 1023) d_roff[NN] = NEP;
}
__global__ void k_fill(const int* __restrict__ ei){
    int e = blockIdx.x*blockDim.x + threadIdx.x;
    if (e >= NEP) return;
    int s, d;
    if (e < NE){ s = ei[e]; d = ei[NE+e]; } else { s = d = e - NE; }
    int pos = atomicAdd(&d_rpos[d], 1);
    d_csrc[pos] = s;
}
__global__ void k_dinv(){
    int n = blockIdx.x*blockDim.x + threadIdx.x;
    if (n < NN) d_dinv[n] = rsqrtf((float)d_deg[n]);
}

// ================= GAT =================
__global__ void k_attn_coef(const float* __restrict__ att_src,
                            const float* __restrict__ att_dst){
    int wid  = (blockIdx.x*blockDim.x + threadIdx.x) >> 5;
    int lane = threadIdx.x & 31;
    if (wid >= NN*NH) return;
    int n = wid / NH, hh = wid % NH;
    const float* hp = d_h + (size_t)n*HF + hh*NF;
    float s1 = 0.f, s2 = 0.f;
    for (int f = lane; f < NF; f += 32){
        float v = hp[f];
        s1 += v * att_src[hh*NF + f];
        s2 += v * att_dst[hh*NF + f];
    }
    #pragma unroll
    for (int o=16;o>0;o>>=1){ s1 += __shfl_down_sync(~0u,s1,o); s2 += __shfl_down_sync(~0u,s2,o); }
    if (!lane){ d_asrc[wid] = s1; d_adst[wid] = s2; }
}
__global__ void k_gat_soft(){
    int w    = (blockIdx.x*blockDim.x + threadIdx.x) >> 5;
    int lane = threadIdx.x & 31;
    if (w >= NN || lane >= NH) return;
    int s0 = d_roff[w], s1 = d_roff[w+1];
    float ad = d_adst[w*NH + lane];
    float mx = -1e30f;
    for (int p = s0; p < s1; p++){
        float a = d_asrc[d_csrc[p]*NH + lane] + ad;
        a = a > 0.f ? a : 0.2f*a;
        mx = fmaxf(mx, a);
    }
    float sum = 0.f;
    for (int p = s0; p < s1; p++){
        float a = d_asrc[d_csrc[p]*NH + lane] + ad;
        a = a > 0.f ? a : 0.2f*a;
        float e = expf(a - mx);
        d_alpha[(size_t)p*NH + lane] = e;
        sum += e;
    }
    d_invden[w*NH + lane] = 1.f / (sum + 1e-16f);
}
__global__ void k_gat_agg(const float* __restrict__ gat_b){
    int n = blockIdx.x;
    int tid = threadIdx.x;
    __shared__ float invd[NH];
    __shared__ int   csrc_c[25];
    __shared__ float coef_c[25][NH];
    if (tid < NH) invd[tid] = d_invden[n*NH + tid];
    __syncthreads();
    int s0 = d_roff[n], s1 = d_roff[n+1];
    float4 acc = make_float4(0.f,0.f,0.f,0.f);
    int c0 = tid*4;
    int h0 = c0/NF, h1 = (c0+1)/NF, h2 = (c0+2)/NF, h3 = (c0+3)/NF;
    for (int base = s0; base < s1; base += 25){
        int cnt = s1 - base; if (cnt > 25) cnt = 25;
        if (tid < cnt) csrc_c[tid] = d_csrc[base + tid];
        if (tid < cnt*NH){
            int p = tid / NH, hh = tid - p*NH;
            coef_c[p][hh] = d_alpha[(size_t)(base+p)*NH + hh] * invd[hh];
        }
        __syncthreads();
        if (tid < 195){
            #pragma unroll 2
            for (int j = 0; j < cnt; j++){
                float4 v = *(const float4*)(d_h + (size_t)csrc_c[j]*HF + c0);
                acc.x += coef_c[j][h0]*v.x;
                acc.y += coef_c[j][h1]*v.y;
                acc.z += coef_c[j][h2]*v.z;
                acc.w += coef_c[j][h3]*v.w;
            }
        }
        __syncthreads();
    }
    if (tid < 195){
        float4 bb = *(const float4*)(gat_b + c0);
        float r[4] = { fmaxf(acc.x + bb.x, 0.f), fmaxf(acc.y + bb.y, 0.f),
                       fmaxf(acc.z + bb.z, 0.f), fmaxf(acc.w + bb.w, 0.f) };
        #pragma unroll
        for (int q = 0; q < 4; q++){
            __nv_bfloat16 h, l; split_bf16(r[q], h, l);
            d_x1h[(size_t)n*KP_GCN + c0 + q] = h;
            d_x1l[(size_t)n*KP_GCN + c0 + q] = l;
        }
    } else if (tid < 208){
        #pragma unroll
        for (int q = 0; q < 4; q++){
            d_x1h[(size_t)n*KP_GCN + c0 + q] = __float2bfloat16(0.f);
            d_x1l[(size_t)n*KP_GCN + c0 + q] = __float2bfloat16(0.f);
        }
    }
}

// ================= GCN aggregate =================
__global__ void k_gcn_agg(const float* __restrict__ gcn_b){
    int n = blockIdx.x;
    int tid = threadIdx.x;
    __shared__ int   csrc_c[64];
    __shared__ float coef_c[64];
    int s0 = d_roff[n], s1 = d_roff[n+1];
    float dn = d_dinv[n];
    float4 acc = make_float4(0.f,0.f,0.f,0.f);
    int c0 = tid*4;
    for (int base = s0; base < s1; base += 64){
        int cnt = s1 - base; if (cnt > 64) cnt = 64;
        if (tid < cnt){
            int s = d_csrc[base + tid];
            csrc_c[tid] = s;
            coef_c[tid] = dn * d_dinv[s];
        }
        __syncthreads();
        if (tid < 195){
            #pragma unroll 2
            for (int j = 0; j < cnt; j++){
                float4 v = *(const float4*)(d_h2 + (size_t)csrc_c[j]*HF + c0);
                float cf = coef_c[j];
                acc.x += cf*v.x; acc.y += cf*v.y; acc.z += cf*v.z; acc.w += cf*v.w;
            }
        }
        __syncthreads();
    }
    if (tid < 195){
        float4 bb = *(const float4*)(gcn_b + c0);
        float4 r = make_float4(fmaxf(acc.x + bb.x, 0.f), fmaxf(acc.y + bb.y, 0.f),
                               fmaxf(acc.z + bb.z, 0.f), fmaxf(acc.w + bb.w, 0.f));
        *(float4*)(d_x2 + (size_t)n*HF + c0) = r;
    }
}

// ================= pooling =================
__global__ void k_start(const int* __restrict__ batch){
    int g = blockIdx.x*blockDim.x + threadIdx.x;
    if (g > NG) return;
    if (g == NG){ d_start[NG] = NN; return; }
    int lo = 0, hi = NN;
    while (lo < hi){ int mid = (lo+hi) >> 1; if (batch[mid] < g) lo = mid+1; else hi = mid; }
    d_start[g] = lo;
}
__global__ void k_pool(){
    int g = blockIdx.x;
    int s = d_start[g], e = d_start[g+1];
    int cnt = e - s;
    size_t rb = (size_t)g*KP_POOL;
    for (int c = threadIdx.x; c < HF; c += blockDim.x){
        float mx = -1e30f, sm = 0.f;
        #pragma unroll 4
        for (int n = s; n < e; n++){
            float v = d_x2[(size_t)n*HF + c];
            mx = fmaxf(mx, v); sm += v;
        }
        float vmax = (cnt > 0) ? mx : 0.f;
        float vmean = sm / fmaxf((float)cnt, 1.f);
        __nv_bfloat16 h, l;
        split_bf16(vmax, h, l);  d_poolh[rb + c] = h;      d_pooll[rb + c] = l;
        split_bf16(vmean, h, l); d_poolh[rb + HF + c] = h; d_pooll[rb + HF + c] = l;
    }
    if (threadIdx.x < KP_POOL - 2*HF){
        d_poolh[rb + 2*HF + threadIdx.x] = __float2bfloat16(0.f);
        d_pooll[rb + 2*HF + threadIdx.x] = __float2bfloat16(0.f);
    }
}

// ================= small GEMM (f32x2, split-K capable) =================
__global__ void gemm2_kernel(const float* __restrict__ A, const float* __restrict__ B,
                             const float* __restrict__ bias, float* __restrict__ C,
                             int M, int N, int K, int ldc, int act)
{
    __shared__ float As[16*64];
    __shared__ float Bs[16*64];
    int tid = threadIdx.x;
    int row0 = blockIdx.y*64, col0 = blockIdx.x*64;
    int tx = tid & 15, ty = tid >> 4;
    int Z = gridDim.z, z = blockIdx.z;
    int T = (K + 15) / 16;
    int kc0 = (int)((long long)T * z / Z), kc1 = (int)((long long)T * (z+1) / Z);
    unsigned long long acc2[4][2];
    #pragma unroll
    for (int i=0;i<4;i++){ acc2[i][0] = 0ull; acc2[i][1] = 0ull; }
    for (int kc = kc0; kc < kc1; kc++){
        int k0 = kc*16;
        #pragma unroll
        for (int i=0;i<4;i++){
            int l = tid + i*256;
            int m = l >> 4, kk = l & 15;
            int r = row0 + m, kg = k0 + kk;
            As[kk*64+m] = (r < M && kg < K) ? A[(size_t)r*K + kg] : 0.f;
        }
        #pragma unroll
        for (int i=0;i<4;i++){
            int l = tid + i*256;
            int kk = l >> 6, n = l & 63;
            int kg = k0 + kk, c = col0 + n;
            Bs[kk*64+n] = (kg < K && c < N) ? B[(size_t)kg*N + c] : 0.f;
        }
        __syncthreads();
        #pragma unroll
        for (int kk=0; kk<16; kk++){
            float ra[4];
            #pragma unroll
            for (int i=0;i<4;i++) ra[i] = As[kk*64 + ty*4 + i];
            unsigned long long rb0 = *(const unsigned long long*)&Bs[kk*64 + tx*4];
            unsigned long long rb1 = *(const unsigned long long*)&Bs[kk*64 + tx*4 + 2];
            #pragma unroll
            for (int i=0;i<4;i++){
                unsigned long long ad;
                asm("mov.b64 %0, {%1, %1};" : "=l"(ad) : "r"(__float_as_uint(ra[i])));
                asm("fma.rn.f32x2 %0, %1, %2, %0;" : "+l"(acc2[i][0]) : "l"(ad), "l"(rb0));
                asm("fma.rn.f32x2 %0, %1, %2, %0;" : "+l"(acc2[i][1]) : "l"(ad), "l"(rb1));
            }
        }
        __syncthreads();
    }
    #pragma unroll
    for (int i=0;i<4;i++){
        int r = row0 + ty*4 + i;
        if (r >= M) continue;
        #pragma unroll
        for (int jp=0;jp<2;jp++){
            unsigned int lo, hi;
            asm("mov.b64 {%0, %1}, %2;" : "=r"(lo), "=r"(hi) : "l"(acc2[i][jp]));
            float vv[2] = { __uint_as_float(lo), __uint_as_float(hi) };
            int c = col0 + tx*4 + jp*2;
            #pragma unroll
            for (int q=0;q<2;q++){
                int cc = c + q;
                if (cc >= N) continue;
                if (Z == 1){
                    float v = vv[q];
                    if (bias) v += bias[cc];
                    if (act)  v = fmaxf(v, 0.f);
                    C[(size_t)r*ldc + cc] = v;
                } else {
                    atomicAdd(&C[(size_t)r*ldc + cc], vv[q]);
                }
            }
        }
    }
}

__global__ void k_binit(float* __restrict__ C, const float* __restrict__ bias,
                        int M, int N, int ldc){
    int i = blockIdx.x*blockDim.x + threadIdx.x;
    if (i >= M*N) return;
    int r = i / N, c = i - r*N;
    C[(size_t)r*ldc + c] = bias[c];
}
__global__ void k_relu(float* __restrict__ C, int total){
    int i = blockIdx.x*blockDim.x + threadIdx.x;
    if (i < total) C[i] = fmaxf(C[i], 0.f);
}

// ================= target branch =================
__global__ void k_buildM(const float* __restrict__ emb){
    int i = blockIdx.x*blockDim.x + threadIdx.x;
    if (i >= 128*KP_U) return;
    int p = i / KP_U, kidx = i - p*KP_U;
    float val = 0.f;
    if (p < CONVOUT && kidx < UCOLS){
        int v = kidx >> 3, kk = kidx & 7;
        val = emb[v*EMB + p + kk];
    }
    __nv_bfloat16 h, l; split_bf16(val, h, l);
    d_Mmh[i] = h; d_Mml[i] = l;
}
__global__ void k_transW(const float* __restrict__ W){
    int i = blockIdx.x*blockDim.x + threadIdx.x;
    if (i >= NFILT*SEQL*8) return;
    int o = i / (SEQL*8), c = (i >> 3) % SEQL, k = i & 7;
    d_Wt[c*(NFILT*8) + o*8 + k] = W[i];
}
__global__ void k_buildU(const int* __restrict__ target){
    __shared__ float sU[USZ];
    __shared__ int   st[SEQL];
    int g = blockIdx.x;
    for (int i = threadIdx.x; i < USZ;  i += blockDim.x) sU[i] = 0.f;
    for (int i = threadIdx.x; i < SEQL; i += blockDim.x) st[i] = target[g*SEQL + i];
    __syncthreads();
    int o = threadIdx.x >> 3, k = threadIdx.x & 7;
    for (int c = 0; c < SEQL; c++){
        int v = st[c];
        sU[o*UCOLS + v*8 + k] += d_Wt[c*(NFILT*8) + threadIdx.x];
    }
    __syncthreads();
    for (int i = threadIdx.x; i < NFILT*KP_U; i += blockDim.x){
        int oo = i / KP_U, col = i - oo*KP_U;
        float v = (col < UCOLS) ? sU[oo*UCOLS + col] : 0.f;
        __nv_bfloat16 h, l; split_bf16(v, h, l);
        size_t idx = ((size_t)g*NFILT + oo)*KP_U + col;
        d_Uh[idx] = h; d_Ul[idx] = l;
    }
}
__global__ void k_fcxtb2(const float* __restrict__ fcxt_W,
                         const float* __restrict__ fcxt_b,
                         const float* __restrict__ conv_b){
    int j = blockIdx.x;
    __shared__ float red[128];
    float s = 0.f;
    for (int r = threadIdx.x; r < NFILT*CONVOUT; r += blockDim.x)
        s += conv_b[r / CONVOUT] * fcxt_W[(size_t)r*128 + j];
    red[threadIdx.x] = s; __syncthreads();
    for (int o = 64; o > 0; o >>= 1){
        if (threadIdx.x < o) red[threadIdx.x] += red[threadIdx.x + o];
        __syncthreads();
    }
    if (!threadIdx.x) d_fcxtb2[j] = fcxt_b[j] + red[0];
}

// ================= final projection =================
__global__ void k_out(const float* __restrict__ oW, const float* __restrict__ ob,
                      float* __restrict__ out){
    int g    = (blockIdx.x*blockDim.x + threadIdx.x) >> 5;
    int lane = threadIdx.x & 31;
    if (g >= NG) return;
    float s = 0.f;
    for (int k = lane; k < 512; k += 32) s += d_f2[g*512 + k] * oW[k];
    #pragma unroll
    for (int o = 16; o > 0; o >>= 1) s += __shfl_down_sync(~0u, s, o);
    if (!lane) out[g] = s + ob[0];
}

extern "C" void kernel_launch(void* const* d_in, const int* in_sizes, int n_in,
                              void* d_out, int out_size){
    const float* x        = (const float*)d_in[0];
    const int*   ei       = (const int*)  d_in[1];
    const int*   batch    = (const int*)  d_in[2];
    const int*   target   = (const int*)  d_in[3];
    const float* gat_W    = (const float*)d_in[4];
    const float* gat_asrc = (const float*)d_in[5];
    const float* gat_adst = (const float*)d_in[6];
    const float* gat_b    = (const float*)d_in[7];
    const float* gcn_W    = (const float*)d_in[8];
    const float* gcn_b    = (const float*)d_in[9];
    const float* fcg1_W   = (const float*)d_in[10];
    const float* fcg1_b   = (const float*)d_in[11];
    const float* fcg2_W   = (const float*)d_in[12];
    const float* fcg2_b   = (const float*)d_in[13];
    const float* emb      = (const float*)d_in[14];
    const float* conv_W   = (const float*)d_in[15];
    const float* conv_b   = (const float*)d_in[16];
    const float* fcxt_W   = (const float*)d_in[17];
    const float* fcxt_b   = (const float*)d_in[18];
    const float* fc1_W    = (const float*)d_in[19];
    const float* fc1_b    = (const float*)d_in[20];
    const float* fc2_W    = (const float*)d_in[21];
    const float* fc2_b    = (const float*)d_in[22];
    const float* out_W    = (const float*)d_in[23];
    const float* out_b    = (const float*)d_in[24];

    float *p_h, *p_h2, *p_xg1, *p_xc, *p_conv, *p_f1, *p_f2, *p_fcxtb2;
    __nv_bfloat16 *p_xh, *p_xl, *p_x1h, *p_x1l, *p_gWh, *p_gWl, *p_cWh, *p_cWl;
    __nv_bfloat16 *p_poolh, *p_pooll, *p_fWh, *p_fWl, *p_Uh, *p_Ul, *p_Mmh, *p_Mml;
    cudaGetSymbolAddress((void**)&p_h,    d_h);
    cudaGetSymbolAddress((void**)&p_h2,   d_h2);
    cudaGetSymbolAddress((void**)&p_xg1,  d_xg1);
    cudaGetSymbolAddress((void**)&p_xc,   d_xc);
    cudaGetSymbolAddress((void**)&p_conv, d_conv);
    cudaGetSymbolAddress((void**)&p_f1,   d_f1);
    cudaGetSymbolAddress((void**)&p_f2,   d_f2);
    cudaGetSymbolAddress((void**)&p_fcxtb2, d_fcxtb2);
    cudaGetSymbolAddress((void**)&p_xh,  d_xh);
    cudaGetSymbolAddress((void**)&p_xl,  d_xl);
    cudaGetSymbolAddress((void**)&p_x1h, d_x1h);
    cudaGetSymbolAddress((void**)&p_x1l, d_x1l);
    cudaGetSymbolAddress((void**)&p_gWh, d_gWh);
    cudaGetSymbolAddress((void**)&p_gWl, d_gWl);
    cudaGetSymbolAddress((void**)&p_cWh, d_cWh);
    cudaGetSymbolAddress((void**)&p_cWl, d_cWl);
    cudaGetSymbolAddress((void**)&p_poolh, d_poolh);
    cudaGetSymbolAddress((void**)&p_pooll, d_pooll);
    cudaGetSymbolAddress((void**)&p_fWh, d_fWh);
    cudaGetSymbolAddress((void**)&p_fWl, d_fWl);
    cudaGetSymbolAddress((void**)&p_Uh, d_Uh);
    cudaGetSymbolAddress((void**)&p_Ul, d_Ul);
    cudaGetSymbolAddress((void**)&p_Mmh, d_Mmh);
    cudaGetSymbolAddress((void**)&p_Mml, d_Mml);

    cudaFuncSetAttribute(gemm_mma, cudaFuncAttributeMaxDynamicSharedMemorySize, 2*STG);

    // launches 0..2: splits (launch 3 = gemm_mma GAT lands under ncu -s 5)
    k_split_x<<<(NN*KP_GAT + 255)/256, 256>>>(x);
    k_splitB<<<(NPADG*KP_GAT + 255)/256, 256>>>(gat_W, p_gWh, p_gWl, NF, HF, KP_GAT, NPADG);
    k_splitB<<<(NPADG*KP_GCN + 255)/256, 256>>>(gcn_W, p_cWh, p_cWl, HF, HF, KP_GCN, NPADG);

    // launch 3: GAT transform (profiled)
    {
        dim3 grid(NPADG/64, (NN + 127)/128);
        gemm_mma<<<grid, 256, 2*STG>>>(p_xh, p_xl, p_gWh, p_gWl, p_h, NN, HF, KP_GAT, HF, nullptr, 0, NPADG);
    }

    // CSR build
    k_deg_init<<<(NN + 255)/256, 256>>>();
    k_count<<<(NE + 255)/256, 256>>>(ei);
    k_scan<<<1, 1024>>>();
    k_fill<<<(NEP + 255)/256, 256>>>(ei);
    k_dinv<<<(NN + 255)/256, 256>>>();

    // remaining prep
    k_splitB<<<(NP_FCG1*KP_POOL + 255)/256, 256>>>(fcg1_W, p_fWh, p_fWl, 2*HF, 1024, KP_POOL, NP_FCG1);
    k_buildM<<<(128*KP_U + 255)/256, 256>>>(emb);
    k_transW<<<(NFILT*SEQL*8 + 255)/256, 256>>>(conv_W);

    // GAT attention + aggregation
    k_attn_coef<<<(NN*NH*32 + 255)/256, 256>>>(gat_asrc, gat_adst);
    k_gat_soft<<<(NN*32 + 255)/256, 256>>>();
    k_gat_agg<<<NN, 256>>>(gat_b);

    // GCN
    {
        dim3 grid(NPADG/64, (NN + 127)/128);
        gemm_mma<<<grid, 256, 2*STG>>>(p_x1h, p_x1l, p_cWh, p_cWl, p_h2, NN, HF, KP_GCN, HF, nullptr, 0, NPADG);
    }
    k_gcn_agg<<<NN, 256>>>(gcn_b);

    // pooling + graph head
    k_start<<<3, 256>>>(batch);
    k_pool<<<NG, 256>>>();
    {   // fcg1 on tensor cores, fused bias+relu
        dim3 grid(1024/64, NG/128);
        gemm_mma<<<grid, 256, 2*STG>>>(p_poolh, p_pooll, p_fWh, p_fWl, p_xg1, NG, 1024, KP_POOL, 1024, fcg1_b, 1, NP_FCG1);
    }
    {   // fcg2 split-K
        k_binit<<<(NG*128 + 255)/256, 256>>>(p_xc, fcg2_b, NG, 128, 256);
        dim3 grid(2, 8, 4);
        gemm2_kernel<<<grid, 256>>>(p_xg1, fcg2_W, nullptr, p_xc, NG, 128, 1024, 256, 0);
    }

    // target branch
    k_buildU<<<NG, 256>>>(target);
    {   // conv GEMM on tensor cores
        dim3 grid(2, (NG*NFILT)/128);
        gemm_mma<<<grid, 256, 2*STG>>>(p_Uh, p_Ul, p_Mmh, p_Mml, p_conv, NG*NFILT, CONVOUT, KP_U, CONVOUT, nullptr, 0, 128);
    }
    k_fcxtb2<<<128, 128>>>(fcxt_W, fcxt_b, conv_b);
    {   // fcxt split-K
        k_binit<<<(NG*128 + 255)/256, 256>>>(p_xc + 128, p_fcxtb2, NG, 128, 256);
        dim3 grid(2, 8, 4);
        gemm2_kernel<<<grid, 256>>>(p_conv, fcxt_W, nullptr, p_xc + 128, NG, 128, NFILT*CONVOUT, 256, 0);
    }

    // fusion head
    {
        dim3 grid(16, 8, 1);
        gemm2_kernel<<<grid, 256>>>(p_xc, fc1_W, fc1_b, p_f1, NG, 1024, 256, 1024, 1);
    }
    {
        k_binit<<<(NG*512 + 255)/256, 256>>>(p_f2, fc2_b, NG, 512, 512);
        dim3 grid(8, 8, 2);
        gemm2_kernel<<<grid, 256>>>(p_f1, fc2_W, nullptr, p_f2, NG, 512, 1024, 512, 0);
        k_relu<<<(NG*512 + 255)/256, 256>>>(p_f2, NG*512);
    }
    k_out<<<(NG*32 + 255)/256, 256>>>(out_W, out_b, (float*)d_out);
}

// round 9
// speedup vs baseline: 3.0905x; 1.0154x over previous
#include <cuda_runtime.h>
#include <cuda_bf16.h>
#include <math.h>
#include <stdint.h>

#define NN      25000
#define NE      100000
#define NEP     125000
#define NG      512
#define NH      10
#define NF      78
#define HF      780
#define SEQL    1000
#define EMB     128
#define NFILT   32
#define CONVOUT 121
#define VOCAB   26
#define UCOLS   (VOCAB*8)        // 208
#define USZ     (NFILT*UCOLS)

#define KP_GAT  128
#define KP_GCN  832
#define NPADG   832
#define KP_POOL 1600
#define NP_FCG1 1024
#define KP_U    256

// ---------------- device scratch ----------------
__device__ float d_h[NN*HF];
__device__ float d_asrc[NN*NH];
__device__ float d_adst[NN*NH];
__device__ float d_wsrc[NF*NH];
__device__ float d_wdst[NF*NH];
__device__ float d_invden[NN*NH];
__device__ float d_alpha[(size_t)NEP*NH];
__device__ float d_h2[NN*HF];
__device__ float d_x2[NN*HF];
__device__ float d_dinv[NN];
__device__ int   d_deg[NN];
__device__ int   d_roff[NN+1];
__device__ int   d_rpos[NN];
__device__ int   d_csrc[NEP];
__device__ int   d_start[NG+1];
__device__ float d_xg1[NG*1024];
__device__ float d_Wt[SEQL*NFILT*8];
__device__ float d_conv[(size_t)NG*NFILT*CONVOUT];
__device__ float d_fcxtb2[128];
__device__ float d_xc[NG*256];
__device__ float d_f1[NG*1024];
__device__ float d_f2[NG*512];
__device__ __nv_bfloat16 d_xh[(size_t)NN*KP_GAT];
__device__ __nv_bfloat16 d_xl[(size_t)NN*KP_GAT];
__device__ __nv_bfloat16 d_x1h[(size_t)NN*KP_GCN];
__device__ __nv_bfloat16 d_x1l[(size_t)NN*KP_GCN];
__device__ __nv_bfloat16 d_gWh[(size_t)NPADG*KP_GAT];
__device__ __nv_bfloat16 d_gWl[(size_t)NPADG*KP_GAT];
__device__ __nv_bfloat16 d_cWh[(size_t)NPADG*KP_GCN];
__device__ __nv_bfloat16 d_cWl[(size_t)NPADG*KP_GCN];
__device__ __nv_bfloat16 d_poolh[(size_t)NG*KP_POOL];
__device__ __nv_bfloat16 d_pooll[(size_t)NG*KP_POOL];
__device__ __nv_bfloat16 d_fWh[(size_t)NP_FCG1*KP_POOL];
__device__ __nv_bfloat16 d_fWl[(size_t)NP_FCG1*KP_POOL];
__device__ __nv_bfloat16 d_Uh[(size_t)NG*NFILT*KP_U];
__device__ __nv_bfloat16 d_Ul[(size_t)NG*NFILT*KP_U];
__device__ __nv_bfloat16 d_Mmh[128*KP_U];
__device__ __nv_bfloat16 d_Mml[128*KP_U];

// ================= helpers =================
__device__ __forceinline__ uint32_t smem_u32(const void* p){
    uint32_t a;
    asm("{ .reg .u64 t; cvta.to.shared.u64 t, %1; cvt.u32.u64 %0, t; }" : "=r"(a) : "l"(p));
    return a;
}
#define LDMX4(r, a) \
    asm volatile("ldmatrix.sync.aligned.m8n8.x4.shared.b16 {%0,%1,%2,%3}, [%4];" \
        : "=r"((r)[0]), "=r"((r)[1]), "=r"((r)[2]), "=r"((r)[3]) : "r"(a))
#define MMA16816(d, a, b0, b1) \
    asm volatile("mma.sync.aligned.m16n8k16.row.col.f32.bf16.bf16.f32 " \
        "{%0,%1,%2,%3}, {%4,%5,%6,%7}, {%8,%9}, {%0,%1,%2,%3};" \
        : "+f"((d)[0]), "+f"((d)[1]), "+f"((d)[2]), "+f"((d)[3]) \
        : "r"((a)[0]), "r"((a)[1]), "r"((a)[2]), "r"((a)[3]), "r"(b0), "r"(b1))
#define CPA_COMMIT() asm volatile("cp.async.commit_group;" ::: "memory")
#define CPA_WAIT0()  asm volatile("cp.async.wait_group 0;" ::: "memory")

__device__ __forceinline__ void cpa16(uint32_t dst, const void* src, int sz){
    size_t g;
    asm("cvta.to.global.u64 %0, %1;" : "=l"(g) : "l"(src));
    asm volatile("cp.async.cg.shared.global [%0], [%1], 16, %2;" :: "r"(dst), "l"(g), "r"(sz) : "memory");
}
__device__ __forceinline__ void split_bf16(float v, __nv_bfloat16& h, __nv_bfloat16& l){
    h = __float2bfloat16(v);
    l = __float2bfloat16(v - __bfloat162float(h));
}

// ================= mma.sync split-bf16 GEMM =================
#define GPITCH 72
#define ATILEB 18432
#define BTILEB 9216
#define STG    55296

__device__ __forceinline__ void ld_tileA(uint32_t sdst, const __nv_bfloat16* G,
                                         int row0, int k0, int KP, int rlim, int tid){
    #pragma unroll
    for (int i = 0; i < 4; i++){
        int v = tid + i*256;
        int r = v >> 3, cq = v & 7;
        int row = row0 + r;
        int sz = (row < rlim) ? 16 : 0;
        cpa16(sdst + r*144 + cq*16, G + (size_t)(sz ? row : row0)*KP + k0 + cq*8, sz);
    }
}
__device__ __forceinline__ void ld_tileB(uint32_t sdst, const __nv_bfloat16* G,
                                         int row0, int k0, int KP, int rlim, int tid){
    #pragma unroll
    for (int i = 0; i < 2; i++){
        int v = tid + i*256;
        int r = v >> 3, cq = v & 7;
        int row = row0 + r;
        int sz = (row < rlim) ? 16 : 0;
        cpa16(sdst + r*144 + cq*16, G + (size_t)(sz ? row : row0)*KP + k0 + cq*8, sz);
    }
}

__global__ void __launch_bounds__(256, 2) gemm_mma(
    const __nv_bfloat16* __restrict__ Ah, const __nv_bfloat16* __restrict__ Al,
    const __nv_bfloat16* __restrict__ Bh, const __nv_bfloat16* __restrict__ Bl,
    float* __restrict__ C, int M, int Nout, int KP, int ldc,
    const float* __restrict__ bias, int act, int Brows)
{
    extern __shared__ char sm[];
    uint32_t sb = smem_u32(sm);
    int tid = threadIdx.x;
    int m0 = blockIdx.y*128, n0 = blockIdx.x*64;
    int w = tid >> 5, lane = tid & 31;
    int wm = (w >> 1) * 32;
    int wn = (w & 1) * 32;
    int NC = KP / 64;

    float acc[2][4][4];
    #pragma unroll
    for (int i=0;i<2;i++)
        #pragma unroll
        for (int j=0;j<4;j++)
            #pragma unroll
            for (int q=0;q<4;q++) acc[i][j][q] = 0.f;

    int a_row = (lane & 15);
    int a_kc  = (lane >> 4) * 8;
    int b_row = ((lane >> 4) * 8) + (lane & 7);
    int b_kc  = ((lane >> 3) & 1) * 8;

    ld_tileA(sb + 0,                 Ah, m0, 0, KP, M, tid);
    ld_tileA(sb + ATILEB,            Al, m0, 0, KP, M, tid);
    ld_tileB(sb + 2*ATILEB,          Bh, n0, 0, KP, Brows, tid);
    ld_tileB(sb + 2*ATILEB + BTILEB, Bl, n0, 0, KP, Brows, tid);
    CPA_COMMIT();

    uint32_t ah[2][2][4], al[2][2][4], bh[2][2][4], bl[2][2][4];

    for (int ci = 0; ci < NC; ci++){
        int b = ci & 1;
        uint32_t st = sb + b*STG;
        CPA_WAIT0();
        __syncthreads();
        if (ci + 1 < NC){
            uint32_t s2 = sb + (1-b)*STG;
            int k0n = (ci+1)*64;
            ld_tileA(s2 + 0,                 Ah, m0, k0n, KP, M, tid);
            ld_tileA(s2 + ATILEB,            Al, m0, k0n, KP, M, tid);
            ld_tileB(s2 + 2*ATILEB,          Bh, n0, k0n, KP, Brows, tid);
            ld_tileB(s2 + 2*ATILEB + BTILEB, Bl, n0, k0n, KP, Brows, tid);
            CPA_COMMIT();
        }
        uint32_t bAh = st, bAl = st + ATILEB, bBh = st + 2*ATILEB, bBl = st + 2*ATILEB + BTILEB;

        #define LOADF(buf, kk) do{ \
            _Pragma("unroll") \
            for (int mt = 0; mt < 2; mt++){ \
                uint32_t off = (uint32_t)((wm + mt*16 + a_row)*GPITCH + (kk) + a_kc) * 2; \
                LDMX4(ah[buf][mt], bAh + off); \
                LDMX4(al[buf][mt], bAl + off); \
            } \
            _Pragma("unroll") \
            for (int nt = 0; nt < 2; nt++){ \
                uint32_t offb = (uint32_t)((wn + nt*16 + b_row)*GPITCH + (kk) + b_kc) * 2; \
                LDMX4(bh[buf][nt], bBh + offb); \
                LDMX4(bl[buf][nt], bBl + offb); \
            } \
        }while(0)

        LOADF(0, 0);
        #pragma unroll
        for (int kks = 0; kks < 4; kks++){
            int cur = kks & 1;
            if (kks < 3){
                int nxt = 1 - cur;
                LOADF(nxt, (kks+1)*16);
            }
            // term-major ordering: same-acc MMAs spaced 8 apart
            #pragma unroll
            for (int nt2 = 0; nt2 < 2; nt2++)
                #pragma unroll
                for (int mt = 0; mt < 2; mt++){
                    MMA16816(acc[mt][nt2*2],   ah[cur][mt], bh[cur][nt2][0], bh[cur][nt2][1]);
                    MMA16816(acc[mt][nt2*2+1], ah[cur][mt], bh[cur][nt2][2], bh[cur][nt2][3]);
                }
            #pragma unroll
            for (int nt2 = 0; nt2 < 2; nt2++)
                #pragma unroll
                for (int mt = 0; mt < 2; mt++){
                    MMA16816(acc[mt][nt2*2],   ah[cur][mt], bl[cur][nt2][0], bl[cur][nt2][1]);
                    MMA16816(acc[mt][nt2*2+1], ah[cur][mt], bl[cur][nt2][2], bl[cur][nt2][3]);
                }
            #pragma unroll
            for (int nt2 = 0; nt2 < 2; nt2++)
                #pragma unroll
                for (int mt = 0; mt < 2; mt++){
                    MMA16816(acc[mt][nt2*2],   al[cur][mt], bh[cur][nt2][0], bh[cur][nt2][1]);
                    MMA16816(acc[mt][nt2*2+1], al[cur][mt], bh[cur][nt2][2], bh[cur][nt2][3]);
                }
        }
        #undef LOADF
    }
    #pragma unroll
    for (int mt = 0; mt < 2; mt++){
        int r0 = m0 + wm + mt*16 + (lane >> 2);
        #pragma unroll
        for (int nt = 0; nt < 4; nt++){
            int c = n0 + wn + nt*8 + (lane & 3)*2;
            #pragma unroll
            for (int half = 0; half < 2; half++){
                int rr = r0 + half*8;
                if (rr >= M) continue;
                #pragma unroll
                for (int q = 0; q < 2; q++){
                    int cc = c + q;
                    if (cc >= Nout) continue;
                    float v = acc[mt][nt][half*2 + q];
                    if (bias) v += bias[cc];
                    if (act)  v = fmaxf(v, 0.f);
                    C[(size_t)rr*ldc + cc] = v;
                }
            }
        }
    }
}

// ================= split-prep =================
__global__ void k_split_x(const float* __restrict__ x){
    int i = blockIdx.x*blockDim.x + threadIdx.x;
    if (i >= NN*KP_GAT) return;
    int r = i >> 7, k = i & (KP_GAT-1);
    float v = (k < NF) ? x[r*NF + k] : 0.f;
    split_bf16(v, d_xh[i], d_xl[i]);
}
__global__ void k_splitB(const float* __restrict__ W, __nv_bfloat16* __restrict__ bh,
                         __nv_bfloat16* __restrict__ bl, int K, int N, int KP, int NR){
    int i = blockIdx.x*blockDim.x + threadIdx.x;
    if (i >= NR*KP) return;
    int n = i / KP, k = i - n*KP;
    float v = (k < K && n < N) ? W[(size_t)k*N + n] : 0.f;
    __nv_bfloat16 h, l; split_bf16(v, h, l);
    bh[i] = h; bl[i] = l;
}

// ================= CSR build =================
__global__ void k_deg_init(){
    int n = blockIdx.x*blockDim.x + threadIdx.x;
    if (n < NN) d_deg[n] = 1;
}
__global__ void k_count(const int* __restrict__ ei){
    int e = blockIdx.x*blockDim.x + threadIdx.x;
    if (e < NE) atomicAdd(&d_deg[ei[NE+e]], 1);
}
__global__ void k_scan(){
    __shared__ int part[1024];
    int t = threadIdx.x;
    const int PER = 25;
    int base = t*PER, sum = 0;
    for (int i = 0; i < PER; i++){ int idx = base+i; if (idx < NN) sum += d_deg[idx]; }
    part[t] = sum; __syncthreads();
    for (int off = 1; off < 1024; off <<= 1){
        int v = (t >= off) ? part[t-off] : 0; __syncthreads();
        part[t] += v; __syncthreads();
    }
    int run = part[t] - sum;
    for (int i = 0; i < PER; i++){
        int idx = base+i;
        if (idx < NN){ d_roff[idx] = run; d_rpos[idx] = run; run += d_deg[idx]; }
    }
    if (t == 1023) d_roff[NN] = NEP;
}
__global__ void k_fill(const int* __restrict__ ei){
    int e = blockIdx.x*blockDim.x + threadIdx.x;
    if (e >= NEP) return;
    int s, d;
    if (e < NE){ s = ei[e]; d = ei[NE+e]; } else { s = d = e - NE; }
    int pos = atomicAdd(&d_rpos[d], 1);
    d_csrc[pos] = s;
}
__global__ void k_dinv(){
    int n = blockIdx.x*blockDim.x + threadIdx.x;
    if (n < NN) d_dinv[n] = rsqrtf((float)d_deg[n]);
}

// ================= GAT attention (folded) =================
// w_src[f_in, hh] = sum_f gat_W[f_in, hh*NF+f] * att_src[hh, f]   (same for dst)
__global__ void k_attw(const float* __restrict__ gat_W,
                       const float* __restrict__ att_src,
                       const float* __restrict__ att_dst){
    int wid  = (blockIdx.x*blockDim.x + threadIdx.x) >> 5;
    int lane = threadIdx.x & 31;
    if (wid >= 2*NF*NH) return;
    int which = (wid >= NF*NH);
    int r = wid - which*NF*NH;
    int f_in = r / NH, hh = r - f_in*NH;
    const float* att = which ? att_dst : att_src;
    float s = 0.f;
    for (int f = lane; f < NF; f += 32)
        s += gat_W[(size_t)f_in*HF + hh*NF + f] * att[hh*NF + f];
    #pragma unroll
    for (int o = 16; o > 0; o >>= 1) s += __shfl_down_sync(~0u, s, o);
    if (!lane){
        if (which) d_wdst[f_in*NH + hh] = s;
        else       d_wsrc[f_in*NH + hh] = s;
    }
}
// asrc/adst = x @ w  (thread per node, weights staged in smem)
__global__ void k_asrcdst(const float* __restrict__ x){
    __shared__ float ws[NF*NH], wd[NF*NH];
    int tid = threadIdx.x;
    for (int i = tid; i < NF*NH; i += 256){ ws[i] = d_wsrc[i]; wd[i] = d_wdst[i]; }
    __syncthreads();
    int n = blockIdx.x*256 + tid;
    if (n >= NN) return;
    float as[NH], ad[NH];
    #pragma unroll
    for (int hh = 0; hh < NH; hh++){ as[hh] = 0.f; ad[hh] = 0.f; }
    const float* xr = x + (size_t)n*NF;
    for (int f = 0; f < NF; f++){
        float xv = xr[f];
        #pragma unroll
        for (int hh = 0; hh < NH; hh++){
            as[hh] += xv * ws[f*NH + hh];
            ad[hh] += xv * wd[f*NH + hh];
        }
    }
    #pragma unroll
    for (int hh = 0; hh < NH; hh++){
        d_asrc[n*NH + hh] = as[hh];
        d_adst[n*NH + hh] = ad[hh];
    }
}

__global__ void k_gat_soft(){
    int w    = (blockIdx.x*blockDim.x + threadIdx.x) >> 5;
    int lane = threadIdx.x & 31;
    if (w >= NN || lane >= NH) return;
    int s0 = d_roff[w], s1 = d_roff[w+1];
    float ad = d_adst[w*NH + lane];
    float mx = -1e30f;
    for (int p = s0; p < s1; p++){
        float a = d_asrc[d_csrc[p]*NH + lane] + ad;
        a = a > 0.f ? a : 0.2f*a;
        mx = fmaxf(mx, a);
    }
    float sum = 0.f;
    for (int p = s0; p < s1; p++){
        float a = d_asrc[d_csrc[p]*NH + lane] + ad;
        a = a > 0.f ? a : 0.2f*a;
        float e = expf(a - mx);
        d_alpha[(size_t)p*NH + lane] = e;
        sum += e;
    }
    d_invden[w*NH + lane] = 1.f / (sum + 1e-16f);
}
__global__ void k_gat_agg(const float* __restrict__ gat_b){
    int n = blockIdx.x;
    int tid = threadIdx.x;
    __shared__ float invd[NH];
    __shared__ int   csrc_c[25];
    __shared__ float coef_c[25][NH];
    if (tid < NH) invd[tid] = d_invden[n*NH + tid];
    __syncthreads();
    int s0 = d_roff[n], s1 = d_roff[n+1];
    float4 acc = make_float4(0.f,0.f,0.f,0.f);
    int c0 = tid*4;
    int h0 = c0/NF, h1 = (c0+1)/NF, h2 = (c0+2)/NF, h3 = (c0+3)/NF;
    for (int base = s0; base < s1; base += 25){
        int cnt = s1 - base; if (cnt > 25) cnt = 25;
        if (tid < cnt) csrc_c[tid] = d_csrc[base + tid];
        if (tid < cnt*NH){
            int p = tid / NH, hh = tid - p*NH;
            coef_c[p][hh] = d_alpha[(size_t)(base+p)*NH + hh] * invd[hh];
        }
        __syncthreads();
        if (tid < 195){
            #pragma unroll 2
            for (int j = 0; j < cnt; j++){
                float4 v = *(const float4*)(d_h + (size_t)csrc_c[j]*HF + c0);
                acc.x += coef_c[j][h0]*v.x;
                acc.y += coef_c[j][h1]*v.y;
                acc.z += coef_c[j][h2]*v.z;
                acc.w += coef_c[j][h3]*v.w;
            }
        }
        __syncthreads();
    }
    if (tid < 195){
        float4 bb = *(const float4*)(gat_b + c0);
        float r[4] = { fmaxf(acc.x + bb.x, 0.f), fmaxf(acc.y + bb.y, 0.f),
                       fmaxf(acc.z + bb.z, 0.f), fmaxf(acc.w + bb.w, 0.f) };
        #pragma unroll
        for (int q = 0; q < 4; q++){
            __nv_bfloat16 h, l; split_bf16(r[q], h, l);
            d_x1h[(size_t)n*KP_GCN + c0 + q] = h;
            d_x1l[(size_t)n*KP_GCN + c0 + q] = l;
        }
    } else if (tid < 208){
        #pragma unroll
        for (int q = 0; q < 4; q++){
            d_x1h[(size_t)n*KP_GCN + c0 + q] = __float2bfloat16(0.f);
            d_x1l[(size_t)n*KP_GCN + c0 + q] = __float2bfloat16(0.f);
        }
    }
}

// ================= GCN aggregate =================
__global__ void k_gcn_agg(const float* __restrict__ gcn_b){
    int n = blockIdx.x;
    int tid = threadIdx.x;
    __shared__ int   csrc_c[64];
    __shared__ float coef_c[64];
    int s0 = d_roff[n], s1 = d_roff[n+1];
    float dn = d_dinv[n];
    float4 acc = make_float4(0.f,0.f,0.f,0.f);
    int c0 = tid*4;
    for (int base = s0; base < s1; base += 64){
        int cnt = s1 - base; if (cnt > 64) cnt = 64;
        if (tid < cnt){
            int s = d_csrc[base + tid];
            csrc_c[tid] = s;
            coef_c[tid] = dn * d_dinv[s];
        }
        __syncthreads();
        if (tid < 195){
            #pragma unroll 2
            for (int j = 0; j < cnt; j++){
                float4 v = *(const float4*)(d_h2 + (size_t)csrc_c[j]*HF + c0);
                float cf = coef_c[j];
                acc.x += cf*v.x; acc.y += cf*v.y; acc.z += cf*v.z; acc.w += cf*v.w;
            }
        }
        __syncthreads();
    }
    if (tid < 195){
        float4 bb = *(const float4*)(gcn_b + c0);
        float4 r = make_float4(fmaxf(acc.x + bb.x, 0.f), fmaxf(acc.y + bb.y, 0.f),
                               fmaxf(acc.z + bb.z, 0.f), fmaxf(acc.w + bb.w, 0.f));
        *(float4*)(d_x2 + (size_t)n*HF + c0) = r;
    }
}

// ================= pooling =================
__global__ void k_start(const int* __restrict__ batch){
    int g = blockIdx.x*blockDim.x + threadIdx.x;
    if (g > NG) return;
    if (g == NG){ d_start[NG] = NN; return; }
    int lo = 0, hi = NN;
    while (lo < hi){ int mid = (lo+hi) >> 1; if (batch[mid] < g) lo = mid+1; else hi = mid; }
    d_start[g] = lo;
}
__global__ void k_pool(){
    int g = blockIdx.x;
    int s = d_start[g], e = d_start[g+1];
    int cnt = e - s;
    size_t rb = (size_t)g*KP_POOL;
    for (int c = threadIdx.x; c < HF; c += blockDim.x){
        float mx = -1e30f, sm = 0.f;
        #pragma unroll 4
        for (int n = s; n < e; n++){
            float v = d_x2[(size_t)n*HF + c];
            mx = fmaxf(mx, v); sm += v;
        }
        float vmax = (cnt > 0) ? mx : 0.f;
        float vmean = sm / fmaxf((float)cnt, 1.f);
        __nv_bfloat16 h, l;
        split_bf16(vmax, h, l);  d_poolh[rb + c] = h;      d_pooll[rb + c] = l;
        split_bf16(vmean, h, l); d_poolh[rb + HF + c] = h; d_pooll[rb + HF + c] = l;
    }
    if (threadIdx.x < KP_POOL - 2*HF){
        d_poolh[rb + 2*HF + threadIdx.x] = __float2bfloat16(0.f);
        d_pooll[rb + 2*HF + threadIdx.x] = __float2bfloat16(0.f);
    }
}

// ================= small GEMM (f32x2, split-K capable) =================
__global__ void gemm2_kernel(const float* __restrict__ A, const float* __restrict__ B,
                             const float* __restrict__ bias, float* __restrict__ C,
                             int M, int N, int K, int ldc, int act)
{
    __shared__ float As[16*64];
    __shared__ float Bs[16*64];
    int tid = threadIdx.x;
    int row0 = blockIdx.y*64, col0 = blockIdx.x*64;
    int tx = tid & 15, ty = tid >> 4;
    int Z = gridDim.z, z = blockIdx.z;
    int T = (K + 15) / 16;
    int kc0 = (int)((long long)T * z / Z), kc1 = (int)((long long)T * (z+1) / Z);
    unsigned long long acc2[4][2];
    #pragma unroll
    for (int i=0;i<4;i++){ acc2[i][0] = 0ull; acc2[i][1] = 0ull; }
    for (int kc = kc0; kc < kc1; kc++){
        int k0 = kc*16;
        #pragma unroll
        for (int i=0;i<4;i++){
            int l = tid + i*256;
            int m = l >> 4, kk = l & 15;
            int r = row0 + m, kg = k0 + kk;
            As[kk*64+m] = (r < M && kg < K) ? A[(size_t)r*K + kg] : 0.f;
        }
        #pragma unroll
        for (int i=0;i<4;i++){
            int l = tid + i*256;
            int kk = l >> 6, n = l & 63;
            int kg = k0 + kk, c = col0 + n;
            Bs[kk*64+n] = (kg < K && c < N) ? B[(size_t)kg*N + c] : 0.f;
        }
        __syncthreads();
        #pragma unroll
        for (int kk=0; kk<16; kk++){
            float ra[4];
            #pragma unroll
            for (int i=0;i<4;i++) ra[i] = As[kk*64 + ty*4 + i];
            unsigned long long rb0 = *(const unsigned long long*)&Bs[kk*64 + tx*4];
            unsigned long long rb1 = *(const unsigned long long*)&Bs[kk*64 + tx*4 + 2];
            #pragma unroll
            for (int i=0;i<4;i++){
                unsigned long long ad;
                asm("mov.b64 %0, {%1, %1};" : "=l"(ad) : "r"(__float_as_uint(ra[i])));
                asm("fma.rn.f32x2 %0, %1, %2, %0;" : "+l"(acc2[i][0]) : "l"(ad), "l"(rb0));
                asm("fma.rn.f32x2 %0, %1, %2, %0;" : "+l"(acc2[i][1]) : "l"(ad), "l"(rb1));
            }
        }
        __syncthreads();
    }
    #pragma unroll
    for (int i=0;i<4;i++){
        int r = row0 + ty*4 + i;
        if (r >= M) continue;
        #pragma unroll
        for (int jp=0;jp<2;jp++){
            unsigned int lo, hi;
            asm("mov.b64 {%0, %1}, %2;" : "=r"(lo), "=r"(hi) : "l"(acc2[i][jp]));
            float vv[2] = { __uint_as_float(lo), __uint_as_float(hi) };
            int c = col0 + tx*4 + jp*2;
            #pragma unroll
            for (int q=0;q<2;q++){
                int cc = c + q;
                if (cc >= N) continue;
                if (Z == 1){
                    float v = vv[q];
                    if (bias) v += bias[cc];
                    if (act)  v = fmaxf(v, 0.f);
                    C[(size_t)r*ldc + cc] = v;
                } else {
                    atomicAdd(&C[(size_t)r*ldc + cc], vv[q]);
                }
            }
        }
    }
}

__global__ void k_binit(float* __restrict__ C, const float* __restrict__ bias,
                        int M, int N, int ldc){
    int i = blockIdx.x*blockDim.x + threadIdx.x;
    if (i >= M*N) return;
    int r = i / N, c = i - r*N;
    C[(size_t)r*ldc + c] = bias[c];
}
__global__ void k_relu(float* __restrict__ C, int total){
    int i = blockIdx.x*blockDim.x + threadIdx.x;
    if (i < total) C[i] = fmaxf(C[i], 0.f);
}

// ================= target branch =================
__global__ void k_buildM(const float* __restrict__ emb){
    int i = blockIdx.x*blockDim.x + threadIdx.x;
    if (i >= 128*KP_U) return;
    int p = i / KP_U, kidx = i - p*KP_U;
    float val = 0.f;
    if (p < CONVOUT && kidx < UCOLS){
        int v = kidx >> 3, kk = kidx & 7;
        val = emb[v*EMB + p + kk];
    }
    __nv_bfloat16 h, l; split_bf16(val, h, l);
    d_Mmh[i] = h; d_Mml[i] = l;
}
__global__ void k_transW(const float* __restrict__ W){
    int i = blockIdx.x*blockDim.x + threadIdx.x;
    if (i >= NFILT*SEQL*8) return;
    int o = i / (SEQL*8), c = (i >> 3) % SEQL, k = i & 7;
    d_Wt[c*(NFILT*8) + o*8 + k] = W[i];
}
__global__ void k_buildU(const int* __restrict__ target){
    __shared__ float sU[USZ];
    __shared__ int   st[SEQL];
    int g = blockIdx.x;
    for (int i = threadIdx.x; i < USZ;  i += blockDim.x) sU[i] = 0.f;
    for (int i = threadIdx.x; i < SEQL; i += blockDim.x) st[i] = target[g*SEQL + i];
    __syncthreads();
    int o = threadIdx.x >> 3, k = threadIdx.x & 7;
    for (int c = 0; c < SEQL; c++){
        int v = st[c];
        sU[o*UCOLS + v*8 + k] += d_Wt[c*(NFILT*8) + threadIdx.x];
    }
    __syncthreads();
    for (int i = threadIdx.x; i < NFILT*KP_U; i += blockDim.x){
        int oo = i / KP_U, col = i - oo*KP_U;
        float v = (col < UCOLS) ? sU[oo*UCOLS + col] : 0.f;
        __nv_bfloat16 h, l; split_bf16(v, h, l);
        size_t idx = ((size_t)g*NFILT + oo)*KP_U + col;
        d_Uh[idx] = h; d_Ul[idx] = l;
    }
}
__global__ void k_fcxtb2(const float* __restrict__ fcxt_W,
                         const float* __restrict__ fcxt_b,
                         const float* __restrict__ conv_b){
    int j = blockIdx.x;
    __shared__ float red[128];
    float s = 0.f;
    for (int r = threadIdx.x; r < NFILT*CONVOUT; r += blockDim.x)
        s += conv_b[r / CONVOUT] * fcxt_W[(size_t)r*128 + j];
    red[threadIdx.x] = s; __syncthreads();
    for (int o = 64; o > 0; o >>= 1){
        if (threadIdx.x < o) red[threadIdx.x] += red[threadIdx.x + o];
        __syncthreads();
    }
    if (!threadIdx.x) d_fcxtb2[j] = fcxt_b[j] + red[0];
}

// ================= final projection =================
__global__ void k_out(const float* __restrict__ oW, const float* __restrict__ ob,
                      float* __restrict__ out){
    int g    = (blockIdx.x*blockDim.x + threadIdx.x) >> 5;
    int lane = threadIdx.x & 31;
    if (g >= NG) return;
    float s = 0.f;
    for (int k = lane; k < 512; k += 32) s += d_f2[g*512 + k] * oW[k];
    #pragma unroll
    for (int o = 16; o > 0; o >>= 1) s += __shfl_down_sync(~0u, s, o);
    if (!lane) out[g] = s + ob[0];
}

extern "C" void kernel_launch(void* const* d_in, const int* in_sizes, int n_in,
                              void* d_out, int out_size){
    const float* x        = (const float*)d_in[0];
    const int*   ei       = (const int*)  d_in[1];
    const int*   batch    = (const int*)  d_in[2];
    const int*   target   = (const int*)  d_in[3];
    const float* gat_W    = (const float*)d_in[4];
    const float* gat_asrc = (const float*)d_in[5];
    const float* gat_adst = (const float*)d_in[6];
    const float* gat_b    = (const float*)d_in[7];
    const float* gcn_W    = (const float*)d_in[8];
    const float* gcn_b    = (const float*)d_in[9];
    const float* fcg1_W   = (const float*)d_in[10];
    const float* fcg1_b   = (const float*)d_in[11];
    const float* fcg2_W   = (const float*)d_in[12];
    const float* fcg2_b   = (const float*)d_in[13];
    const float* emb      = (const float*)d_in[14];
    const float* conv_W   = (const float*)d_in[15];
    const float* conv_b   = (const float*)d_in[16];
    const float* fcxt_W   = (const float*)d_in[17];
    const float* fcxt_b   = (const float*)d_in[18];
    const float* fc1_W    = (const float*)d_in[19];
    const float* fc1_b    = (const float*)d_in[20];
    const float* fc2_W    = (const float*)d_in[21];
    const float* fc2_b    = (const float*)d_in[22];
    const float* out_W    = (const float*)d_in[23];
    const float* out_b    = (const float*)d_in[24];

    float *p_h, *p_h2, *p_xg1, *p_xc, *p_conv, *p_f1, *p_f2, *p_fcxtb2;
    __nv_bfloat16 *p_xh, *p_xl, *p_x1h, *p_x1l, *p_gWh, *p_gWl, *p_cWh, *p_cWl;
    __nv_bfloat16 *p_poolh, *p_pooll, *p_fWh, *p_fWl, *p_Uh, *p_Ul, *p_Mmh, *p_Mml;
    cudaGetSymbolAddress((void**)&p_h,    d_h);
    cudaGetSymbolAddress((void**)&p_h2,   d_h2);
    cudaGetSymbolAddress((void**)&p_xg1,  d_xg1);
    cudaGetSymbolAddress((void**)&p_xc,   d_xc);
    cudaGetSymbolAddress((void**)&p_conv, d_conv);
    cudaGetSymbolAddress((void**)&p_f1,   d_f1);
    cudaGetSymbolAddress((void**)&p_f2,   d_f2);
    cudaGetSymbolAddress((void**)&p_fcxtb2, d_fcxtb2);
    cudaGetSymbolAddress((void**)&p_xh,  d_xh);
    cudaGetSymbolAddress((void**)&p_xl,  d_xl);
    cudaGetSymbolAddress((void**)&p_x1h, d_x1h);
    cudaGetSymbolAddress((void**)&p_x1l, d_x1l);
    cudaGetSymbolAddress((void**)&p_gWh, d_gWh);
    cudaGetSymbolAddress((void**)&p_gWl, d_gWl);
    cudaGetSymbolAddress((void**)&p_cWh, d_cWh);
    cudaGetSymbolAddress((void**)&p_cWl, d_cWl);
    cudaGetSymbolAddress((void**)&p_poolh, d_poolh);
    cudaGetSymbolAddress((void**)&p_pooll, d_pooll);
    cudaGetSymbolAddress((void**)&p_fWh, d_fWh);
    cudaGetSymbolAddress((void**)&p_fWl, d_fWl);
    cudaGetSymbolAddress((void**)&p_Uh, d_Uh);
    cudaGetSymbolAddress((void**)&p_Ul, d_Ul);
    cudaGetSymbolAddress((void**)&p_Mmh, d_Mmh);
    cudaGetSymbolAddress((void**)&p_Mml, d_Mml);

    cudaFuncSetAttribute(gemm_mma, cudaFuncAttributeMaxDynamicSharedMemorySize, 2*STG);

    // launches 0..2: splits (launch 3 = gemm_mma GAT lands under ncu -s 5)
    k_split_x<<<(NN*KP_GAT + 255)/256, 256>>>(x);
    k_splitB<<<(NPADG*KP_GAT + 255)/256, 256>>>(gat_W, p_gWh, p_gWl, NF, HF, KP_GAT, NPADG);
    k_splitB<<<(NPADG*KP_GCN + 255)/256, 256>>>(gcn_W, p_cWh, p_cWl, HF, HF, KP_GCN, NPADG);

    // launch 3: GAT transform (profiled)
    {
        dim3 grid(NPADG/64, (NN + 127)/128);
        gemm_mma<<<grid, 256, 2*STG>>>(p_xh, p_xl, p_gWh, p_gWl, p_h, NN, HF, KP_GAT, HF, nullptr, 0, NPADG);
    }

    // CSR build
    k_deg_init<<<(NN + 255)/256, 256>>>();
    k_count<<<(NE + 255)/256, 256>>>(ei);
    k_scan<<<1, 1024>>>();
    k_fill<<<(NEP + 255)/256, 256>>>(ei);
    k_dinv<<<(NN + 255)/256, 256>>>();

    // remaining prep
    k_splitB<<<(NP_FCG1*KP_POOL + 255)/256, 256>>>(fcg1_W, p_fWh, p_fWl, 2*HF, 1024, KP_POOL, NP_FCG1);
    k_buildM<<<(128*KP_U + 255)/256, 256>>>(emb);
    k_transW<<<(NFILT*SEQL*8 + 255)/256, 256>>>(conv_W);

    // GAT attention (folded) + aggregation
    k_attw<<<(2*NF*NH*32 + 255)/256, 256>>>(gat_W, gat_asrc, gat_adst);
    k_asrcdst<<<(NN + 255)/256, 256>>>(x);
    k_gat_soft<<<(NN*32 + 255)/256, 256>>>();
    k_gat_agg<<<NN, 256>>>(gat_b);

    // GCN
    {
        dim3 grid(NPADG/64, (NN + 127)/128);
        gemm_mma<<<grid, 256, 2*STG>>>(p_x1h, p_x1l, p_cWh, p_cWl, p_h2, NN, HF, KP_GCN, HF, nullptr, 0, NPADG);
    }
    k_gcn_agg<<<NN, 256>>>(gcn_b);

    // pooling + graph head
    k_start<<<3, 256>>>(batch);
    k_pool<<<NG, 256>>>();
    {
        dim3 grid(1024/64, NG/128);
        gemm_mma<<<grid, 256, 2*STG>>>(p_poolh, p_pooll, p_fWh, p_fWl, p_xg1, NG, 1024, KP_POOL, 1024, fcg1_b, 1, NP_FCG1);
    }
    {
        k_binit<<<(NG*128 + 255)/256, 256>>>(p_xc, fcg2_b, NG, 128, 256);
        dim3 grid(2, 8, 4);
        gemm2_kernel<<<grid, 256>>>(p_xg1, fcg2_W, nullptr, p_xc, NG, 128, 1024, 256, 0);
    }

    // target branch
    k_buildU<<<NG, 256>>>(target);
    {
        dim3 grid(2, (NG*NFILT)/128);
        gemm_mma<<<grid, 256, 2*STG>>>(p_Uh, p_Ul, p_Mmh, p_Mml, p_conv, NG*NFILT, CONVOUT, KP_U, CONVOUT, nullptr, 0, 128);
    }
    k_fcxtb2<<<128, 128>>>(fcxt_W, fcxt_b, conv_b);
    {
        k_binit<<<(NG*128 + 255)/256, 256>>>(p_xc + 128, p_fcxtb2, NG, 128, 256);
        dim3 grid(2, 8, 4);
        gemm2_kernel<<<grid, 256>>>(p_conv, fcxt_W, nullptr, p_xc + 128, NG, 128, NFILT*CONVOUT, 256, 0);
    }

    // fusion head
    {
        dim3 grid(16, 8, 1);
        gemm2_kernel<<<grid, 256>>>(p_xc, fc1_W, fc1_b, p_f1, NG, 1024, 256, 1024, 1);
    }
    {
        k_binit<<<(NG*512 + 255)/256, 256>>>(p_f2, fc2_b, NG, 512, 512);
        dim3 grid(8, 8, 2);
        gemm2_kernel<<<grid, 256>>>(p_f1, fc2_W, nullptr, p_f2, NG, 512, 1024, 512, 0);
        k_relu<<<(NG*512 + 255)/256, 256>>>(p_f2, NG*512);
    }
    k_out<<<(NG*32 + 255)/256, 256>>>(out_W, out_b, (float*)d_out);
}